// round 1
// baseline (speedup 1.0000x reference)
#include <cuda_runtime.h>
#include <cuda_bf16.h>
#include <math.h>

#define DD 800
#define NA_ 20000
#define NB_ 24000
#define NG_ 256

// ---------------------------------------------------------------------------
// Scratch: single static device array (no runtime allocation).
// Layout (float offsets):
//   Ah1 0, Dh1 16e6, Eh1 32e6, Ah2 48e6, Dh2 64e6, Eh2 80e6   (6 x NA*D)
//   Cu 96,000,000  Fu +204800  Iu +409600
//   uacc 96,614,400 (4 x 204800)
//   bnsum 97,433,600 (5x800) bnsq 97,437,600 bnscale 97,441,600 bnshift 97,445,600
//   cnts 97,449,600 (4x256)
// total < 97,500,000 floats (~390 MB)
// ---------------------------------------------------------------------------
__device__ float g_scratch[97500000];

// ---------------------------------------------------------------------------
// SGEMM: C[M x 800] = A[M x 800] @ W[800 x 800] (+bias), row-major.
// BM=BN=128, BK=8, 256 threads, 8x8 per-thread microtile.
// MODE 0: store   C = acc + b
// MODE 1: mix     C = C*0.8 + 0.2*(acc + b)
// MODE 2: segadd  atomicAdd(segout[seg[row]*800 + col], acc + b)
// ---------------------------------------------------------------------------
template<int MODE>
__global__ __launch_bounds__(256, 2)
void sgemm_k(const float* __restrict__ A, const float* __restrict__ W,
             const float* __restrict__ bias, float* __restrict__ C,
             int M, const int* __restrict__ seg, float* __restrict__ segout)
{
    const int BM = 128, BN = 128, BK = 8;
    __shared__ float As[BK][BM];
    __shared__ float Bs[BK][BN];

    int tid = threadIdx.x;
    int bm = blockIdx.y * BM;
    int bn = blockIdx.x * BN;
    int ty = tid >> 4;          // 0..15
    int tx = tid & 15;          // 0..15

    float acc[8][8];
#pragma unroll
    for (int i = 0; i < 8; i++)
#pragma unroll
        for (int j = 0; j < 8; j++) acc[i][j] = 0.f;

    // A-load mapping: one float4 per thread
    int am = tid >> 1;            // 0..127
    int aq = (tid & 1) * 4;       // 0 or 4
    bool arow_ok = (bm + am) < M;
    const float* Arow = A + (size_t)(bm + am) * DD + aq;

    // B-load mapping: one float4 per thread
    int bk = tid >> 5;            // 0..7
    int bnn = (tid & 31) * 4;     // 0..124
    int bcol = bn + bnn;
    bool bcol_ok = bcol < DD;
    const float* Bsrc = W + (size_t)bk * DD + bcol;

    for (int k0 = 0; k0 < DD; k0 += BK) {
        float4 av = make_float4(0.f, 0.f, 0.f, 0.f);
        if (arow_ok) av = *(const float4*)(Arow + k0);
        As[aq + 0][am] = av.x; As[aq + 1][am] = av.y;
        As[aq + 2][am] = av.z; As[aq + 3][am] = av.w;

        float4 bv = make_float4(0.f, 0.f, 0.f, 0.f);
        if (bcol_ok) bv = *(const float4*)(Bsrc + (size_t)k0 * DD);
        *(float4*)&Bs[bk][bnn] = bv;

        __syncthreads();
#pragma unroll
        for (int k = 0; k < BK; k++) {
            float a[8], b[8];
            *(float4*)&a[0] = *(const float4*)&As[k][ty * 8];
            *(float4*)&a[4] = *(const float4*)&As[k][ty * 8 + 4];
            *(float4*)&b[0] = *(const float4*)&Bs[k][tx * 8];
            *(float4*)&b[4] = *(const float4*)&Bs[k][tx * 8 + 4];
#pragma unroll
            for (int i = 0; i < 8; i++)
#pragma unroll
                for (int j = 0; j < 8; j++)
                    acc[i][j] += a[i] * b[j];
        }
        __syncthreads();
    }

#pragma unroll
    for (int i = 0; i < 8; i++) {
        int row = bm + ty * 8 + i;
        if (row >= M) continue;
        int srow = 0;
        if (MODE == 2) srow = seg[row];
#pragma unroll
        for (int j = 0; j < 8; j++) {
            int col = bn + tx * 8 + j;
            if (col >= DD) continue;
            float v = acc[i][j] + bias[col];
            if (MODE == 0) {
                C[(size_t)row * DD + col] = v;
            } else if (MODE == 1) {
                float* p = &C[(size_t)row * DD + col];
                *p = *p * 0.8f + 0.2f * v;
            } else {
                atomicAdd(&segout[srow * DD + col], v);
            }
        }
    }
}

// ---------------------------------------------------------------------------
__global__ void zero_k(float* p, int n) {
    int i = blockIdx.x * blockDim.x + threadIdx.x;
    if (i < n) p[i] = 0.f;
}

__global__ void count_k(const int* __restrict__ seg, int n, float* cnt) {
    int i = blockIdx.x * blockDim.x + threadIdx.x;
    if (i < n) atomicAdd(&cnt[seg[i]], 1.0f);
}

// e_out (holds Be) += Ah[i0] + Ah[i1] + Cu[graph]
__global__ void bondpre_k(float* __restrict__ e_out, const float* __restrict__ Ah,
                          const float* __restrict__ Cu,
                          const int* __restrict__ bond_atoms,
                          const int* __restrict__ bond_graph)
{
    int b = blockIdx.x;
    int i0 = bond_atoms[b * 2];
    int i1 = bond_atoms[b * 2 + 1];
    int g  = bond_graph[b];
    const float* a0 = Ah + (size_t)i0 * DD;
    const float* a1 = Ah + (size_t)i1 * DD;
    const float* cu = Cu + (size_t)g * DD;
    float* eo = e_out + (size_t)b * DD;
    for (int c = threadIdx.x; c < DD; c += blockDim.x)
        eo[c] += a0[c] + a1[c] + cu[c];
}

// column sums / sums-of-squares (chunked rows, atomic partials)
__global__ void colstats_k(const float* __restrict__ X, int R,
                           float* __restrict__ sum, float* __restrict__ sumsq)
{
    int col = blockIdx.x * blockDim.x + threadIdx.x;
    if (col >= DD) return;
    int chunk = (R + gridDim.y - 1) / gridDim.y;
    int r0 = blockIdx.y * chunk;
    int r1 = min(r0 + chunk, R);
    float s = 0.f, q = 0.f;
    for (int r = r0; r < r1; r++) {
        float v = X[(size_t)r * DD + col];
        s += v;
        q += v * v;
    }
    atomicAdd(&sum[col], s);
    atomicAdd(&sumsq[col], q);
}

__global__ void bnprep_k(const float* __restrict__ sum, const float* __restrict__ sumsq,
                         const float* __restrict__ gamma, const float* __restrict__ beta,
                         float Rf, float* __restrict__ scale, float* __restrict__ shift)
{
    int c = blockIdx.x * blockDim.x + threadIdx.x;
    if (c >= DD) return;
    float m = sum[c] / Rf;
    float v = sumsq[c] / Rf - m * m;
    float sc = gamma[c] * rsqrtf(v + 1e-5f);
    scale[c] = sc;
    shift[c] = beta[c] - m * sc;
}

__global__ void bnrelu_k(float* __restrict__ X, int n,
                         const float* __restrict__ scale, const float* __restrict__ shift)
{
    int i = blockIdx.x * blockDim.x + threadIdx.x;
    if (i >= n) return;
    int col = i % DD;
    float y = X[i] * scale[col] + shift[col];
    X[i] = fmaxf(y, 0.f);
}

// gated mailbox aggregation: h_out = Dh + sum_k(sig_k * Eh[other_k]) / (sum sig + eps) + Fu[g]
__global__ void atom_k(float* __restrict__ h_out, const float* __restrict__ Dh,
                       const float* __restrict__ Eh, const float* __restrict__ Fu,
                       const float* __restrict__ e_new,
                       const int* __restrict__ atom_bonds, const int* __restrict__ bond_atoms,
                       const int* __restrict__ atom_graph)
{
    int a = blockIdx.x;
    __shared__ int sh_bond[4];
    __shared__ int sh_other[4];
    if (threadIdx.x < 4) {
        int b = atom_bonds[a * 4 + threadIdx.x];
        sh_bond[threadIdx.x] = b;
        int p0 = bond_atoms[b * 2];
        int p1 = bond_atoms[b * 2 + 1];
        sh_other[threadIdx.x] = (p0 != a) ? p0 : p1;
    }
    __syncthreads();
    int g = atom_graph[a];
    int b0 = sh_bond[0], b1 = sh_bond[1], b2 = sh_bond[2], b3 = sh_bond[3];
    int o0 = sh_other[0], o1 = sh_other[1], o2 = sh_other[2], o3 = sh_other[3];
    const float* e0 = e_new + (size_t)b0 * DD;
    const float* e1 = e_new + (size_t)b1 * DD;
    const float* e2p = e_new + (size_t)b2 * DD;
    const float* e3 = e_new + (size_t)b3 * DD;
    const float* E0 = Eh + (size_t)o0 * DD;
    const float* E1 = Eh + (size_t)o1 * DD;
    const float* E2 = Eh + (size_t)o2 * DD;
    const float* E3 = Eh + (size_t)o3 * DD;
    const float* dh = Dh + (size_t)a * DD;
    const float* fu = Fu + (size_t)g * DD;
    float* ho = h_out + (size_t)a * DD;
    for (int c = threadIdx.x; c < DD; c += blockDim.x) {
        float s0 = 1.f / (1.f + expf(-e0[c]));
        float s1 = 1.f / (1.f + expf(-e1[c]));
        float s2 = 1.f / (1.f + expf(-e2p[c]));
        float s3 = 1.f / (1.f + expf(-e3[c]));
        float num = s0 * E0[c] + s1 * E1[c] + s2 * E2[c] + s3 * E3[c];
        float den = s0 + s1 + s2 + s3 + 1e-6f;
        ho[c] = dh[c] + num / den + fu[c];
    }
}

// c = 1/(|Dh1-Dh2|+1); t1 = c*Dh1; t2 = c*Dh2
__global__ void cross_k(const float* __restrict__ Dh1, const float* __restrict__ Dh2,
                        float* __restrict__ t1, float* __restrict__ t2, int n)
{
    int i = blockIdx.x * blockDim.x + threadIdx.x;
    if (i >= n) return;
    float d1 = Dh1[i], d2 = Dh2[i];
    float c = 1.f / (fabsf(d1 - d2) + 1.f);
    t1[i] = c * d1;
    t2[i] = c * d2;
}

// u_out = sum_k uacc_k / max(cnt_k,1) + Iu
__global__ void ucomb_k(float* __restrict__ u_out, const float* __restrict__ uacc,
                        const float* __restrict__ cnts, const float* __restrict__ Iu)
{
    int i = blockIdx.x * blockDim.x + threadIdx.x;
    if (i >= NG_ * DD) return;
    int g = i / DD;
    float v = Iu[i];
#pragma unroll
    for (int k = 0; k < 4; k++)
        v += uacc[k * (NG_ * DD) + i] / fmaxf(cnts[k * NG_ + g], 1.0f);
    u_out[i] = v;
}

// ---------------------------------------------------------------------------
static inline void gemm0(const float* A, const float* W, const float* b, float* C, int M) {
    dim3 g((DD + 127) / 128, (M + 127) / 128);
    sgemm_k<0><<<g, 256>>>(A, W, b, C, M, nullptr, nullptr);
}
static inline void gemm_mix(const float* A, const float* W, const float* b, float* C, int M) {
    dim3 g((DD + 127) / 128, (M + 127) / 128);
    sgemm_k<1><<<g, 256>>>(A, W, b, C, M, nullptr, nullptr);
}
static inline void gemm_seg(const float* A, const float* W, const float* b, int M,
                            const int* seg, float* segout) {
    dim3 g((DD + 127) / 128, (M + 127) / 128);
    sgemm_k<2><<<g, 256>>>(A, W, b, nullptr, M, seg, segout);
}

extern "C" void kernel_launch(void* const* d_in, const int* in_sizes, int n_in,
                              void* d_out, int out_size)
{
    const float* h   = (const float*)d_in[0];
    const float* e   = (const float*)d_in[1];
    const float* h2  = (const float*)d_in[2];
    const float* e2  = (const float*)d_in[3];
    const float* u   = (const float*)d_in[4];
    const float* Ws  = (const float*)d_in[5];   // [10][800][800]
    const float* bs  = (const float*)d_in[6];   // [10][800]
    const float* gam = (const float*)d_in[7];   // [3][800]
    const float* bet = (const float*)d_in[8];
    const int* ba1 = (const int*)d_in[9];
    const int* ab1 = (const int*)d_in[10];
    const int* ag1 = (const int*)d_in[11];
    const int* bg1 = (const int*)d_in[12];
    const int* ba2 = (const int*)d_in[13];
    const int* ab2 = (const int*)d_in[14];
    const int* ag2 = (const int*)d_in[15];
    const int* bg2 = (const int*)d_in[16];

    float* out = (float*)d_out;
    float* h1n = out;                       // 16,000,000
    float* e1n = out + 16000000;            // 19,200,000
    float* h2n = out + 35200000;            // 16,000,000
    float* e2n = out + 51200000;            // 19,200,000
    float* un  = out + 70400000;            // 204,800

    float* sp = nullptr;
    cudaGetSymbolAddress((void**)&sp, g_scratch);

    float* Ah1 = sp;
    float* Dh1 = sp + 16000000;
    float* Eh1 = sp + 32000000;
    float* Ah2 = sp + 48000000;
    float* Dh2 = sp + 64000000;
    float* Eh2 = sp + 80000000;
    float* Cu  = sp + 96000000;
    float* Fu  = Cu + 204800;
    float* Iu  = Fu + 204800;
    float* uacc = sp + 96614400;            // 4 x 204800
    float* bnsum = sp + 97433600;           // 5 x 800
    float* bnsq  = sp + 97437600;
    float* bnsc  = sp + 97441600;
    float* bnsh  = sp + 97445600;
    float* cnts  = sp + 97449600;           // 4 x 256

    const float* W = Ws;                    // W(i) = Ws + i*640000
    const float* B = bs;                    // b(i) = bs + i*800

    // zero accumulators (uacc .. cnts): 836,224 floats
    {
        int n = 836224;
        zero_k<<<(n + 255) / 256, 256>>>(uacc, n);
    }
    count_k<<<(NA_ + 255) / 256, 256>>>(ag1, NA_, cnts + 0);
    count_k<<<(NB_ + 255) / 256, 256>>>(bg1, NB_, cnts + 256);
    count_k<<<(NA_ + 255) / 256, 256>>>(ag2, NA_, cnts + 512);
    count_k<<<(NB_ + 255) / 256, 256>>>(bg2, NB_, cnts + 768);

    // small u GEMMs
    gemm0(u, W + 2 * 640000, B + 2 * 800, Cu, NG_);
    gemm0(u, W + 5 * 640000, B + 5 * 800, Fu, NG_);
    gemm0(u, W + 8 * 640000, B + 8 * 800, Iu, NG_);

    // big projections
    gemm0(h,  W + 0 * 640000, B + 0 * 800, Ah1, NA_);
    gemm0(h,  W + 3 * 640000, B + 3 * 800, Dh1, NA_);
    gemm0(h,  W + 4 * 640000, B + 4 * 800, Eh1, NA_);
    gemm0(h2, W + 0 * 640000, B + 0 * 800, Ah2, NA_);
    gemm0(h2, W + 3 * 640000, B + 3 * 800, Dh2, NA_);
    gemm0(h2, W + 4 * 640000, B + 4 * 800, Eh2, NA_);
    gemm0(e,  W + 1 * 640000, B + 1 * 800, e1n, NB_);   // Be -> e1n slot
    gemm0(e2, W + 1 * 640000, B + 1 * 800, e2n, NB_);

    // bond update pre-activation
    bondpre_k<<<NB_, 256>>>(e1n, Ah1, Cu, ba1, bg1);
    bondpre_k<<<NB_, 256>>>(e2n, Ah2, Cu, ba2, bg2);

    // BN+relu on e1n / e2n (bn index 0 params)
    {
        dim3 gs((DD + 255) / 256, 64);
        colstats_k<<<gs, 256>>>(e1n, NB_, bnsum + 0, bnsq + 0);
        bnprep_k<<<4, 256>>>(bnsum + 0, bnsq + 0, gam + 0, bet + 0, (float)NB_, bnsc + 0, bnsh + 0);
        int n = NB_ * DD;
        bnrelu_k<<<(n + 255) / 256, 256>>>(e1n, n, bnsc + 0, bnsh + 0);

        colstats_k<<<gs, 256>>>(e2n, NB_, bnsum + 800, bnsq + 800);
        bnprep_k<<<4, 256>>>(bnsum + 800, bnsq + 800, gam + 0, bet + 0, (float)NB_, bnsc + 800, bnsh + 800);
        bnrelu_k<<<(n + 255) / 256, 256>>>(e2n, n, bnsc + 800, bnsh + 800);
    }

    // atom update -> h slots (pre-mix, pre-BN)
    atom_k<<<NA_, 256>>>(h1n, Dh1, Eh1, Fu, e1n, ab1, ba1, ag1);
    atom_k<<<NA_, 256>>>(h2n, Dh2, Eh2, Fu, e2n, ab2, ba2, ag2);

    // cross messages: t1 = c*Dh1, t2 = c*Dh2 (reuse Eh buffers)
    {
        int n = NA_ * DD;
        cross_k<<<(n + 255) / 256, 256>>>(Dh1, Dh2, Eh1, Eh2, n);
    }
    // h1n = 0.8*h1n + 0.2*(t2 @ W9 + b9)   (m21)
    gemm_mix(Eh2, W + 9 * 640000, B + 9 * 800, h1n, NA_);
    // h2n = 0.8*h2n + 0.2*(t1 @ W9 + b9)   (m12)
    gemm_mix(Eh1, W + 9 * 640000, B + 9 * 800, h2n, NA_);

    // BN+relu on h1n / h2n (bn index 1 params)
    {
        dim3 gs((DD + 255) / 256, 64);
        int n = NA_ * DD;
        colstats_k<<<gs, 256>>>(h1n, NA_, bnsum + 1600, bnsq + 1600);
        bnprep_k<<<4, 256>>>(bnsum + 1600, bnsq + 1600, gam + 800, bet + 800, (float)NA_, bnsc + 1600, bnsh + 1600);
        bnrelu_k<<<(n + 255) / 256, 256>>>(h1n, n, bnsc + 1600, bnsh + 1600);

        colstats_k<<<gs, 256>>>(h2n, NA_, bnsum + 2400, bnsq + 2400);
        bnprep_k<<<4, 256>>>(bnsum + 2400, bnsq + 2400, gam + 800, bet + 800, (float)NA_, bnsc + 2400, bnsh + 2400);
        bnrelu_k<<<(n + 255) / 256, 256>>>(h2n, n, bnsc + 2400, bnsh + 2400);
    }

    // global readout: segment-accumulate in GEMM epilogue
    gemm_seg(h1n, W + 6 * 640000, B + 6 * 800, NA_, ag1, uacc + 0 * 204800);
    gemm_seg(e1n, W + 7 * 640000, B + 7 * 800, NB_, bg1, uacc + 1 * 204800);
    gemm_seg(h2n, W + 6 * 640000, B + 6 * 800, NA_, ag2, uacc + 2 * 204800);
    gemm_seg(e2n, W + 7 * 640000, B + 7 * 800, NB_, bg2, uacc + 3 * 204800);

    // combine + BN+relu on u (bn index 2 params)
    {
        int n = NG_ * DD;
        ucomb_k<<<(n + 255) / 256, 256>>>(un, uacc, cnts, Iu);
        dim3 gs((DD + 255) / 256, 64);
        colstats_k<<<gs, 256>>>(un, NG_, bnsum + 3200, bnsq + 3200);
        bnprep_k<<<4, 256>>>(bnsum + 3200, bnsq + 3200, gam + 1600, bet + 1600, (float)NG_, bnsc + 3200, bnsh + 3200);
        bnrelu_k<<<(n + 255) / 256, 256>>>(un, n, bnsc + 3200, bnsh + 3200);
    }
}

// round 3
// speedup vs baseline: 2.7195x; 2.7195x over previous
#include <cuda_runtime.h>
#include <cuda_bf16.h>
#include <cstdint>
#include <math.h>

#define DD 800
#define NA_ 20000
#define NB_ 24000
#define NG_ 256

// ---- HMMA GEMM tiling ----
#define BM 128
#define BN 160
#define BK 32
#define NSTAGE 3
#define SA_HI 0
#define SA_LO 10240
#define SB_HI 20480
#define SB_LO 33280
#define STAGE_B 46080
#define SMEM_TOT (NSTAGE * STAGE_B)   // 138240

// ---------------------------------------------------------------------------
// Scratch layout (float offsets)
// ---------------------------------------------------------------------------
static constexpr size_t O_AH1 = 0;
static constexpr size_t O_DH1 = 16000000;
static constexpr size_t O_EH1 = 32000000;
static constexpr size_t O_AH2 = 48000000;
static constexpr size_t O_DH2 = 64000000;
static constexpr size_t O_EH2 = 80000000;
static constexpr size_t O_SMALL = 96000000;
static constexpr size_t O_TW  = 97500000;   // 10 x (hi+lo 800x800 bf16) = 6.4M floats
static constexpr size_t O_TH  = 103900000;  // 16M floats (hi+lo bf16 planes of 20000x800)
static constexpr size_t O_TH2 = 119900000;
static constexpr size_t O_TE  = 135900000;  // 19.2M floats
static constexpr size_t O_TE2 = 155100000;
static constexpr size_t O_TU  = 174300000;  // 204800 floats
__device__ __align__(1024) float g_scratch[175000000];

// ---------------------------------------------------------------------------
// helpers
// ---------------------------------------------------------------------------
__device__ __forceinline__ uint32_t smem_u32(const void* p) {
    uint32_t a;
    asm("{ .reg .u64 t; cvta.to.shared.u64 t, %1; cvt.u32.u64 %0, t; }" : "=r"(a) : "l"(p));
    return a;
}
__device__ __forceinline__ void cp16(uint32_t saddr, const void* gaddr) {
    asm volatile("cp.async.cg.shared.global [%0], [%1], 16;" :: "r"(saddr), "l"(gaddr));
}
__device__ __forceinline__ void cp_commit() {
    asm volatile("cp.async.commit_group;" ::: "memory");
}
__device__ __forceinline__ void cp_wait1() {
    asm volatile("cp.async.wait_group 1;" ::: "memory");
}
__device__ __forceinline__ void ldsm4(uint32_t* r, uint32_t addr) {
    asm volatile("ldmatrix.sync.aligned.m8n8.x4.shared.b16 {%0,%1,%2,%3}, [%4];"
                 : "=r"(r[0]), "=r"(r[1]), "=r"(r[2]), "=r"(r[3]) : "r"(addr));
}
__device__ __forceinline__ void mma16816(float* c, const uint32_t* a, const uint32_t* b) {
    asm volatile(
        "mma.sync.aligned.m16n8k16.row.col.f32.bf16.bf16.f32 "
        "{%0,%1,%2,%3}, {%4,%5,%6,%7}, {%8,%9}, {%0,%1,%2,%3};"
        : "+f"(c[0]), "+f"(c[1]), "+f"(c[2]), "+f"(c[3])
        : "r"(a[0]), "r"(a[1]), "r"(a[2]), "r"(a[3]), "r"(b[0]), "r"(b[1]));
}

// ---------------------------------------------------------------------------
// bf16x3 HMMA GEMM: C[M x 800] = A[M x 800] @ W[800 x 800] (+bias)
// A planes: Ahi/Alo row-major [M][800] bf16. B planes: W^T hi/lo [800n][800k].
// MODE 0: store; MODE 1: C = 0.8*C + 0.2*(acc+b); MODE 2: atomic segadd
// ---------------------------------------------------------------------------
template<int MODE>
__global__ __launch_bounds__(256, 1)
void hgemm_k(const __nv_bfloat16* __restrict__ Ahi, const __nv_bfloat16* __restrict__ Alo,
             const __nv_bfloat16* __restrict__ Bhi, const __nv_bfloat16* __restrict__ Blo,
             const float* __restrict__ bias, float* __restrict__ C,
             int M, const int* __restrict__ seg, float* __restrict__ segout)
{
    extern __shared__ char smem[];
    uint32_t sb = smem_u32(smem);
    int tid = threadIdx.x;
    int lid = tid & 31, wid = tid >> 5;
    int wm = wid & 3, wn = wid >> 2;
    int ntile = blockIdx.x, mtile = blockIdx.y;

    // --- load assignments ---
    int arow[2], acol[2];   // A: 512 chunks (128 rows x 4 chunks of 16B)
    uint32_t asoff[2];
#pragma unroll
    for (int t = 0; t < 2; t++) {
        int q = tid + t * 256;
        int r = q >> 2, c = q & 3;
        arow[t] = min(mtile * BM + r, M - 1);
        acol[t] = c * 8;
        asoff[t] = r * 80 + c * 16;
    }
    int brow[3], bcol[3];   // B: 640 chunks (160 rows x 4)
    uint32_t bsoff[3];
#pragma unroll
    for (int t = 0; t < 3; t++) {
        int q = tid + t * 256;
        int r = q >> 2, c = q & 3;
        brow[t] = ntile * BN + r;
        bcol[t] = c * 8;
        bsoff[t] = r * 80 + c * 16;
    }
    bool b3 = (tid < 128);

    auto load_stage = [&](int s, int kc) {
        uint32_t st = sb + s * STAGE_B;
        int k0 = kc * BK;
#pragma unroll
        for (int t = 0; t < 2; t++) {
            size_t go = (size_t)arow[t] * DD + k0 + acol[t];
            cp16(st + SA_HI + asoff[t], Ahi + go);
            cp16(st + SA_LO + asoff[t], Alo + go);
        }
#pragma unroll
        for (int t = 0; t < 2; t++) {
            size_t go = (size_t)brow[t] * DD + k0 + bcol[t];
            cp16(st + SB_HI + bsoff[t], Bhi + go);
            cp16(st + SB_LO + bsoff[t], Blo + go);
        }
        if (b3) {
            size_t go = (size_t)brow[2] * DD + k0 + bcol[2];
            cp16(st + SB_HI + bsoff[2], Bhi + go);
            cp16(st + SB_LO + bsoff[2], Blo + go);
        }
    };

    float acc[2][10][4];
#pragma unroll
    for (int i = 0; i < 2; i++)
#pragma unroll
        for (int j = 0; j < 10; j++)
#pragma unroll
            for (int k = 0; k < 4; k++) acc[i][j][k] = 0.f;

    uint32_t aswz = (lid & 15) * 80 + (lid >> 4) * 16;
    uint32_t bswz = ((lid & 7) + ((lid & 16) ? 8 : 0)) * 80 + ((lid >> 3) & 1) * 16;
    uint32_t a_base = (wm * 32) * 80 + aswz;
    uint32_t b_base = (wn * 80) * 80 + bswz;

    load_stage(0, 0); cp_commit();
    load_stage(1, 1); cp_commit();

#pragma unroll 1
    for (int kc = 0; kc < 25; kc++) {
        int s = kc % 3;
        cp_wait1();
        __syncthreads();
        uint32_t st = sb + s * STAGE_B;
#pragma unroll
        for (int k16 = 0; k16 < 2; k16++) {
            uint32_t aH[2][4], aL[2][4];
            ldsm4(aH[0], st + SA_HI + a_base + k16 * 32);
            ldsm4(aH[1], st + SA_HI + a_base + 16 * 80 + k16 * 32);
            ldsm4(aL[0], st + SA_LO + a_base + k16 * 32);
            ldsm4(aL[1], st + SA_LO + a_base + 16 * 80 + k16 * 32);
#pragma unroll
            for (int g = 0; g < 5; g++) {
                uint32_t bH[4], bL[4];
                ldsm4(bH, st + SB_HI + b_base + g * 16 * 80 + k16 * 32);
                ldsm4(bL, st + SB_LO + b_base + g * 16 * 80 + k16 * 32);
                // pass 1: hi*hi
                mma16816(acc[0][2 * g], aH[0], bH);
                mma16816(acc[0][2 * g + 1], aH[0], bH + 2);
                mma16816(acc[1][2 * g], aH[1], bH);
                mma16816(acc[1][2 * g + 1], aH[1], bH + 2);
                // pass 2: hi*lo
                mma16816(acc[0][2 * g], aH[0], bL);
                mma16816(acc[0][2 * g + 1], aH[0], bL + 2);
                mma16816(acc[1][2 * g], aH[1], bL);
                mma16816(acc[1][2 * g + 1], aH[1], bL + 2);
                // pass 3: lo*hi
                mma16816(acc[0][2 * g], aL[0], bH);
                mma16816(acc[0][2 * g + 1], aL[0], bH + 2);
                mma16816(acc[1][2 * g], aL[1], bH);
                mma16816(acc[1][2 * g + 1], aL[1], bH + 2);
            }
        }
        if (kc + 2 < 25) load_stage((kc + 2) % 3, kc + 2);
        cp_commit();
    }

    // --- epilogue ---
#pragma unroll
    for (int i = 0; i < 2; i++) {
        int ra = mtile * BM + wm * 32 + i * 16 + (lid >> 2);
#pragma unroll
        for (int half = 0; half < 2; half++) {
            int r = ra + half * 8;
            if (r >= M) continue;
            int srow = 0;
            if (MODE == 2) srow = seg[r];
#pragma unroll
            for (int j = 0; j < 10; j++) {
                int col = ntile * BN + wn * 80 + j * 8 + (lid & 3) * 2;
                float v0 = acc[i][j][half * 2 + 0] + bias[col];
                float v1 = acc[i][j][half * 2 + 1] + bias[col + 1];
                if (MODE == 0) {
                    *(float2*)&C[(size_t)r * DD + col] = make_float2(v0, v1);
                } else if (MODE == 1) {
                    float2* p = (float2*)&C[(size_t)r * DD + col];
                    float2 o = *p;
                    *p = make_float2(o.x * 0.8f + 0.2f * v0, o.y * 0.8f + 0.2f * v1);
                } else {
                    atomicAdd(&segout[srow * DD + col], v0);
                    atomicAdd(&segout[srow * DD + col + 1], v1);
                }
            }
        }
    }
}

// ---------------------------------------------------------------------------
// Conversions: fp32 -> hi/lo bf16 planes
// ---------------------------------------------------------------------------
__device__ __forceinline__ void split2(float v, unsigned short& hs, unsigned short& ls) {
    __nv_bfloat16 hb = __float2bfloat16(v);
    float hf = __bfloat162float(hb);
    __nv_bfloat16 lb = __float2bfloat16(v - hf);
    hs = __bfloat16_as_ushort(hb);
    ls = __bfloat16_as_ushort(lb);
}

__global__ void conv_a_k(const float* __restrict__ A, int n, __nv_bfloat16* __restrict__ T)
{
    int i4 = (blockIdx.x * blockDim.x + threadIdx.x) * 4;
    if (i4 >= n) return;
    float4 v = *(const float4*)(A + i4);
    unsigned short h0, h1, h2, h3, l0, l1, l2, l3;
    split2(v.x, h0, l0); split2(v.y, h1, l1); split2(v.z, h2, l2); split2(v.w, h3, l3);
    uint2 hq = make_uint2(h0 | (h1 << 16), h2 | (h3 << 16));
    uint2 lq = make_uint2(l0 | (l1 << 16), l2 | (l3 << 16));
    *(uint2*)((unsigned short*)T + i4) = hq;
    *(uint2*)((unsigned short*)T + n + i4) = lq;
}

// weight transpose: W[k][n] -> hi/lo planes of W^T[n][k]
__global__ void conv_w_k(const float* __restrict__ Ws, __nv_bfloat16* __restrict__ TW)
{
    __shared__ float t[32][33];
    int wi = blockIdx.z;
    const float* W = Ws + (size_t)wi * (DD * DD);
    __nv_bfloat16* hi = TW + (size_t)wi * 1280000;
    __nv_bfloat16* lo = hi + 640000;
    int tx = threadIdx.x, ty = threadIdx.y;     // 32 x 8
    int kb = blockIdx.y * 32, nb = blockIdx.x * 32;
#pragma unroll
    for (int r = 0; r < 4; r++)
        t[ty + r * 8][tx] = W[(size_t)(kb + ty + r * 8) * DD + nb + tx];
    __syncthreads();
#pragma unroll
    for (int r = 0; r < 4; r++) {
        int nrow = nb + ty + r * 8;
        int kcol = kb + tx;
        float v = t[tx][ty + r * 8];
        unsigned short hs, ls;
        split2(v, hs, ls);
        hi[(size_t)nrow * DD + kcol] = __ushort_as_bfloat16(hs);
        lo[(size_t)nrow * DD + kcol] = __ushort_as_bfloat16(ls);
    }
}

// ---------------------------------------------------------------------------
// Elementwise / graph kernels
// ---------------------------------------------------------------------------
__global__ void zero_k(float* p, int n) {
    int i = blockIdx.x * blockDim.x + threadIdx.x;
    if (i < n) p[i] = 0.f;
}
__global__ void count_k(const int* __restrict__ seg, int n, float* cnt) {
    int i = blockIdx.x * blockDim.x + threadIdx.x;
    if (i < n) atomicAdd(&cnt[seg[i]], 1.0f);
}
__global__ void bondpre_k(float* __restrict__ e_out, const float* __restrict__ Ah,
                          const float* __restrict__ Cu,
                          const int* __restrict__ bond_atoms,
                          const int* __restrict__ bond_graph)
{
    int b = blockIdx.x;
    int i0 = bond_atoms[b * 2];
    int i1 = bond_atoms[b * 2 + 1];
    int g = bond_graph[b];
    const float* a0 = Ah + (size_t)i0 * DD;
    const float* a1 = Ah + (size_t)i1 * DD;
    const float* cu = Cu + (size_t)g * DD;
    float* eo = e_out + (size_t)b * DD;
    for (int c = threadIdx.x; c < DD; c += blockDim.x)
        eo[c] += a0[c] + a1[c] + cu[c];
}
__global__ void colstats_k(const float* __restrict__ X, int R,
                           float* __restrict__ sum, float* __restrict__ sumsq)
{
    int col = blockIdx.x * blockDim.x + threadIdx.x;
    if (col >= DD) return;
    int chunk = (R + gridDim.y - 1) / gridDim.y;
    int r0 = blockIdx.y * chunk;
    int r1 = min(r0 + chunk, R);
    float s = 0.f, q = 0.f;
    for (int r = r0; r < r1; r++) {
        float v = X[(size_t)r * DD + col];
        s += v; q += v * v;
    }
    atomicAdd(&sum[col], s);
    atomicAdd(&sumsq[col], q);
}
__global__ void bnprep_k(const float* __restrict__ sum, const float* __restrict__ sumsq,
                         const float* __restrict__ gamma, const float* __restrict__ beta,
                         float Rf, float* __restrict__ scale, float* __restrict__ shift)
{
    int c = blockIdx.x * blockDim.x + threadIdx.x;
    if (c >= DD) return;
    float m = sum[c] / Rf;
    float v = sumsq[c] / Rf - m * m;
    float sc = gamma[c] * rsqrtf(v + 1e-5f);
    scale[c] = sc;
    shift[c] = beta[c] - m * sc;
}
__global__ void bnrelu_k(float* __restrict__ X, int n,
                         const float* __restrict__ scale, const float* __restrict__ shift)
{
    int i = blockIdx.x * blockDim.x + threadIdx.x;
    if (i >= n) return;
    int col = i % DD;
    float y = X[i] * scale[col] + shift[col];
    X[i] = fmaxf(y, 0.f);
}
__global__ void atom_k(float* __restrict__ h_out, const float* __restrict__ Dh,
                       const float* __restrict__ Eh, const float* __restrict__ Fu,
                       const float* __restrict__ e_new,
                       const int* __restrict__ atom_bonds, const int* __restrict__ bond_atoms,
                       const int* __restrict__ atom_graph)
{
    int a = blockIdx.x;
    __shared__ int sh_bond[4];
    __shared__ int sh_other[4];
    if (threadIdx.x < 4) {
        int b = atom_bonds[a * 4 + threadIdx.x];
        sh_bond[threadIdx.x] = b;
        int p0 = bond_atoms[b * 2];
        int p1 = bond_atoms[b * 2 + 1];
        sh_other[threadIdx.x] = (p0 != a) ? p0 : p1;
    }
    __syncthreads();
    int g = atom_graph[a];
    int b0 = sh_bond[0], b1 = sh_bond[1], b2 = sh_bond[2], b3 = sh_bond[3];
    int o0 = sh_other[0], o1 = sh_other[1], o2 = sh_other[2], o3 = sh_other[3];
    const float* e0 = e_new + (size_t)b0 * DD;
    const float* e1 = e_new + (size_t)b1 * DD;
    const float* e2p = e_new + (size_t)b2 * DD;
    const float* e3 = e_new + (size_t)b3 * DD;
    const float* E0 = Eh + (size_t)o0 * DD;
    const float* E1 = Eh + (size_t)o1 * DD;
    const float* E2 = Eh + (size_t)o2 * DD;
    const float* E3 = Eh + (size_t)o3 * DD;
    const float* dh = Dh + (size_t)a * DD;
    const float* fu = Fu + (size_t)g * DD;
    float* ho = h_out + (size_t)a * DD;
    for (int c = threadIdx.x; c < DD; c += blockDim.x) {
        float s0 = 1.f / (1.f + expf(-e0[c]));
        float s1 = 1.f / (1.f + expf(-e1[c]));
        float s2 = 1.f / (1.f + expf(-e2p[c]));
        float s3 = 1.f / (1.f + expf(-e3[c]));
        float num = s0 * E0[c] + s1 * E1[c] + s2 * E2[c] + s3 * E3[c];
        float den = s0 + s1 + s2 + s3 + 1e-6f;
        ho[c] = dh[c] + num / den + fu[c];
    }
}
__global__ void cross_k(const float* __restrict__ Dh1, const float* __restrict__ Dh2,
                        float* __restrict__ t1, float* __restrict__ t2, int n)
{
    int i = blockIdx.x * blockDim.x + threadIdx.x;
    if (i >= n) return;
    float d1 = Dh1[i], d2 = Dh2[i];
    float c = 1.f / (fabsf(d1 - d2) + 1.f);
    t1[i] = c * d1;
    t2[i] = c * d2;
}
__global__ void ucomb_k(float* __restrict__ u_out, const float* __restrict__ uacc,
                        const float* __restrict__ cnts, const float* __restrict__ Iu)
{
    int i = blockIdx.x * blockDim.x + threadIdx.x;
    if (i >= NG_ * DD) return;
    int g = i / DD;
    float v = Iu[i];
#pragma unroll
    for (int k = 0; k < 4; k++)
        v += uacc[k * (NG_ * DD) + i] / fmaxf(cnts[k * NG_ + g], 1.0f);
    u_out[i] = v;
}

// ---------------------------------------------------------------------------
extern "C" void kernel_launch(void* const* d_in, const int* in_sizes, int n_in,
                              void* d_out, int out_size)
{
    const float* h   = (const float*)d_in[0];
    const float* e   = (const float*)d_in[1];
    const float* h2  = (const float*)d_in[2];
    const float* e2  = (const float*)d_in[3];
    const float* u   = (const float*)d_in[4];
    const float* Ws  = (const float*)d_in[5];
    const float* bs  = (const float*)d_in[6];
    const float* gam = (const float*)d_in[7];
    const float* bet = (const float*)d_in[8];
    const int* ba1 = (const int*)d_in[9];
    const int* ab1 = (const int*)d_in[10];
    const int* ag1 = (const int*)d_in[11];
    const int* bg1 = (const int*)d_in[12];
    const int* ba2 = (const int*)d_in[13];
    const int* ab2 = (const int*)d_in[14];
    const int* ag2 = (const int*)d_in[15];
    const int* bg2 = (const int*)d_in[16];

    float* out = (float*)d_out;
    float* h1n = out;
    float* e1n = out + 16000000;
    float* h2n = out + 35200000;
    float* e2n = out + 51200000;
    float* un  = out + 70400000;

    float* sp = nullptr;
    cudaGetSymbolAddress((void**)&sp, g_scratch);

    float* Ah1 = sp + O_AH1;  float* Dh1 = sp + O_DH1;  float* Eh1 = sp + O_EH1;
    float* Ah2 = sp + O_AH2;  float* Dh2 = sp + O_DH2;  float* Eh2 = sp + O_EH2;
    float* Cu  = sp + O_SMALL;
    float* Fu  = Cu + 204800;
    float* Iu  = Cu + 409600;
    float* uacc = Cu + 614400;
    float* cnts = Cu + 1433600;
    float* bnsum = Cu + 1434624;
    float* bnsq  = Cu + 1438624;
    float* bnsc  = Cu + 1442624;
    float* bnsh  = Cu + 1446624;

    __nv_bfloat16* tw  = (__nv_bfloat16*)(sp + O_TW);
    __nv_bfloat16* th  = (__nv_bfloat16*)(sp + O_TH);
    __nv_bfloat16* th2 = (__nv_bfloat16*)(sp + O_TH2);
    __nv_bfloat16* te  = (__nv_bfloat16*)(sp + O_TE);
    __nv_bfloat16* te2 = (__nv_bfloat16*)(sp + O_TE2);
    __nv_bfloat16* tu  = (__nv_bfloat16*)(sp + O_TU);

    const float* B = bs;

    cudaFuncSetAttribute(hgemm_k<0>, cudaFuncAttributeMaxDynamicSharedMemorySize, SMEM_TOT);
    cudaFuncSetAttribute(hgemm_k<1>, cudaFuncAttributeMaxDynamicSharedMemorySize, SMEM_TOT);
    cudaFuncSetAttribute(hgemm_k<2>, cudaFuncAttributeMaxDynamicSharedMemorySize, SMEM_TOT);

    const int MT_H = 157, MT_E = 188, MT_U = 2;
    const int NH = NA_ * DD, NE = NB_ * DD, NU = NG_ * DD;
    auto Whi = [&](int i) { return (const __nv_bfloat16*)(tw + (size_t)i * 1280000); };
    auto Wlo = [&](int i) { return (const __nv_bfloat16*)(tw + (size_t)i * 1280000 + 640000); };

    #define G0(TA, n, wi, C, M, MT)  hgemm_k<0><<<dim3(5, MT), 256, SMEM_TOT>>>((const __nv_bfloat16*)(TA), (const __nv_bfloat16*)(TA) + (n), Whi(wi), Wlo(wi), B + (wi) * 800, C, M, nullptr, nullptr)
    #define G1(TA, n, wi, C, M, MT)  hgemm_k<1><<<dim3(5, MT), 256, SMEM_TOT>>>((const __nv_bfloat16*)(TA), (const __nv_bfloat16*)(TA) + (n), Whi(wi), Wlo(wi), B + (wi) * 800, C, M, nullptr, nullptr)
    #define G2(TA, n, wi, M, MT, seg, so) hgemm_k<2><<<dim3(5, MT), 256, SMEM_TOT>>>((const __nv_bfloat16*)(TA), (const __nv_bfloat16*)(TA) + (n), Whi(wi), Wlo(wi), B + (wi) * 800, nullptr, M, seg, so)

    // 1-5: conversions (launch #6 is a big GEMM for ncu -s 5)
    conv_a_k<<<NH / 1024, 256>>>(h,  NH, th);
    conv_a_k<<<NH / 1024, 256>>>(h2, NH, th2);
    conv_a_k<<<NE / 1024, 256>>>(e,  NE, te);
    conv_a_k<<<NE / 1024, 256>>>(e2, NE, te2);
    conv_w_k<<<dim3(25, 25, 10), dim3(32, 8)>>>(Ws, tw);

    // big projection GEMMs
    G0(th,  NH, 0, Ah1, NA_, MT_H);
    G0(th,  NH, 3, Dh1, NA_, MT_H);
    G0(th,  NH, 4, Eh1, NA_, MT_H);
    G0(th2, NH, 0, Ah2, NA_, MT_H);
    G0(th2, NH, 3, Dh2, NA_, MT_H);
    G0(th2, NH, 4, Eh2, NA_, MT_H);
    G0(te,  NE, 1, e1n, NB_, MT_E);
    G0(te2, NE, 1, e2n, NB_, MT_E);

    // accumulator zero + counts
    zero_k<<<(828224 + 255) / 256, 256>>>(uacc, 828224);
    count_k<<<(NA_ + 255) / 256, 256>>>(ag1, NA_, cnts + 0);
    count_k<<<(NB_ + 255) / 256, 256>>>(bg1, NB_, cnts + 256);
    count_k<<<(NA_ + 255) / 256, 256>>>(ag2, NA_, cnts + 512);
    count_k<<<(NB_ + 255) / 256, 256>>>(bg2, NB_, cnts + 768);

    // u projections
    conv_a_k<<<NU / 1024, 256>>>(u, NU, tu);
    G0(tu, NU, 2, Cu, NG_, MT_U);
    G0(tu, NU, 5, Fu, NG_, MT_U);
    G0(tu, NU, 8, Iu, NG_, MT_U);

    // bond update + BN(e) + relu
    bondpre_k<<<NB_, 256>>>(e1n, Ah1, Cu, ba1, bg1);
    bondpre_k<<<NB_, 256>>>(e2n, Ah2, Cu, ba2, bg2);
    {
        dim3 gs((DD + 255) / 256, 64);
        colstats_k<<<gs, 256>>>(e1n, NB_, bnsum + 0, bnsq + 0);
        bnprep_k<<<4, 256>>>(bnsum + 0, bnsq + 0, gam + 0, bet + 0, (float)NB_, bnsc + 0, bnsh + 0);
        bnrelu_k<<<(NE + 255) / 256, 256>>>(e1n, NE, bnsc + 0, bnsh + 0);
        colstats_k<<<gs, 256>>>(e2n, NB_, bnsum + 800, bnsq + 800);
        bnprep_k<<<4, 256>>>(bnsum + 800, bnsq + 800, gam + 0, bet + 0, (float)NB_, bnsc + 800, bnsh + 800);
        bnrelu_k<<<(NE + 255) / 256, 256>>>(e2n, NE, bnsc + 800, bnsh + 800);
    }

    // atom update (pre-mix h)
    atom_k<<<NA_, 256>>>(h1n, Dh1, Eh1, Fu, e1n, ab1, ba1, ag1);
    atom_k<<<NA_, 256>>>(h2n, Dh2, Eh2, Fu, e2n, ab2, ba2, ag2);

    // cross messages
    cross_k<<<(NH + 255) / 256, 256>>>(Dh1, Dh2, Eh1, Eh2, NH);
    conv_a_k<<<NH / 1024, 256>>>(Eh1, NH, th);     // t1
    conv_a_k<<<NH / 1024, 256>>>(Eh2, NH, th2);    // t2
    G1(th2, NH, 9, h1n, NA_, MT_H);                // h1n = 0.8 h1n + 0.2 m21
    G1(th,  NH, 9, h2n, NA_, MT_H);                // h2n = 0.8 h2n + 0.2 m12

    // BN(h) + relu
    {
        dim3 gs((DD + 255) / 256, 64);
        colstats_k<<<gs, 256>>>(h1n, NA_, bnsum + 1600, bnsq + 1600);
        bnprep_k<<<4, 256>>>(bnsum + 1600, bnsq + 1600, gam + 800, bet + 800, (float)NA_, bnsc + 1600, bnsh + 1600);
        bnrelu_k<<<(NH + 255) / 256, 256>>>(h1n, NH, bnsc + 1600, bnsh + 1600);
        colstats_k<<<gs, 256>>>(h2n, NA_, bnsum + 2400, bnsq + 2400);
        bnprep_k<<<4, 256>>>(bnsum + 2400, bnsq + 2400, gam + 800, bet + 800, (float)NA_, bnsc + 2400, bnsh + 2400);
        bnrelu_k<<<(NH + 255) / 256, 256>>>(h2n, NH, bnsc + 2400, bnsh + 2400);
    }

    // global readout
    conv_a_k<<<NH / 1024, 256>>>(h1n, NH, th);
    conv_a_k<<<NH / 1024, 256>>>(h2n, NH, th2);
    conv_a_k<<<NE / 1024, 256>>>(e1n, NE, te);
    conv_a_k<<<NE / 1024, 256>>>(e2n, NE, te2);
    G2(th,  NH, 6, NA_, MT_H, ag1, uacc + 0 * 204800);
    G2(te,  NE, 7, NB_, MT_E, bg1, uacc + 1 * 204800);
    G2(th2, NH, 6, NA_, MT_H, ag2, uacc + 2 * 204800);
    G2(te2, NE, 7, NB_, MT_E, bg2, uacc + 3 * 204800);

    // combine + BN(u) + relu
    {
        ucomb_k<<<(NU + 255) / 256, 256>>>(un, uacc, cnts, Iu);
        dim3 gs((DD + 255) / 256, 64);
        colstats_k<<<gs, 256>>>(un, NG_, bnsum + 3200, bnsq + 3200);
        bnprep_k<<<4, 256>>>(bnsum + 3200, bnsq + 3200, gam + 1600, bet + 1600, (float)NG_, bnsc + 3200, bnsh + 3200);
        bnrelu_k<<<(NU + 255) / 256, 256>>>(un, NU, bnsc + 3200, bnsh + 3200);
    }
    #undef G0
    #undef G1
    #undef G2
}

// round 4
// speedup vs baseline: 3.2139x; 1.1818x over previous
#include <cuda_runtime.h>
#include <cuda_bf16.h>
#include <cstdint>
#include <math.h>

#define DD 800
#define NA_ 20000
#define NB_ 24000
#define NG_ 256

// ---- HMMA GEMM tiling ----
#define BM 128
#define BN 160
#define BK 32
#define SA_HI 0
#define SA_LO 10240
#define SB_HI 20480
#define SB_LO 33280
#define STAGE_B 46080
#define SMEM_TOT (3 * STAGE_B)   // 138240

// ---------------------------------------------------------------------------
// Scratch layout (float offsets)
// ---------------------------------------------------------------------------
static constexpr size_t O_P1 = 0;             // [20000][2400]  A|D|E half1
static constexpr size_t O_P2 = 48000000;      // [20000][2400]  half2
static constexpr size_t O_SMALL = 96000000;
//   UFI 0 (614400 = [256][2400] C|F|I)
//   ZERO span @614400: ssum(819200: h1,e1,h2,e2) cnts(1024) bnsum(4000) bnsq(4000) zbias(800)
//   bnsc 1443424 bnsh 1447424 bADE 1451424 bUFI 1453824
//   mH planes 1456224 (204800)  mE 1661024 (204800)  P6 1865824  P7 2070624
static constexpr size_t O_TW   = 98400000;    // 6.4M floats = 12.8M bf16 weight planes
static constexpr size_t O_THp  = 104800000;   // h hi/lo planes (16M) ; later t1
static constexpr size_t O_TH2p = 120800000;   // h2 planes ; later t2
static constexpr size_t O_TEp  = 136800000;   // e planes (19.2M)
static constexpr size_t O_TE2p = 156000000;
static constexpr size_t O_TUp  = 175200000;   // u planes (204800)
__device__ __align__(1024) float g_scratch[176000000];

// ---------------------------------------------------------------------------
__device__ __forceinline__ uint32_t smem_u32(const void* p) {
    uint32_t a;
    asm("{ .reg .u64 t; cvta.to.shared.u64 t, %1; cvt.u32.u64 %0, t; }" : "=r"(a) : "l"(p));
    return a;
}
__device__ __forceinline__ void cp16(uint32_t saddr, const void* gaddr) {
    asm volatile("cp.async.cg.shared.global [%0], [%1], 16;" :: "r"(saddr), "l"(gaddr));
}
__device__ __forceinline__ void cp_commit() {
    asm volatile("cp.async.commit_group;" ::: "memory");
}
__device__ __forceinline__ void cp_wait1() {
    asm volatile("cp.async.wait_group 1;" ::: "memory");
}
__device__ __forceinline__ void ldsm4(uint32_t* r, uint32_t addr) {
    asm volatile("ldmatrix.sync.aligned.m8n8.x4.shared.b16 {%0,%1,%2,%3}, [%4];"
                 : "=r"(r[0]), "=r"(r[1]), "=r"(r[2]), "=r"(r[3]) : "r"(addr));
}
__device__ __forceinline__ void mma16816(float* c, const uint32_t* a, const uint32_t* b) {
    asm volatile(
        "mma.sync.aligned.m16n8k16.row.col.f32.bf16.bf16.f32 "
        "{%0,%1,%2,%3}, {%4,%5,%6,%7}, {%8,%9}, {%0,%1,%2,%3};"
        : "+f"(c[0]), "+f"(c[1]), "+f"(c[2]), "+f"(c[3])
        : "r"(a[0]), "r"(a[1]), "r"(a[2]), "r"(a[3]), "r"(b[0]), "r"(b[1]));
}

// ---------------------------------------------------------------------------
// bf16x3 HMMA GEMM, z-batched pair. MODE 0: store; MODE 1: 0.8*C + 0.2*(acc+b)
// ---------------------------------------------------------------------------
template<int MODE>
__global__ __launch_bounds__(256, 1)
void hgemm_k(const __nv_bfloat16* __restrict__ Ahi0, const __nv_bfloat16* __restrict__ Ahi1,
             size_t nA,
             const __nv_bfloat16* __restrict__ Bhi0, const __nv_bfloat16* __restrict__ Bhi1,
             size_t nB,
             const float* __restrict__ bias0, const float* __restrict__ bias1,
             float* __restrict__ C0, float* __restrict__ C1,
             int M, int ldc)
{
    extern __shared__ char smem[];
    uint32_t sb = smem_u32(smem);
    int tid = threadIdx.x;
    int lid = tid & 31, wid = tid >> 5;
    int wm = wid & 3, wn = wid >> 2;
    int ntile = blockIdx.x, mtile = blockIdx.y, z = blockIdx.z;

    const __nv_bfloat16* Ahi = z ? Ahi1 : Ahi0;
    const __nv_bfloat16* Alo = Ahi + nA;
    const __nv_bfloat16* Bhi = z ? Bhi1 : Bhi0;
    const __nv_bfloat16* Blo = Bhi + nB;
    const float* bias = z ? bias1 : bias0;
    float* C = z ? C1 : C0;

    int arow[2];
    uint32_t asoff[2];
    int acol[2];
#pragma unroll
    for (int t = 0; t < 2; t++) {
        int q = tid + t * 256;
        int r = q >> 2, c = q & 3;
        arow[t] = min(mtile * BM + r, M - 1);
        acol[t] = c * 8;
        asoff[t] = r * 80 + c * 16;
    }
    int brow[3], bcol[3];
    uint32_t bsoff[3];
#pragma unroll
    for (int t = 0; t < 3; t++) {
        int q = tid + t * 256;
        int r = q >> 2, c = q & 3;
        brow[t] = ntile * BN + r;
        bcol[t] = c * 8;
        bsoff[t] = r * 80 + c * 16;
    }
    bool b3 = (tid < 128);

    auto load_stage = [&](int s, int kc) {
        uint32_t st = sb + s * STAGE_B;
        int k0 = kc * BK;
#pragma unroll
        for (int t = 0; t < 2; t++) {
            size_t go = (size_t)arow[t] * DD + k0 + acol[t];
            cp16(st + SA_HI + asoff[t], Ahi + go);
            cp16(st + SA_LO + asoff[t], Alo + go);
        }
#pragma unroll
        for (int t = 0; t < 2; t++) {
            size_t go = (size_t)brow[t] * DD + k0 + bcol[t];
            cp16(st + SB_HI + bsoff[t], Bhi + go);
            cp16(st + SB_LO + bsoff[t], Blo + go);
        }
        if (b3) {
            size_t go = (size_t)brow[2] * DD + k0 + bcol[2];
            cp16(st + SB_HI + bsoff[2], Bhi + go);
            cp16(st + SB_LO + bsoff[2], Blo + go);
        }
    };

    float acc[2][10][4];
#pragma unroll
    for (int i = 0; i < 2; i++)
#pragma unroll
        for (int j = 0; j < 10; j++)
#pragma unroll
            for (int k = 0; k < 4; k++) acc[i][j][k] = 0.f;

    uint32_t aswz = (lid & 15) * 80 + (lid >> 4) * 16;
    uint32_t bswz = ((lid & 7) + ((lid & 16) ? 8 : 0)) * 80 + ((lid >> 3) & 1) * 16;
    uint32_t a_base = (wm * 32) * 80 + aswz;
    uint32_t b_base = (wn * 80) * 80 + bswz;

    load_stage(0, 0); cp_commit();
    load_stage(1, 1); cp_commit();

#pragma unroll 1
    for (int kc = 0; kc < 25; kc++) {
        int s = kc % 3;
        cp_wait1();
        __syncthreads();
        uint32_t st = sb + s * STAGE_B;
#pragma unroll
        for (int k16 = 0; k16 < 2; k16++) {
            uint32_t aH[2][4], aL[2][4];
            ldsm4(aH[0], st + SA_HI + a_base + k16 * 32);
            ldsm4(aH[1], st + SA_HI + a_base + 16 * 80 + k16 * 32);
            ldsm4(aL[0], st + SA_LO + a_base + k16 * 32);
            ldsm4(aL[1], st + SA_LO + a_base + 16 * 80 + k16 * 32);
#pragma unroll
            for (int g = 0; g < 5; g++) {
                uint32_t bH[4], bL[4];
                ldsm4(bH, st + SB_HI + b_base + g * 16 * 80 + k16 * 32);
                ldsm4(bL, st + SB_LO + b_base + g * 16 * 80 + k16 * 32);
                mma16816(acc[0][2 * g], aH[0], bH);
                mma16816(acc[0][2 * g + 1], aH[0], bH + 2);
                mma16816(acc[1][2 * g], aH[1], bH);
                mma16816(acc[1][2 * g + 1], aH[1], bH + 2);
                mma16816(acc[0][2 * g], aH[0], bL);
                mma16816(acc[0][2 * g + 1], aH[0], bL + 2);
                mma16816(acc[1][2 * g], aH[1], bL);
                mma16816(acc[1][2 * g + 1], aH[1], bL + 2);
                mma16816(acc[0][2 * g], aL[0], bH);
                mma16816(acc[0][2 * g + 1], aL[0], bH + 2);
                mma16816(acc[1][2 * g], aL[1], bH);
                mma16816(acc[1][2 * g + 1], aL[1], bH + 2);
            }
        }
        if (kc + 2 < 25) load_stage((kc + 2) % 3, kc + 2);
        cp_commit();
    }

#pragma unroll
    for (int i = 0; i < 2; i++) {
        int ra = mtile * BM + wm * 32 + i * 16 + (lid >> 2);
#pragma unroll
        for (int half = 0; half < 2; half++) {
            int r = ra + half * 8;
            if (r >= M) continue;
#pragma unroll
            for (int j = 0; j < 10; j++) {
                int col = ntile * BN + wn * 80 + j * 8 + (lid & 3) * 2;
                float v0 = acc[i][j][half * 2 + 0] + bias[col];
                float v1 = acc[i][j][half * 2 + 1] + bias[col + 1];
                if (MODE == 0) {
                    *(float2*)&C[(size_t)r * ldc + col] = make_float2(v0, v1);
                } else {
                    float2* p = (float2*)&C[(size_t)r * ldc + col];
                    float2 o = *p;
                    *p = make_float2(o.x * 0.8f + 0.2f * v0, o.y * 0.8f + 0.2f * v1);
                }
            }
        }
    }
}

// ---------------------------------------------------------------------------
// splits
// ---------------------------------------------------------------------------
__device__ __forceinline__ void split2(float v, unsigned short& hs, unsigned short& ls) {
    __nv_bfloat16 hb = __float2bfloat16(v);
    float hf = __bfloat162float(hb);
    __nv_bfloat16 lb = __float2bfloat16(v - hf);
    hs = __bfloat16_as_ushort(hb);
    ls = __bfloat16_as_ushort(lb);
}
__device__ __forceinline__ void split4(float4 v, uint2& hq, uint2& lq) {
    unsigned short h0, h1, h2, h3, l0, l1, l2, l3;
    split2(v.x, h0, l0); split2(v.y, h1, l1); split2(v.z, h2, l2); split2(v.w, h3, l3);
    hq = make_uint2(h0 | (h1 << 16), h2 | (h3 << 16));
    lq = make_uint2(l0 | (l1 << 16), l2 | (l3 << 16));
}

__global__ void conv_a_k(const float* __restrict__ A, int n, __nv_bfloat16* __restrict__ T)
{
    int i4 = (blockIdx.x * blockDim.x + threadIdx.x) * 4;
    if (i4 >= n) return;
    float4 v = *(const float4*)(A + i4);
    uint2 hq, lq;
    split4(v, hq, lq);
    *(uint2*)((unsigned short*)T + i4) = hq;
    *(uint2*)((unsigned short*)T + n + i4) = lq;
}

// weight transpose into packed plane groups
__global__ void conv_w_k(const float* __restrict__ Ws, __nv_bfloat16* __restrict__ TW)
{
    static const int BASE[10]   = {0, 3840000, 5120000, 0, 0, 5120000, 8960000, 10240000, 5120000, 11520000};
    static const int NROWS[10]  = {2400, 800, 2400, 2400, 2400, 2400, 800, 800, 2400, 800};
    static const int ROWOFF[10] = {0, 0, 0, 800, 1600, 800, 0, 0, 1600, 0};
    __shared__ float t[32][33];
    int wi = blockIdx.z;
    const float* W = Ws + (size_t)wi * (DD * DD);
    __nv_bfloat16* hi = TW + BASE[wi] + (size_t)ROWOFF[wi] * DD;
    __nv_bfloat16* lo = TW + BASE[wi] + (size_t)NROWS[wi] * DD + (size_t)ROWOFF[wi] * DD;
    int tx = threadIdx.x, ty = threadIdx.y;
    int kb = blockIdx.y * 32, nb = blockIdx.x * 32;
#pragma unroll
    for (int r = 0; r < 4; r++)
        t[ty + r * 8][tx] = W[(size_t)(kb + ty + r * 8) * DD + nb + tx];
    __syncthreads();
#pragma unroll
    for (int r = 0; r < 4; r++) {
        int nrow = nb + ty + r * 8;
        int kcol = kb + tx;
        unsigned short hs, ls;
        split2(t[tx][ty + r * 8], hs, ls);
        hi[(size_t)nrow * DD + kcol] = __ushort_as_bfloat16(hs);
        lo[(size_t)nrow * DD + kcol] = __ushort_as_bfloat16(ls);
    }
}

// fused cross-gate + split: t1 = c*Dh1, t2 = c*Dh2 -> bf16 hi/lo planes
__global__ void crossconv_k(const float* __restrict__ P1, const float* __restrict__ P2,
                            __nv_bfloat16* __restrict__ T1, __nv_bfloat16* __restrict__ T2)
{
    int i4 = (blockIdx.x * blockDim.x + threadIdx.x) * 4;
    if (i4 >= NA_ * DD) return;
    int r = i4 / DD, c = i4 % DD;
    size_t po = (size_t)r * 2400 + 800 + c;
    float4 d1 = *(const float4*)(P1 + po);
    float4 d2 = *(const float4*)(P2 + po);
    float4 t1v, t2v;
    float f;
    f = 1.f / (fabsf(d1.x - d2.x) + 1.f); t1v.x = f * d1.x; t2v.x = f * d2.x;
    f = 1.f / (fabsf(d1.y - d2.y) + 1.f); t1v.y = f * d1.y; t2v.y = f * d2.y;
    f = 1.f / (fabsf(d1.z - d2.z) + 1.f); t1v.z = f * d1.z; t2v.z = f * d2.z;
    f = 1.f / (fabsf(d1.w - d2.w) + 1.f); t1v.w = f * d1.w; t2v.w = f * d2.w;
    uint2 hq, lq;
    split4(t1v, hq, lq);
    *(uint2*)((unsigned short*)T1 + i4) = hq;
    *(uint2*)((unsigned short*)T1 + NA_ * DD + i4) = lq;
    split4(t2v, hq, lq);
    *(uint2*)((unsigned short*)T2 + i4) = hq;
    *(uint2*)((unsigned short*)T2 + NA_ * DD + i4) = lq;
}

// ---------------------------------------------------------------------------
// small kernels
// ---------------------------------------------------------------------------
__global__ void zero_k(float* p, int n) {
    int i = blockIdx.x * blockDim.x + threadIdx.x;
    if (i < n) p[i] = 0.f;
}
__global__ void biascat_k(const float* __restrict__ bs, float* __restrict__ bADE,
                          float* __restrict__ bUFI) {
    int i = blockIdx.x * blockDim.x + threadIdx.x;
    if (i >= 2400) return;
    static const int MA[3] = {0, 3, 4};
    static const int MU[3] = {2, 5, 8};
    bADE[i] = bs[MA[i / 800] * 800 + i % 800];
    bUFI[i] = bs[MU[i / 800] * 800 + i % 800];
}
__global__ void count_k(const int* __restrict__ seg, int n, float* cnt) {
    int i = blockIdx.x * blockDim.x + threadIdx.x;
    if (i < n) atomicAdd(&cnt[seg[i]], 1.0f);
}
__global__ void bondpre_k(float* __restrict__ e_out, const float* __restrict__ P,
                          const float* __restrict__ UFI,
                          const int* __restrict__ bond_atoms,
                          const int* __restrict__ bond_graph)
{
    int b = blockIdx.x;
    int i0 = bond_atoms[b * 2];
    int i1 = bond_atoms[b * 2 + 1];
    int g = bond_graph[b];
    const float* a0 = P + (size_t)i0 * 2400;
    const float* a1 = P + (size_t)i1 * 2400;
    const float* cu = UFI + (size_t)g * 2400;
    float* eo = e_out + (size_t)b * DD;
    for (int c = threadIdx.x; c < DD; c += blockDim.x)
        eo[c] += a0[c] + a1[c] + cu[c];
}
__global__ void colstats_k(const float* __restrict__ X, int R,
                           float* __restrict__ sum, float* __restrict__ sumsq)
{
    int col = blockIdx.x * blockDim.x + threadIdx.x;
    if (col >= DD) return;
    int chunk = (R + gridDim.y - 1) / gridDim.y;
    int r0 = blockIdx.y * chunk;
    int r1 = min(r0 + chunk, R);
    float s = 0.f, q = 0.f;
    for (int r = r0; r < r1; r++) {
        float v = X[(size_t)r * DD + col];
        s += v; q += v * v;
    }
    atomicAdd(&sum[col], s);
    atomicAdd(&sumsq[col], q);
}
__global__ void bnprep_k(const float* __restrict__ sum, const float* __restrict__ sumsq,
                         const float* __restrict__ gamma, const float* __restrict__ beta,
                         float Rf, float* __restrict__ scale, float* __restrict__ shift)
{
    int c = blockIdx.x * blockDim.x + threadIdx.x;
    if (c >= DD) return;
    float m = sum[c] / Rf;
    float v = sumsq[c] / Rf - m * m;
    float sc = gamma[c] * rsqrtf(v + 1e-5f);
    scale[c] = sc;
    shift[c] = beta[c] - m * sc;
}
__global__ void bnrelu_k(float* __restrict__ X, int n,
                         const float* __restrict__ scale, const float* __restrict__ shift)
{
    int i = blockIdx.x * blockDim.x + threadIdx.x;
    if (i >= n) return;
    int col = i % DD;
    float y = X[i] * scale[col] + shift[col];
    X[i] = fmaxf(y, 0.f);
}
// fused BN-apply + relu + segment-sum (64-col slices, smem [256][64])
__global__ void bnseg_k(float* __restrict__ X, int M, const int* __restrict__ seg,
                        const float* __restrict__ scale, const float* __restrict__ shift,
                        float* __restrict__ ssum)
{
    extern __shared__ float sm[];   // 16384
    int c0 = blockIdx.x * 64;
    int cl = threadIdx.x & 63;
    int col = c0 + cl;
    int rg = threadIdx.x >> 6;
    for (int i = threadIdx.x; i < 16384; i += 256) sm[i] = 0.f;
    __syncthreads();
    bool ok = col < DD;
    float sc = ok ? scale[col] : 0.f;
    float sh = ok ? shift[col] : 0.f;
    int chunk = (M + gridDim.y - 1) / gridDim.y;
    int r0 = blockIdx.y * chunk;
    int r1 = min(r0 + chunk, M);
    for (int r = r0 + rg; r < r1; r += 4) {
        int g = seg[r];
        if (ok) {
            float y = fmaxf(fmaf(X[(size_t)r * DD + col], sc, sh), 0.f);
            X[(size_t)r * DD + col] = y;
            atomicAdd(&sm[g * 64 + cl], y);
        }
    }
    __syncthreads();
    for (int i = threadIdx.x; i < 16384; i += 256) {
        int g = i >> 6;
        int c = c0 + (i & 63);
        float v = sm[i];
        if (c < DD && v != 0.f) atomicAdd(&ssum[g * DD + c], v);
    }
}
__global__ void atom_k(float* __restrict__ h_out, const float* __restrict__ P,
                       const float* __restrict__ UFI, const float* __restrict__ e_new,
                       const int* __restrict__ atom_bonds, const int* __restrict__ bond_atoms,
                       const int* __restrict__ atom_graph)
{
    int a = blockIdx.x;
    __shared__ int sh_bond[4];
    __shared__ int sh_other[4];
    if (threadIdx.x < 4) {
        int b = atom_bonds[a * 4 + threadIdx.x];
        sh_bond[threadIdx.x] = b;
        int p0 = bond_atoms[b * 2];
        int p1 = bond_atoms[b * 2 + 1];
        sh_other[threadIdx.x] = (p0 != a) ? p0 : p1;
    }
    __syncthreads();
    int g = atom_graph[a];
    const float* e0 = e_new + (size_t)sh_bond[0] * DD;
    const float* e1 = e_new + (size_t)sh_bond[1] * DD;
    const float* e2p = e_new + (size_t)sh_bond[2] * DD;
    const float* e3 = e_new + (size_t)sh_bond[3] * DD;
    const float* E0 = P + (size_t)sh_other[0] * 2400 + 1600;
    const float* E1 = P + (size_t)sh_other[1] * 2400 + 1600;
    const float* E2 = P + (size_t)sh_other[2] * 2400 + 1600;
    const float* E3 = P + (size_t)sh_other[3] * 2400 + 1600;
    const float* dh = P + (size_t)a * 2400 + 800;
    const float* fu = UFI + (size_t)g * 2400 + 800;
    float* ho = h_out + (size_t)a * DD;
    for (int c = threadIdx.x; c < DD; c += blockDim.x) {
        float s0 = 1.f / (1.f + expf(-e0[c]));
        float s1 = 1.f / (1.f + expf(-e1[c]));
        float s2 = 1.f / (1.f + expf(-e2p[c]));
        float s3 = 1.f / (1.f + expf(-e3[c]));
        float num = s0 * E0[c] + s1 * E1[c] + s2 * E2[c] + s3 * E3[c];
        float den = s0 + s1 + s2 + s3 + 1e-6f;
        ho[c] = dh[c] + num / den + fu[c];
    }
}
// per-graph means of both halves, split directly to bf16 planes
__global__ void meanprep_k(const float* __restrict__ ssum, const float* __restrict__ cnts,
                           __nv_bfloat16* __restrict__ mH, __nv_bfloat16* __restrict__ mE)
{
    int i4 = (blockIdx.x * blockDim.x + threadIdx.x) * 4;
    if (i4 >= NG_ * DD) return;
    int g = i4 / DD;
    float cA1 = fmaxf(cnts[g], 1.f),       cA2 = fmaxf(cnts[512 + g], 1.f);
    float cB1 = fmaxf(cnts[256 + g], 1.f), cB2 = fmaxf(cnts[768 + g], 1.f);
    const float* sh1 = ssum + i4;                 // SS_H1
    const float* se1 = ssum + 204800 + i4;        // SS_E1
    const float* sh2 = ssum + 409600 + i4;        // SS_H2
    const float* se2 = ssum + 614400 + i4;        // SS_E2
    float4 vh, ve;
    vh.x = sh1[0] / cA1 + sh2[0] / cA2;  ve.x = se1[0] / cB1 + se2[0] / cB2;
    vh.y = sh1[1] / cA1 + sh2[1] / cA2;  ve.y = se1[1] / cB1 + se2[1] / cB2;
    vh.z = sh1[2] / cA1 + sh2[2] / cA2;  ve.z = se1[2] / cB1 + se2[2] / cB2;
    vh.w = sh1[3] / cA1 + sh2[3] / cA2;  ve.w = se1[3] / cB1 + se2[3] / cB2;
    uint2 hq, lq;
    split4(vh, hq, lq);
    *(uint2*)((unsigned short*)mH + i4) = hq;
    *(uint2*)((unsigned short*)mH + NG_ * DD + i4) = lq;
    split4(ve, hq, lq);
    *(uint2*)((unsigned short*)mE + i4) = hq;
    *(uint2*)((unsigned short*)mE + NG_ * DD + i4) = lq;
}
// u_pre = P6 + P7 + Iu + indicator biases
__global__ void ucomb_k(float* __restrict__ un, const float* __restrict__ P6,
                        const float* __restrict__ P7, const float* __restrict__ UFI,
                        const float* __restrict__ cnts, const float* __restrict__ bs)
{
    int i = blockIdx.x * blockDim.x + threadIdx.x;
    if (i >= NG_ * DD) return;
    int g = i / DD, c = i % DD;
    float indA = (cnts[g] > 0.f ? 1.f : 0.f) + (cnts[512 + g] > 0.f ? 1.f : 0.f);
    float indB = (cnts[256 + g] > 0.f ? 1.f : 0.f) + (cnts[768 + g] > 0.f ? 1.f : 0.f);
    un[i] = P6[i] + P7[i] + UFI[(size_t)g * 2400 + 1600 + c]
          + bs[6 * 800 + c] * indA + bs[7 * 800 + c] * indB;
}

// ---------------------------------------------------------------------------
extern "C" void kernel_launch(void* const* d_in, const int* in_sizes, int n_in,
                              void* d_out, int out_size)
{
    const float* h   = (const float*)d_in[0];
    const float* e   = (const float*)d_in[1];
    const float* h2  = (const float*)d_in[2];
    const float* e2  = (const float*)d_in[3];
    const float* u   = (const float*)d_in[4];
    const float* Ws  = (const float*)d_in[5];
    const float* bs  = (const float*)d_in[6];
    const float* gam = (const float*)d_in[7];
    const float* bet = (const float*)d_in[8];
    const int* ba1 = (const int*)d_in[9];
    const int* ab1 = (const int*)d_in[10];
    const int* ag1 = (const int*)d_in[11];
    const int* bg1 = (const int*)d_in[12];
    const int* ba2 = (const int*)d_in[13];
    const int* ab2 = (const int*)d_in[14];
    const int* ag2 = (const int*)d_in[15];
    const int* bg2 = (const int*)d_in[16];

    float* out = (float*)d_out;
    float* h1n = out;
    float* e1n = out + 16000000;
    float* h2n = out + 35200000;
    float* e2n = out + 51200000;
    float* un  = out + 70400000;

    float* sp = nullptr;
    cudaGetSymbolAddress((void**)&sp, g_scratch);

    float* P1  = sp + O_P1;
    float* P2  = sp + O_P2;
    float* SM  = sp + O_SMALL;
    float* UFI = SM;
    float* ssum  = SM + 614400;
    float* cnts  = SM + 1433600;
    float* bnsum = SM + 1434624;
    float* bnsq  = SM + 1438624;
    float* zbias = SM + 1442624;
    float* bnsc  = SM + 1443424;
    float* bnsh  = SM + 1447424;
    float* bADE  = SM + 1451424;
    float* bUFI  = SM + 1453824;
    __nv_bfloat16* mH = (__nv_bfloat16*)(SM + 1456224);
    __nv_bfloat16* mE = (__nv_bfloat16*)(SM + 1661024);
    float* P6 = SM + 1865824;
    float* P7 = SM + 2070624;

    __nv_bfloat16* tw   = (__nv_bfloat16*)(sp + O_TW);
    __nv_bfloat16* thp  = (__nv_bfloat16*)(sp + O_THp);
    __nv_bfloat16* th2p = (__nv_bfloat16*)(sp + O_TH2p);
    __nv_bfloat16* tep  = (__nv_bfloat16*)(sp + O_TEp);
    __nv_bfloat16* te2p = (__nv_bfloat16*)(sp + O_TE2p);
    __nv_bfloat16* tup  = (__nv_bfloat16*)(sp + O_TUp);

    __nv_bfloat16* TADE = tw + 0;
    __nv_bfloat16* TB1  = tw + 3840000;
    __nv_bfloat16* TUFI = tw + 5120000;
    __nv_bfloat16* TG   = tw + 8960000;
    __nv_bfloat16* TH7  = tw + 10240000;
    __nv_bfloat16* TW9  = tw + 11520000;

    const int NH = NA_ * DD, NE = NB_ * DD, NU = NG_ * DD;

    cudaFuncSetAttribute(hgemm_k<0>, cudaFuncAttributeMaxDynamicSharedMemorySize, SMEM_TOT);
    cudaFuncSetAttribute(hgemm_k<1>, cudaFuncAttributeMaxDynamicSharedMemorySize, SMEM_TOT);
    cudaFuncSetAttribute(bnseg_k, cudaFuncAttributeMaxDynamicSharedMemorySize, 65536);

    // setup
    zero_k<<<(829024 + 255) / 256, 256>>>(ssum, 829024);
    biascat_k<<<10, 256>>>(bs, bADE, bUFI);
    count_k<<<(NA_ + 255) / 256, 256>>>(ag1, NA_, cnts + 0);
    count_k<<<(NB_ + 255) / 256, 256>>>(bg1, NB_, cnts + 256);
    count_k<<<(NA_ + 255) / 256, 256>>>(ag2, NA_, cnts + 512);
    count_k<<<(NB_ + 255) / 256, 256>>>(bg2, NB_, cnts + 768);

    // conversions
    conv_a_k<<<NH / 1024, 256>>>(h,  NH, thp);
    conv_a_k<<<NH / 1024, 256>>>(h2, NH, th2p);
    conv_a_k<<<NE / 1024, 256>>>(e,  NE, tep);
    conv_a_k<<<NE / 1024, 256>>>(e2, NE, te2p);
    conv_a_k<<<NU / 1024, 256>>>(u,  NU, tup);
    conv_w_k<<<dim3(25, 25, 10), dim3(32, 8)>>>(Ws, tw);

    // projections
    hgemm_k<0><<<dim3(15, 157, 2), 256, SMEM_TOT>>>(
        thp, th2p, NH, TADE, TADE, 1920000, bADE, bADE, P1, P2, NA_, 2400);
    hgemm_k<0><<<dim3(5, 188, 2), 256, SMEM_TOT>>>(
        tep, te2p, NE, TB1, TB1, 640000, bs + 800, bs + 800, e1n, e2n, NB_, 800);
    hgemm_k<0><<<dim3(15, 2, 1), 256, SMEM_TOT>>>(
        tup, tup, NU, TUFI, TUFI, 1920000, bUFI, bUFI, UFI, UFI, NG_, 2400);

    // bond update + BN(e) + relu + segsum
    bondpre_k<<<NB_, 256>>>(e1n, P1, UFI, ba1, bg1);
    bondpre_k<<<NB_, 256>>>(e2n, P2, UFI, ba2, bg2);
    {
        dim3 gs((DD + 255) / 256, 64);
        colstats_k<<<gs, 256>>>(e1n, NB_, bnsum + 0, bnsq + 0);
        bnprep_k<<<4, 256>>>(bnsum + 0, bnsq + 0, gam, bet, (float)NB_, bnsc + 0, bnsh + 0);
        colstats_k<<<gs, 256>>>(e2n, NB_, bnsum + 800, bnsq + 800);
        bnprep_k<<<4, 256>>>(bnsum + 800, bnsq + 800, gam, bet, (float)NB_, bnsc + 800, bnsh + 800);
        bnseg_k<<<dim3(13, 12), 256, 65536>>>(e1n, NB_, bg1, bnsc + 0, bnsh + 0, ssum + 204800);
        bnseg_k<<<dim3(13, 12), 256, 65536>>>(e2n, NB_, bg2, bnsc + 800, bnsh + 800, ssum + 614400);
    }

    // atom update (pre-mix h)
    atom_k<<<NA_, 256>>>(h1n, P1, UFI, e1n, ab1, ba1, ag1);
    atom_k<<<NA_, 256>>>(h2n, P2, UFI, e2n, ab2, ba2, ag2);

    // cross + mix
    crossconv_k<<<NH / 1024, 256>>>(P1, P2, thp, th2p);
    hgemm_k<1><<<dim3(5, 157, 2), 256, SMEM_TOT>>>(
        th2p, thp, NH, TW9, TW9, 640000, bs + 9 * 800, bs + 9 * 800, h1n, h2n, NA_, 800);

    // BN(h) + relu + segsum
    {
        dim3 gs((DD + 255) / 256, 64);
        colstats_k<<<gs, 256>>>(h1n, NA_, bnsum + 1600, bnsq + 1600);
        bnprep_k<<<4, 256>>>(bnsum + 1600, bnsq + 1600, gam + 800, bet + 800, (float)NA_, bnsc + 1600, bnsh + 1600);
        colstats_k<<<gs, 256>>>(h2n, NA_, bnsum + 2400, bnsq + 2400);
        bnprep_k<<<4, 256>>>(bnsum + 2400, bnsq + 2400, gam + 800, bet + 800, (float)NA_, bnsc + 2400, bnsh + 2400);
        bnseg_k<<<dim3(13, 12), 256, 65536>>>(h1n, NA_, ag1, bnsc + 1600, bnsh + 1600, ssum + 0);
        bnseg_k<<<dim3(13, 12), 256, 65536>>>(h2n, NA_, ag2, bnsc + 2400, bnsh + 2400, ssum + 409600);
    }

    // global readout on means
    meanprep_k<<<NU / 1024, 256>>>(ssum, cnts, mH, mE);
    hgemm_k<0><<<dim3(5, 2, 2), 256, SMEM_TOT>>>(
        mH, mE, (size_t)NU, TG, TH7, 640000, zbias, zbias, P6, P7, NG_, 800);

    // combine + BN(u) + relu
    ucomb_k<<<(NU + 255) / 256, 256>>>(un, P6, P7, UFI, cnts, bs);
    {
        dim3 gs((DD + 255) / 256, 8);
        colstats_k<<<gs, 256>>>(un, NG_, bnsum + 3200, bnsq + 3200);
        bnprep_k<<<4, 256>>>(bnsum + 3200, bnsq + 3200, gam + 1600, bet + 1600, (float)NG_, bnsc + 3200, bnsh + 3200);
        bnrelu_k<<<(NU + 255) / 256, 256>>>(un, NU, bnsc + 3200, bnsh + 3200);
    }
}

// round 6
// speedup vs baseline: 3.8128x; 1.1863x over previous
#include <cuda_runtime.h>
#include <cuda_fp16.h>
#include <cstdint>
#include <math.h>

#define DD 800
#define NA_ 20000
#define NB_ 24000
#define NG_ 256

// ---- HMMA GEMM tiling (fp16 2-pass asymmetric split) ----
#define BM 128
#define BN 160
#define BK 32
#define SA_HI 0
#define SA_LO 10240
#define SB_   20480
#define STAGE_B 33280
#define SMEM_TOT (3 * STAGE_B)   // 99840

// ---------------------------------------------------------------------------
// Scratch layout (float offsets)
// ---------------------------------------------------------------------------
static constexpr size_t O_P1 = 0;             // [20000][2400]  A|D|E half1
static constexpr size_t O_P2 = 48000000;      // half2
static constexpr size_t O_SMALL = 96000000;
static constexpr size_t O_TW   = 98400000;    // 6.4M fp16 = 3.2M floats weight planes
static constexpr size_t O_THp  = 104800000;   // h hi/lo fp16 planes (16M floats)
static constexpr size_t O_TH2p = 120800000;
static constexpr size_t O_TEp  = 136800000;   // e planes (19.2M)
static constexpr size_t O_TE2p = 156000000;
static constexpr size_t O_TUp  = 175200000;
__device__ __align__(1024) float g_scratch[176000000];

// ---------------------------------------------------------------------------
__device__ __forceinline__ uint32_t smem_u32(const void* p) {
    uint32_t a;
    asm("{ .reg .u64 t; cvta.to.shared.u64 t, %1; cvt.u32.u64 %0, t; }" : "=r"(a) : "l"(p));
    return a;
}
__device__ __forceinline__ void cp16(uint32_t saddr, const void* gaddr) {
    asm volatile("cp.async.cg.shared.global [%0], [%1], 16;" :: "r"(saddr), "l"(gaddr));
}
__device__ __forceinline__ void cp_commit() {
    asm volatile("cp.async.commit_group;" ::: "memory");
}
__device__ __forceinline__ void cp_wait1() {
    asm volatile("cp.async.wait_group 1;" ::: "memory");
}
__device__ __forceinline__ void cp_wait0() {
    asm volatile("cp.async.wait_group 0;" ::: "memory");
}
__device__ __forceinline__ void ldsm4(uint32_t* r, uint32_t addr) {
    asm volatile("ldmatrix.sync.aligned.m8n8.x4.shared.b16 {%0,%1,%2,%3}, [%4];"
                 : "=r"(r[0]), "=r"(r[1]), "=r"(r[2]), "=r"(r[3]) : "r"(addr));
}
__device__ __forceinline__ void mma16816(float* c, const uint32_t* a, const uint32_t* b) {
    asm volatile(
        "mma.sync.aligned.m16n8k16.row.col.f32.f16.f16.f32 "
        "{%0,%1,%2,%3}, {%4,%5,%6,%7}, {%8,%9}, {%0,%1,%2,%3};"
        : "+f"(c[0]), "+f"(c[1]), "+f"(c[2]), "+f"(c[3])
        : "r"(a[0]), "r"(a[1]), "r"(a[2]), "r"(a[3]), "r"(b[0]), "r"(b[1]));
}

// ---------------------------------------------------------------------------
// fp16x2 HMMA GEMM: A split hi/lo, B single fp16 plane.
// MODE 0: store acc+bias
// MODE 1: C = 0.8*C + 0.2*(acc+bias), accumulate BN stats
// MODE 3: C = acc+bias + Ah[i0]+Ah[i1]+Cu[g] (bond fuse), accumulate BN stats
// ---------------------------------------------------------------------------
template<int MODE>
__global__ __launch_bounds__(256, 1)
void hgemm_k(const __half* __restrict__ Ah0, const __half* __restrict__ Ah1, size_t nA,
             const __half* __restrict__ B0_, const __half* __restrict__ B1_,
             const float* __restrict__ bias0, const float* __restrict__ bias1,
             int bm0, int bm1, int bm2,
             float* __restrict__ C0, float* __restrict__ C1, int M, int ldc,
             const int* __restrict__ ba0, const int* __restrict__ ba1p,
             const int* __restrict__ bg0, const int* __restrict__ bg1p,
             const float* __restrict__ P0g, const float* __restrict__ P1g,
             const float* __restrict__ CuB,
             float* __restrict__ st0, float* __restrict__ st1)
{
    extern __shared__ char smem[];
    uint32_t sb = smem_u32(smem);
    int tid = threadIdx.x;
    int lid = tid & 31, wid = tid >> 5;
    int wm = wid & 3, wn = wid >> 2;
    int ntile = blockIdx.x, mtile = blockIdx.y, z = blockIdx.z;

    const __half* Ahi = z ? Ah1 : Ah0;
    const __half* Alo = Ahi + nA;
    const __half* Bp  = z ? B1_ : B0_;
    const float* bias = z ? bias1 : bias0;

    int arow[2], acol[2];
    uint32_t asoff[2];
#pragma unroll
    for (int t = 0; t < 2; t++) {
        int q = tid + t * 256;
        int r = q >> 2, c = q & 3;
        arow[t] = min(mtile * BM + r, M - 1);
        acol[t] = c * 8;
        asoff[t] = r * 80 + c * 16;
    }
    int brow[3], bcol[3];
    uint32_t bsoff[3];
#pragma unroll
    for (int t = 0; t < 3; t++) {
        int q = tid + t * 256;
        int r = q >> 2, c = q & 3;
        brow[t] = ntile * BN + r;
        bcol[t] = c * 8;
        bsoff[t] = r * 80 + c * 16;
    }
    bool b3 = (tid < 128);

    auto load_stage = [&](int s, int kc) {
        uint32_t st = sb + s * STAGE_B;
        int k0 = kc * BK;
#pragma unroll
        for (int t = 0; t < 2; t++) {
            size_t go = (size_t)arow[t] * DD + k0 + acol[t];
            cp16(st + SA_HI + asoff[t], Ahi + go);
            cp16(st + SA_LO + asoff[t], Alo + go);
        }
#pragma unroll
        for (int t = 0; t < 2; t++)
            cp16(st + SB_ + bsoff[t], Bp + (size_t)brow[t] * DD + k0 + bcol[t]);
        if (b3)
            cp16(st + SB_ + bsoff[2], Bp + (size_t)brow[2] * DD + k0 + bcol[2]);
    };

    float acc[2][10][4];
#pragma unroll
    for (int i = 0; i < 2; i++)
#pragma unroll
        for (int j = 0; j < 10; j++)
#pragma unroll
            for (int k = 0; k < 4; k++) acc[i][j][k] = 0.f;

    uint32_t aswz = (lid & 15) * 80 + (lid >> 4) * 16;
    uint32_t bswz = ((lid & 7) + ((lid & 16) ? 8 : 0)) * 80 + ((lid >> 3) & 1) * 16;
    uint32_t a_base = (wm * 32) * 80 + aswz;
    uint32_t b_base = (wn * 80) * 80 + bswz;

    load_stage(0, 0); cp_commit();
    load_stage(1, 1); cp_commit();

#pragma unroll 1
    for (int kc = 0; kc < 25; kc++) {
        int s = kc % 3;
        cp_wait1();
        __syncthreads();
        uint32_t st = sb + s * STAGE_B;
#pragma unroll
        for (int k16 = 0; k16 < 2; k16++) {
            uint32_t aH[2][4], aL[2][4];
            ldsm4(aH[0], st + SA_HI + a_base + k16 * 32);
            ldsm4(aH[1], st + SA_HI + a_base + 16 * 80 + k16 * 32);
            ldsm4(aL[0], st + SA_LO + a_base + k16 * 32);
            ldsm4(aL[1], st + SA_LO + a_base + 16 * 80 + k16 * 32);
#pragma unroll
            for (int g = 0; g < 5; g++) {
                uint32_t bH[4];
                ldsm4(bH, st + SB_ + b_base + g * 16 * 80 + k16 * 32);
                mma16816(acc[0][2 * g],     aH[0], bH);
                mma16816(acc[0][2 * g + 1], aH[0], bH + 2);
                mma16816(acc[1][2 * g],     aH[1], bH);
                mma16816(acc[1][2 * g + 1], aH[1], bH + 2);
                mma16816(acc[0][2 * g],     aL[0], bH);
                mma16816(acc[0][2 * g + 1], aL[0], bH + 2);
                mma16816(acc[1][2 * g],     aL[1], bH);
                mma16816(acc[1][2 * g + 1], aL[1], bH + 2);
            }
        }
        if (kc + 2 < 25) load_stage((kc + 2) % 3, kc + 2);
        cp_commit();
    }

    // ---------------- epilogue ----------------
    cp_wait0();
    __syncthreads();
    float* smst = (float*)smem;     // [2][160] stats staging (reuses stage smem)
    if (MODE != 0) {
        for (int i = tid; i < 320; i += 256) smst[i] = 0.f;
        __syncthreads();
    }

    int bseg = ntile / 5;
    const float* bp = bias + (bseg == 0 ? bm0 : bseg == 1 ? bm1 : bm2) * 800 - bseg * 800;

    float* C  = z ? C1 : C0;
    float* st = z ? st1 : st0;
    const int* BA = z ? ba1p : ba0;
    const int* BG = z ? bg1p : bg0;
    const float* Pg = z ? P1g : P0g;

    int rows[4];
    bool rok[4];
    const float *pA0[4], *pA1[4], *pCu[4];
#pragma unroll
    for (int q = 0; q < 4; q++) {
        int i = q >> 1, half = q & 1;
        int r = mtile * BM + wm * 32 + i * 16 + half * 8 + (lid >> 2);
        rows[q] = r;
        rok[q] = r < M;
        if (MODE == 3 && rok[q]) {
            int2 bb = ((const int2*)BA)[r];
            int gg = BG[r];
            pA0[q] = Pg + (size_t)bb.x * 2400;
            pA1[q] = Pg + (size_t)bb.y * 2400;
            pCu[q] = CuB + (size_t)gg * 2400;
        }
    }

#pragma unroll
    for (int j = 0; j < 10; j++) {
        int colloc = wn * 80 + j * 8 + (lid & 3) * 2;
        int col = ntile * 160 + colloc;
        float2 bv = *(const float2*)(bp + col);
        float s0 = 0.f, s1 = 0.f, q0 = 0.f, q1 = 0.f;
#pragma unroll
        for (int q = 0; q < 4; q++) {
            if (!rok[q]) continue;
            int i = q >> 1, half = q & 1;
            float v0 = acc[i][j][half * 2 + 0] + bv.x;
            float v1 = acc[i][j][half * 2 + 1] + bv.y;
            if (MODE == 3) {
                float2 a0v = *(const float2*)(pA0[q] + col);
                float2 a1v = *(const float2*)(pA1[q] + col);
                float2 cuv = *(const float2*)(pCu[q] + col);
                v0 += a0v.x + a1v.x + cuv.x;
                v1 += a0v.y + a1v.y + cuv.y;
            }
            size_t co = (size_t)rows[q] * ldc + col;
            if (MODE == 1) {
                float2 o = *(float2*)&C[co];
                v0 = o.x * 0.8f + 0.2f * v0;
                v1 = o.y * 0.8f + 0.2f * v1;
            }
            *(float2*)&C[co] = make_float2(v0, v1);
            if (MODE != 0) {
                s0 += v0; q0 += v0 * v0;
                s1 += v1; q1 += v1 * v1;
            }
        }
        if (MODE != 0) {
#pragma unroll
            for (int d = 4; d < 32; d <<= 1) {
                s0 += __shfl_xor_sync(0xFFFFFFFFu, s0, d);
                s1 += __shfl_xor_sync(0xFFFFFFFFu, s1, d);
                q0 += __shfl_xor_sync(0xFFFFFFFFu, q0, d);
                q1 += __shfl_xor_sync(0xFFFFFFFFu, q1, d);
            }
            if (lid < 4) {
                atomicAdd(&smst[colloc], s0);
                atomicAdd(&smst[colloc + 1], s1);
                atomicAdd(&smst[160 + colloc], q0);
                atomicAdd(&smst[160 + colloc + 1], q1);
            }
        }
    }
    if (MODE != 0) {
        __syncthreads();
        for (int i = tid; i < 160; i += 256) {
            atomicAdd(&st[ntile * 160 + i], smst[i]);
            atomicAdd(&st[4000 + ntile * 160 + i], smst[160 + i]);
        }
    }
}

// ---------------------------------------------------------------------------
// splits (fp16 hi/lo)
// ---------------------------------------------------------------------------
__device__ __forceinline__ void split2h(float v, unsigned short& hs, unsigned short& ls) {
    __half hb = __float2half_rn(v);
    __half lb = __float2half_rn(v - __half2float(hb));
    hs = __half_as_ushort(hb);
    ls = __half_as_ushort(lb);
}
__device__ __forceinline__ void split4h(float4 v, uint2& hq, uint2& lq) {
    unsigned short h0, h1, h2, h3, l0, l1, l2, l3;
    split2h(v.x, h0, l0); split2h(v.y, h1, l1); split2h(v.z, h2, l2); split2h(v.w, h3, l3);
    hq = make_uint2(h0 | (h1 << 16), h2 | (h3 << 16));
    lq = make_uint2(l0 | (l1 << 16), l2 | (l3 << 16));
}

__global__ void conv_a_k(const float* __restrict__ A, int n, __half* __restrict__ T)
{
    int i4 = (blockIdx.x * blockDim.x + threadIdx.x) * 4;
    if (i4 >= n) return;
    float4 v = *(const float4*)(A + i4);
    uint2 hq, lq;
    split4h(v, hq, lq);
    *(uint2*)((unsigned short*)T + i4) = hq;
    *(uint2*)((unsigned short*)T + n + i4) = lq;
}

// weight transpose -> single fp16 plane, packed groups
__global__ void conv_w_k(const float* __restrict__ Ws, __half* __restrict__ TW)
{
    static const int BASE[10]   = {0, 1920000, 2560000, 0, 0, 2560000, 4480000, 5120000, 2560000, 5760000};
    static const int ROWOFF[10] = {0, 0, 0, 800, 1600, 800, 0, 0, 1600, 0};
    __shared__ float t[32][33];
    int wi = blockIdx.z;
    const float* W = Ws + (size_t)wi * (DD * DD);
    __half* hi = TW + BASE[wi] + (size_t)ROWOFF[wi] * DD;
    int tx = threadIdx.x, ty = threadIdx.y;
    int kb = blockIdx.y * 32, nb = blockIdx.x * 32;
#pragma unroll
    for (int r = 0; r < 4; r++)
        t[ty + r * 8][tx] = W[(size_t)(kb + ty + r * 8) * DD + nb + tx];
    __syncthreads();
#pragma unroll
    for (int r = 0; r < 4; r++) {
        int nrow = nb + ty + r * 8;
        int kcol = kb + tx;
        hi[(size_t)nrow * DD + kcol] = __float2half_rn(t[tx][ty + r * 8]);
    }
}

// fused cross-gate + split: t1 = c*Dh1, t2 = c*Dh2 -> fp16 hi/lo planes
__global__ void crossconv_k(const float* __restrict__ P1, const float* __restrict__ P2,
                            __half* __restrict__ T1, __half* __restrict__ T2)
{
    int i4 = (blockIdx.x * blockDim.x + threadIdx.x) * 4;
    if (i4 >= NA_ * DD) return;
    int r = i4 / DD, c = i4 % DD;
    size_t po = (size_t)r * 2400 + 800 + c;
    float4 d1 = *(const float4*)(P1 + po);
    float4 d2 = *(const float4*)(P2 + po);
    float4 t1v, t2v;
    float f;
    f = 1.f / (fabsf(d1.x - d2.x) + 1.f); t1v.x = f * d1.x; t2v.x = f * d2.x;
    f = 1.f / (fabsf(d1.y - d2.y) + 1.f); t1v.y = f * d1.y; t2v.y = f * d2.y;
    f = 1.f / (fabsf(d1.z - d2.z) + 1.f); t1v.z = f * d1.z; t2v.z = f * d2.z;
    f = 1.f / (fabsf(d1.w - d2.w) + 1.f); t1v.w = f * d1.w; t2v.w = f * d2.w;
    uint2 hq, lq;
    split4h(t1v, hq, lq);
    *(uint2*)((unsigned short*)T1 + i4) = hq;
    *(uint2*)((unsigned short*)T1 + NA_ * DD + i4) = lq;
    split4h(t2v, hq, lq);
    *(uint2*)((unsigned short*)T2 + i4) = hq;
    *(uint2*)((unsigned short*)T2 + NA_ * DD + i4) = lq;
}

// ---------------------------------------------------------------------------
__global__ void zero_k(float* p, int n) {
    int i = blockIdx.x * blockDim.x + threadIdx.x;
    if (i < n) p[i] = 0.f;
}
__global__ void count_all_k(const int* __restrict__ ag1, const int* __restrict__ bg1,
                            const int* __restrict__ ag2, const int* __restrict__ bg2,
                            float* __restrict__ cnts)
{
    int y = blockIdx.y;
    int i = blockIdx.x * blockDim.x + threadIdx.x;
    const int* s = (y == 0) ? ag1 : (y == 1) ? bg1 : (y == 2) ? ag2 : bg2;
    int n = (y & 1) ? NB_ : NA_;
    if (i < n) atomicAdd(&cnts[y * 256 + s[i]], 1.0f);
}
__global__ void bnprep_k(const float* __restrict__ sum, const float* __restrict__ sumsq,
                         const float* __restrict__ gamma, const float* __restrict__ beta,
                         float Rf, float* __restrict__ scale, float* __restrict__ shift)
{
    int c = blockIdx.x * blockDim.x + threadIdx.x;
    if (c >= DD) return;
    float m = sum[c] / Rf;
    float v = sumsq[c] / Rf - m * m;
    float sc = gamma[c] * rsqrtf(v + 1e-5f);
    scale[c] = sc;
    shift[c] = beta[c] - m * sc;
}
__global__ void colstats_k(const float* __restrict__ X, int R,
                           float* __restrict__ sum, float* __restrict__ sumsq)
{
    int col = blockIdx.x * blockDim.x + threadIdx.x;
    if (col >= DD) return;
    int chunk = (R + gridDim.y - 1) / gridDim.y;
    int r0 = blockIdx.y * chunk;
    int r1 = min(r0 + chunk, R);
    float s = 0.f, q = 0.f;
    for (int r = r0; r < r1; r++) {
        float v = X[(size_t)r * DD + col];
        s += v; q += v * v;
    }
    atomicAdd(&sum[col], s);
    atomicAdd(&sumsq[col], q);
}
__global__ void bnrelu_k(float* __restrict__ X, int n,
                         const float* __restrict__ scale, const float* __restrict__ shift)
{
    int i = blockIdx.x * blockDim.x + threadIdx.x;
    if (i >= n) return;
    int col = i % DD;
    X[i] = fmaxf(fmaf(X[i], scale[col], shift[col]), 0.f);
}
// fused BN-apply + relu + segment-sum
__global__ void bnseg_k(float* __restrict__ X, int M, const int* __restrict__ seg,
                        const float* __restrict__ scale, const float* __restrict__ shift,
                        float* __restrict__ ssum)
{
    extern __shared__ float sm[];
    int c0 = blockIdx.x * 64;
    int cl = threadIdx.x & 63;
    int col = c0 + cl;
    int rg = threadIdx.x >> 6;
    for (int i = threadIdx.x; i < 16384; i += 256) sm[i] = 0.f;
    __syncthreads();
    bool ok = col < DD;
    float sc = ok ? scale[col] : 0.f;
    float sh = ok ? shift[col] : 0.f;
    int chunk = (M + gridDim.y - 1) / gridDim.y;
    int r0 = blockIdx.y * chunk;
    int r1 = min(r0 + chunk, M);
    for (int r = r0 + rg; r < r1; r += 4) {
        int g = seg[r];
        if (ok) {
            float y = fmaxf(fmaf(X[(size_t)r * DD + col], sc, sh), 0.f);
            X[(size_t)r * DD + col] = y;
            atomicAdd(&sm[g * 64 + cl], y);
        }
    }
    __syncthreads();
    for (int i = threadIdx.x; i < 16384; i += 256) {
        int g = i >> 6;
        int c = c0 + (i & 63);
        float v = sm[i];
        if (c < DD && v != 0.f) atomicAdd(&ssum[g * DD + c], v);
    }
}
__global__ void atom_k(float* __restrict__ h_out, const float* __restrict__ P,
                       const float* __restrict__ UFI, const float* __restrict__ e_new,
                       const int* __restrict__ atom_bonds, const int* __restrict__ bond_atoms,
                       const int* __restrict__ atom_graph)
{
    int a = blockIdx.x;
    __shared__ int sh_bond[4];
    __shared__ int sh_other[4];
    if (threadIdx.x < 4) {
        int b = atom_bonds[a * 4 + threadIdx.x];
        sh_bond[threadIdx.x] = b;
        int p0 = bond_atoms[b * 2];
        int p1 = bond_atoms[b * 2 + 1];
        sh_other[threadIdx.x] = (p0 != a) ? p0 : p1;
    }
    __syncthreads();
    int g = atom_graph[a];
    const float* e0 = e_new + (size_t)sh_bond[0] * DD;
    const float* e1 = e_new + (size_t)sh_bond[1] * DD;
    const float* e2p = e_new + (size_t)sh_bond[2] * DD;
    const float* e3 = e_new + (size_t)sh_bond[3] * DD;
    const float* E0 = P + (size_t)sh_other[0] * 2400 + 1600;
    const float* E1 = P + (size_t)sh_other[1] * 2400 + 1600;
    const float* E2 = P + (size_t)sh_other[2] * 2400 + 1600;
    const float* E3 = P + (size_t)sh_other[3] * 2400 + 1600;
    const float* dh = P + (size_t)a * 2400 + 800;
    const float* fu = UFI + (size_t)g * 2400 + 800;
    float* ho = h_out + (size_t)a * DD;
    for (int c = threadIdx.x; c < DD; c += blockDim.x) {
        float s0 = 1.f / (1.f + expf(-e0[c]));
        float s1 = 1.f / (1.f + expf(-e1[c]));
        float s2 = 1.f / (1.f + expf(-e2p[c]));
        float s3 = 1.f / (1.f + expf(-e3[c]));
        float num = s0 * E0[c] + s1 * E1[c] + s2 * E2[c] + s3 * E3[c];
        float den = s0 + s1 + s2 + s3 + 1e-6f;
        ho[c] = dh[c] + num / den + fu[c];
    }
}
__global__ void meanprep_k(const float* __restrict__ ssum, const float* __restrict__ cnts,
                           __half* __restrict__ mH, __half* __restrict__ mE)
{
    int i4 = (blockIdx.x * blockDim.x + threadIdx.x) * 4;
    if (i4 >= NG_ * DD) return;
    int g = i4 / DD;
    float cA1 = fmaxf(cnts[g], 1.f),       cA2 = fmaxf(cnts[512 + g], 1.f);
    float cB1 = fmaxf(cnts[256 + g], 1.f), cB2 = fmaxf(cnts[768 + g], 1.f);
    const float* sh1 = ssum + i4;
    const float* se1 = ssum + 204800 + i4;
    const float* sh2 = ssum + 409600 + i4;
    const float* se2 = ssum + 614400 + i4;
    float4 vh, ve;
    vh.x = sh1[0] / cA1 + sh2[0] / cA2;  ve.x = se1[0] / cB1 + se2[0] / cB2;
    vh.y = sh1[1] / cA1 + sh2[1] / cA2;  ve.y = se1[1] / cB1 + se2[1] / cB2;
    vh.z = sh1[2] / cA1 + sh2[2] / cA2;  ve.z = se1[2] / cB1 + se2[2] / cB2;
    vh.w = sh1[3] / cA1 + sh2[3] / cA2;  ve.w = se1[3] / cB1 + se2[3] / cB2;
    uint2 hq, lq;
    split4h(vh, hq, lq);
    *(uint2*)((unsigned short*)mH + i4) = hq;
    *(uint2*)((unsigned short*)mH + NG_ * DD + i4) = lq;
    split4h(ve, hq, lq);
    *(uint2*)((unsigned short*)mE + i4) = hq;
    *(uint2*)((unsigned short*)mE + NG_ * DD + i4) = lq;
}
__global__ void ucomb_k(float* __restrict__ un, const float* __restrict__ P6,
                        const float* __restrict__ P7, const float* __restrict__ UFI,
                        const float* __restrict__ cnts, const float* __restrict__ bs)
{
    int i = blockIdx.x * blockDim.x + threadIdx.x;
    if (i >= NG_ * DD) return;
    int g = i / DD, c = i % DD;
    float indA = (cnts[g] > 0.f ? 1.f : 0.f) + (cnts[512 + g] > 0.f ? 1.f : 0.f);
    float indB = (cnts[256 + g] > 0.f ? 1.f : 0.f) + (cnts[768 + g] > 0.f ? 1.f : 0.f);
    un[i] = P6[i] + P7[i] + UFI[(size_t)g * 2400 + 1600 + c]
          + bs[6 * 800 + c] * indA + bs[7 * 800 + c] * indB;
}

// ---------------------------------------------------------------------------
extern "C" void kernel_launch(void* const* d_in, const int* in_sizes, int n_in,
                              void* d_out, int out_size)
{
    const float* h   = (const float*)d_in[0];
    const float* e   = (const float*)d_in[1];
    const float* h2  = (const float*)d_in[2];
    const float* e2  = (const float*)d_in[3];
    const float* u   = (const float*)d_in[4];
    const float* Ws  = (const float*)d_in[5];
    const float* bs  = (const float*)d_in[6];
    const float* gam = (const float*)d_in[7];
    const float* bet = (const float*)d_in[8];
    const int* ba1 = (const int*)d_in[9];
    const int* ab1 = (const int*)d_in[10];
    const int* ag1 = (const int*)d_in[11];
    const int* bg1 = (const int*)d_in[12];
    const int* ba2 = (const int*)d_in[13];
    const int* ab2 = (const int*)d_in[14];
    const int* ag2 = (const int*)d_in[15];
    const int* bg2 = (const int*)d_in[16];

    float* out = (float*)d_out;
    float* h1n = out;
    float* e1n = out + 16000000;
    float* h2n = out + 35200000;
    float* e2n = out + 51200000;
    float* un  = out + 70400000;

    float* sp = nullptr;
    cudaGetSymbolAddress((void**)&sp, g_scratch);

    float* P1  = sp + O_P1;
    float* P2  = sp + O_P2;
    float* SM  = sp + O_SMALL;
    float* UFI = SM;
    float* ssum  = SM + 614400;
    float* cnts  = SM + 1433600;
    float* bnsum = SM + 1434624;
    float* bnsq  = SM + 1438624;   // bnsum + 4000
    float* zbias = SM + 1442624;
    float* bnsc  = SM + 1443424;
    float* bnsh  = SM + 1447424;
    __half* mH = (__half*)(SM + 1456224);
    __half* mE = (__half*)(SM + 1661024);
    float* P6 = SM + 1865824;
    float* P7 = SM + 2070624;

    __half* tw   = (__half*)(sp + O_TW);
    __half* thp  = (__half*)(sp + O_THp);
    __half* th2p = (__half*)(sp + O_TH2p);
    __half* tep  = (__half*)(sp + O_TEp);
    __half* te2p = (__half*)(sp + O_TE2p);
    __half* tup  = (__half*)(sp + O_TUp);

    __half* TADE = tw + 0;
    __half* TB1  = tw + 1920000;
    __half* TUFI = tw + 2560000;
    __half* TG   = tw + 4480000;
    __half* TH7  = tw + 5120000;
    __half* TW9  = tw + 5760000;

    const int NH = NA_ * DD, NE = NB_ * DD, NU = NG_ * DD;

    cudaFuncSetAttribute(hgemm_k<0>, cudaFuncAttributeMaxDynamicSharedMemorySize, SMEM_TOT);
    cudaFuncSetAttribute(hgemm_k<1>, cudaFuncAttributeMaxDynamicSharedMemorySize, SMEM_TOT);
    cudaFuncSetAttribute(hgemm_k<3>, cudaFuncAttributeMaxDynamicSharedMemorySize, SMEM_TOT);
    cudaFuncSetAttribute(bnseg_k, cudaFuncAttributeMaxDynamicSharedMemorySize, 65536);

    // 1-5: conversions; launch 6 = ADE GEMM (ncu -s 5 profiles it)
    conv_a_k<<<NH / 1024, 256>>>(h,  NH, thp);
    conv_a_k<<<NH / 1024, 256>>>(h2, NH, th2p);
    conv_a_k<<<NE / 1024, 256>>>(e,  NE, tep);
    conv_a_k<<<NE / 1024, 256>>>(e2, NE, te2p);
    conv_w_k<<<dim3(25, 25, 10), dim3(32, 8)>>>(Ws, tw);

    // 6: ADE projections (both halves)
    hgemm_k<0><<<dim3(15, 157, 2), 256, SMEM_TOT>>>(
        thp, th2p, (size_t)NH, TADE, TADE, bs, bs, 0, 3, 4,
        P1, P2, NA_, 2400,
        nullptr, nullptr, nullptr, nullptr, nullptr, nullptr, nullptr, nullptr, nullptr);

    // setup (before fused-stats GEMMs)
    zero_k<<<(829024 + 255) / 256, 256>>>(ssum, 829024);
    count_all_k<<<dim3(94, 4), 256>>>(ag1, bg1, ag2, bg2, cnts);
    conv_a_k<<<NU / 1024, 256>>>(u, NU, tup);
    hgemm_k<0><<<dim3(15, 2, 1), 256, SMEM_TOT>>>(
        tup, tup, (size_t)NU, TUFI, TUFI, bs, bs, 2, 5, 8,
        UFI, UFI, NG_, 2400,
        nullptr, nullptr, nullptr, nullptr, nullptr, nullptr, nullptr, nullptr, nullptr);

    // e-projection + fused bond update + BN stats
    hgemm_k<3><<<dim3(5, 188, 2), 256, SMEM_TOT>>>(
        tep, te2p, (size_t)NE, TB1, TB1, bs, bs, 1, 1, 1,
        e1n, e2n, NB_, 800,
        ba1, ba2, bg1, bg2, P1, P2, UFI,
        bnsum + 0, bnsum + 800);

    // BN(e) prep + apply + segsum
    bnprep_k<<<4, 256>>>(bnsum + 0, bnsq + 0, gam, bet, (float)NB_, bnsc + 0, bnsh + 0);
    bnprep_k<<<4, 256>>>(bnsum + 800, bnsq + 800, gam, bet, (float)NB_, bnsc + 800, bnsh + 800);
    bnseg_k<<<dim3(13, 12), 256, 65536>>>(e1n, NB_, bg1, bnsc + 0, bnsh + 0, ssum + 204800);
    bnseg_k<<<dim3(13, 12), 256, 65536>>>(e2n, NB_, bg2, bnsc + 800, bnsh + 800, ssum + 614400);

    // atom update (pre-mix h)
    atom_k<<<NA_, 256>>>(h1n, P1, UFI, e1n, ab1, ba1, ag1);
    atom_k<<<NA_, 256>>>(h2n, P2, UFI, e2n, ab2, ba2, ag2);

    // cross + mix (fused BN stats)
    crossconv_k<<<NH / 1024, 256>>>(P1, P2, thp, th2p);
    hgemm_k<1><<<dim3(5, 157, 2), 256, SMEM_TOT>>>(
        th2p, thp, (size_t)NH, TW9, TW9, bs, bs, 9, 9, 9,
        h1n, h2n, NA_, 800,
        nullptr, nullptr, nullptr, nullptr, nullptr, nullptr, nullptr,
        bnsum + 1600, bnsum + 2400);

    // BN(h) prep + apply + segsum
    bnprep_k<<<4, 256>>>(bnsum + 1600, bnsq + 1600, gam + 800, bet + 800, (float)NA_, bnsc + 1600, bnsh + 1600);
    bnprep_k<<<4, 256>>>(bnsum + 2400, bnsq + 2400, gam + 800, bet + 800, (float)NA_, bnsc + 2400, bnsh + 2400);
    bnseg_k<<<dim3(13, 12), 256, 65536>>>(h1n, NA_, ag1, bnsc + 1600, bnsh + 1600, ssum + 0);
    bnseg_k<<<dim3(13, 12), 256, 65536>>>(h2n, NA_, ag2, bnsc + 2400, bnsh + 2400, ssum + 409600);

    // global readout on means
    meanprep_k<<<NU / 1024, 256>>>(ssum, cnts, mH, mE);
    hgemm_k<0><<<dim3(5, 2, 2), 256, SMEM_TOT>>>(
        mH, mE, (size_t)NU, TG, TH7, zbias, zbias, 0, 0, 0,
        P6, P7, NG_, 800,
        nullptr, nullptr, nullptr, nullptr, nullptr, nullptr, nullptr, nullptr, nullptr);

    // combine + BN(u) + relu
    ucomb_k<<<(NU + 255) / 256, 256>>>(un, P6, P7, UFI, cnts, bs);
    {
        dim3 gs((DD + 255) / 256, 8);
        colstats_k<<<gs, 256>>>(un, NG_, bnsum + 3200, bnsq + 3200);
        bnprep_k<<<4, 256>>>(bnsum + 3200, bnsq + 3200, gam + 1600, bet + 1600, (float)NG_, bnsc + 3200, bnsh + 3200);
        bnrelu_k<<<(NU + 255) / 256, 256>>>(un, NU, bnsc + 3200, bnsh + 3200);
    }
}

// round 7
// speedup vs baseline: 5.2570x; 1.3788x over previous
#include <cuda_runtime.h>
#include <cuda_fp16.h>
#include <cstdint>
#include <math.h>

#define DD 800
#define NA_ 20000
#define NB_ 24000
#define NG_ 256

// ---- HMMA GEMM tiling (pure fp16 single pass) ----
#define BM 128
#define BN 160
#define BK 32
#define SA_ 0
#define SB_ 10240
#define STAGE_B 23040
#define SMEM_TOT (3 * STAGE_B)   // 69120

// ---------------------------------------------------------------------------
// Scratch layout (float offsets)
// ---------------------------------------------------------------------------
static constexpr size_t O_P1 = 0;             // [20000][2400]  A|D|E half1
static constexpr size_t O_P2 = 48000000;      // half2
static constexpr size_t O_SMALL = 96000000;
static constexpr size_t O_TW   = 98400000;    // fp16 weight planes (6.4M fp16)
static constexpr size_t O_THp  = 104800000;   // h fp16 plane (8M floats used)
static constexpr size_t O_TH2p = 120800000;
static constexpr size_t O_TEp  = 136800000;
static constexpr size_t O_TE2p = 156000000;
static constexpr size_t O_TUp  = 175200000;
__device__ __align__(1024) float g_scratch[176000000];

// ---------------------------------------------------------------------------
__device__ __forceinline__ uint32_t smem_u32(const void* p) {
    uint32_t a;
    asm("{ .reg .u64 t; cvta.to.shared.u64 t, %1; cvt.u32.u64 %0, t; }" : "=r"(a) : "l"(p));
    return a;
}
__device__ __forceinline__ void cp16(uint32_t saddr, const void* gaddr) {
    asm volatile("cp.async.cg.shared.global [%0], [%1], 16;" :: "r"(saddr), "l"(gaddr));
}
__device__ __forceinline__ void cp_commit() {
    asm volatile("cp.async.commit_group;" ::: "memory");
}
__device__ __forceinline__ void cp_wait1() {
    asm volatile("cp.async.wait_group 1;" ::: "memory");
}
__device__ __forceinline__ void cp_wait0() {
    asm volatile("cp.async.wait_group 0;" ::: "memory");
}
__device__ __forceinline__ void ldsm4(uint32_t* r, uint32_t addr) {
    asm volatile("ldmatrix.sync.aligned.m8n8.x4.shared.b16 {%0,%1,%2,%3}, [%4];"
                 : "=r"(r[0]), "=r"(r[1]), "=r"(r[2]), "=r"(r[3]) : "r"(addr));
}
__device__ __forceinline__ void mma16816(float* c, const uint32_t* a, const uint32_t* b) {
    asm volatile(
        "mma.sync.aligned.m16n8k16.row.col.f32.f16.f16.f32 "
        "{%0,%1,%2,%3}, {%4,%5,%6,%7}, {%8,%9}, {%0,%1,%2,%3};"
        : "+f"(c[0]), "+f"(c[1]), "+f"(c[2]), "+f"(c[3])
        : "r"(a[0]), "r"(a[1]), "r"(a[2]), "r"(a[3]), "r"(b[0]), "r"(b[1]));
}

// ---------------------------------------------------------------------------
// fp16 HMMA GEMM (single pass), z-batched pair.
// MODE 0: store acc+bias
// MODE 1: C = 0.8*C + 0.2*(acc+bias), accumulate BN stats
// MODE 3: C = acc+bias + Ah[i0]+Ah[i1]+Cu[g] (bond fuse), accumulate BN stats
// ---------------------------------------------------------------------------
template<int MODE>
__global__ __launch_bounds__(256, 2)
void hgemm_k(const __half* __restrict__ Ah0, const __half* __restrict__ Ah1,
             const __half* __restrict__ B0_, const __half* __restrict__ B1_,
             const float* __restrict__ bias0, const float* __restrict__ bias1,
             int bm0, int bm1, int bm2,
             float* __restrict__ C0, float* __restrict__ C1, int M, int ldc,
             const int* __restrict__ ba0, const int* __restrict__ ba1p,
             const int* __restrict__ bg0, const int* __restrict__ bg1p,
             const float* __restrict__ P0g, const float* __restrict__ P1g,
             const float* __restrict__ CuB,
             float* __restrict__ st0, float* __restrict__ st1)
{
    extern __shared__ char smem[];
    uint32_t sb = smem_u32(smem);
    int tid = threadIdx.x;
    int lid = tid & 31, wid = tid >> 5;
    int wm = wid & 3, wn = wid >> 2;
    int ntile = blockIdx.x, mtile = blockIdx.y, z = blockIdx.z;

    const __half* Ahp = z ? Ah1 : Ah0;
    const __half* Bp  = z ? B1_ : B0_;
    const float* bias = z ? bias1 : bias0;

    int arow[2], acol[2];
    uint32_t asoff[2];
#pragma unroll
    for (int t = 0; t < 2; t++) {
        int q = tid + t * 256;
        int r = q >> 2, c = q & 3;
        arow[t] = min(mtile * BM + r, M - 1);
        acol[t] = c * 8;
        asoff[t] = r * 80 + c * 16;
    }
    int brow[3], bcol[3];
    uint32_t bsoff[3];
#pragma unroll
    for (int t = 0; t < 3; t++) {
        int q = tid + t * 256;
        int r = q >> 2, c = q & 3;
        brow[t] = ntile * BN + r;
        bcol[t] = c * 8;
        bsoff[t] = r * 80 + c * 16;
    }
    bool b3 = (tid < 128);

    auto load_stage = [&](int s, int kc) {
        uint32_t st = sb + s * STAGE_B;
        int k0 = kc * BK;
#pragma unroll
        for (int t = 0; t < 2; t++)
            cp16(st + SA_ + asoff[t], Ahp + (size_t)arow[t] * DD + k0 + acol[t]);
#pragma unroll
        for (int t = 0; t < 2; t++)
            cp16(st + SB_ + bsoff[t], Bp + (size_t)brow[t] * DD + k0 + bcol[t]);
        if (b3)
            cp16(st + SB_ + bsoff[2], Bp + (size_t)brow[2] * DD + k0 + bcol[2]);
    };

    float acc[2][10][4];
#pragma unroll
    for (int i = 0; i < 2; i++)
#pragma unroll
        for (int j = 0; j < 10; j++)
#pragma unroll
            for (int k = 0; k < 4; k++) acc[i][j][k] = 0.f;

    uint32_t aswz = (lid & 15) * 80 + (lid >> 4) * 16;
    uint32_t bswz = ((lid & 7) + ((lid & 16) ? 8 : 0)) * 80 + ((lid >> 3) & 1) * 16;
    uint32_t a_base = (wm * 32) * 80 + aswz;
    uint32_t b_base = (wn * 80) * 80 + bswz;

    load_stage(0, 0); cp_commit();
    load_stage(1, 1); cp_commit();

#pragma unroll 1
    for (int kc = 0; kc < 25; kc++) {
        int s = kc % 3;
        cp_wait1();
        __syncthreads();
        uint32_t st = sb + s * STAGE_B;
#pragma unroll
        for (int k16 = 0; k16 < 2; k16++) {
            uint32_t aH[2][4];
            ldsm4(aH[0], st + SA_ + a_base + k16 * 32);
            ldsm4(aH[1], st + SA_ + a_base + 16 * 80 + k16 * 32);
#pragma unroll
            for (int g = 0; g < 5; g++) {
                uint32_t bH[4];
                ldsm4(bH, st + SB_ + b_base + g * 16 * 80 + k16 * 32);
                mma16816(acc[0][2 * g],     aH[0], bH);
                mma16816(acc[0][2 * g + 1], aH[0], bH + 2);
                mma16816(acc[1][2 * g],     aH[1], bH);
                mma16816(acc[1][2 * g + 1], aH[1], bH + 2);
            }
        }
        if (kc + 2 < 25) load_stage((kc + 2) % 3, kc + 2);
        cp_commit();
    }

    // ---------------- epilogue ----------------
    cp_wait0();
    __syncthreads();
    float* smst = (float*)smem;
    if (MODE != 0) {
        for (int i = tid; i < 320; i += 256) smst[i] = 0.f;
        __syncthreads();
    }

    int bseg = ntile / 5;
    const float* bp = bias + (bseg == 0 ? bm0 : bseg == 1 ? bm1 : bm2) * 800 - bseg * 800;

    float* C  = z ? C1 : C0;
    float* st = z ? st1 : st0;
    const int* BA = z ? ba1p : ba0;
    const int* BG = z ? bg1p : bg0;
    const float* Pg = z ? P1g : P0g;

    int rows[4];
    bool rok[4];
    const float *pA0[4], *pA1[4], *pCu[4];
#pragma unroll
    for (int q = 0; q < 4; q++) {
        int i = q >> 1, half = q & 1;
        int r = mtile * BM + wm * 32 + i * 16 + half * 8 + (lid >> 2);
        rows[q] = r;
        rok[q] = r < M;
        if (MODE == 3 && rok[q]) {
            int2 bb = ((const int2*)BA)[r];
            int gg = BG[r];
            pA0[q] = Pg + (size_t)bb.x * 2400;
            pA1[q] = Pg + (size_t)bb.y * 2400;
            pCu[q] = CuB + (size_t)gg * 2400;
        }
    }

#pragma unroll
    for (int j = 0; j < 10; j++) {
        int colloc = wn * 80 + j * 8 + (lid & 3) * 2;
        int col = ntile * 160 + colloc;
        float2 bv = *(const float2*)(bp + col);
        float s0 = 0.f, s1 = 0.f, q0 = 0.f, q1 = 0.f;
#pragma unroll
        for (int q = 0; q < 4; q++) {
            if (!rok[q]) continue;
            int i = q >> 1, half = q & 1;
            float v0 = acc[i][j][half * 2 + 0] + bv.x;
            float v1 = acc[i][j][half * 2 + 1] + bv.y;
            if (MODE == 3) {
                float2 a0v = *(const float2*)(pA0[q] + col);
                float2 a1v = *(const float2*)(pA1[q] + col);
                float2 cuv = *(const float2*)(pCu[q] + col);
                v0 += a0v.x + a1v.x + cuv.x;
                v1 += a0v.y + a1v.y + cuv.y;
            }
            size_t co = (size_t)rows[q] * ldc + col;
            if (MODE == 1) {
                float2 o = *(float2*)&C[co];
                v0 = o.x * 0.8f + 0.2f * v0;
                v1 = o.y * 0.8f + 0.2f * v1;
            }
            *(float2*)&C[co] = make_float2(v0, v1);
            if (MODE != 0) {
                s0 += v0; q0 += v0 * v0;
                s1 += v1; q1 += v1 * v1;
            }
        }
        if (MODE != 0) {
#pragma unroll
            for (int d = 4; d < 32; d <<= 1) {
                s0 += __shfl_xor_sync(0xFFFFFFFFu, s0, d);
                s1 += __shfl_xor_sync(0xFFFFFFFFu, s1, d);
                q0 += __shfl_xor_sync(0xFFFFFFFFu, q0, d);
                q1 += __shfl_xor_sync(0xFFFFFFFFu, q1, d);
            }
            if (lid < 4) {
                atomicAdd(&smst[colloc], s0);
                atomicAdd(&smst[colloc + 1], s1);
                atomicAdd(&smst[160 + colloc], q0);
                atomicAdd(&smst[160 + colloc + 1], q1);
            }
        }
    }
    if (MODE != 0) {
        __syncthreads();
        for (int i = tid; i < 160; i += 256) {
            atomicAdd(&st[ntile * 160 + i], smst[i]);
            atomicAdd(&st[4000 + ntile * 160 + i], smst[160 + i]);
        }
    }
}

// ---------------------------------------------------------------------------
// conversions (plain fp16 casts)
// ---------------------------------------------------------------------------
__global__ void conv_a_k(const float* __restrict__ A, int n, __half* __restrict__ T)
{
    int i4 = (blockIdx.x * blockDim.x + threadIdx.x) * 4;
    if (i4 >= n) return;
    float4 v = *(const float4*)(A + i4);
    __half2 a = __floats2half2_rn(v.x, v.y);
    __half2 b = __floats2half2_rn(v.z, v.w);
    *(uint2*)((unsigned short*)T + i4) =
        make_uint2(*(uint32_t*)&a, *(uint32_t*)&b);
}

// weight transpose -> fp16 plane, packed groups
__global__ void conv_w_k(const float* __restrict__ Ws, __half* __restrict__ TW)
{
    static const int BASE[10]   = {0, 1920000, 2560000, 0, 0, 2560000, 4480000, 5120000, 2560000, 5760000};
    static const int ROWOFF[10] = {0, 0, 0, 800, 1600, 800, 0, 0, 1600, 0};
    __shared__ float t[32][33];
    int wi = blockIdx.z;
    const float* W = Ws + (size_t)wi * (DD * DD);
    __half* hi = TW + BASE[wi] + (size_t)ROWOFF[wi] * DD;
    int tx = threadIdx.x, ty = threadIdx.y;
    int kb = blockIdx.y * 32, nb = blockIdx.x * 32;
#pragma unroll
    for (int r = 0; r < 4; r++)
        t[ty + r * 8][tx] = W[(size_t)(kb + ty + r * 8) * DD + nb + tx];
    __syncthreads();
#pragma unroll
    for (int r = 0; r < 4; r++) {
        int nrow = nb + ty + r * 8;
        int kcol = kb + tx;
        hi[(size_t)nrow * DD + kcol] = __float2half_rn(t[tx][ty + r * 8]);
    }
}

// fused cross-gate + cast: t1 = c*Dh1, t2 = c*Dh2 -> fp16
__global__ void crossconv_k(const float* __restrict__ P1, const float* __restrict__ P2,
                            __half* __restrict__ T1, __half* __restrict__ T2)
{
    int i4 = (blockIdx.x * blockDim.x + threadIdx.x) * 4;
    if (i4 >= NA_ * DD) return;
    int r = i4 / DD, c = i4 % DD;
    size_t po = (size_t)r * 2400 + 800 + c;
    float4 d1 = *(const float4*)(P1 + po);
    float4 d2 = *(const float4*)(P2 + po);
    float4 t1v, t2v;
    float f;
    f = 1.f / (fabsf(d1.x - d2.x) + 1.f); t1v.x = f * d1.x; t2v.x = f * d2.x;
    f = 1.f / (fabsf(d1.y - d2.y) + 1.f); t1v.y = f * d1.y; t2v.y = f * d2.y;
    f = 1.f / (fabsf(d1.z - d2.z) + 1.f); t1v.z = f * d1.z; t2v.z = f * d2.z;
    f = 1.f / (fabsf(d1.w - d2.w) + 1.f); t1v.w = f * d1.w; t2v.w = f * d2.w;
    __half2 a = __floats2half2_rn(t1v.x, t1v.y);
    __half2 b = __floats2half2_rn(t1v.z, t1v.w);
    *(uint2*)((unsigned short*)T1 + i4) = make_uint2(*(uint32_t*)&a, *(uint32_t*)&b);
    a = __floats2half2_rn(t2v.x, t2v.y);
    b = __floats2half2_rn(t2v.z, t2v.w);
    *(uint2*)((unsigned short*)T2 + i4) = make_uint2(*(uint32_t*)&a, *(uint32_t*)&b);
}

// ---------------------------------------------------------------------------
__global__ void zero_k(float* p, int n) {
    int i = blockIdx.x * blockDim.x + threadIdx.x;
    if (i < n) p[i] = 0.f;
}
__global__ void count_all_k(const int* __restrict__ ag1, const int* __restrict__ bg1,
                            const int* __restrict__ ag2, const int* __restrict__ bg2,
                            float* __restrict__ cnts)
{
    int y = blockIdx.y;
    int i = blockIdx.x * blockDim.x + threadIdx.x;
    const int* s = (y == 0) ? ag1 : (y == 1) ? bg1 : (y == 2) ? ag2 : bg2;
    int n = (y & 1) ? NB_ : NA_;
    if (i < n) atomicAdd(&cnts[y * 256 + s[i]], 1.0f);
}
__global__ void bnprep_k(const float* __restrict__ sum, const float* __restrict__ sumsq,
                         const float* __restrict__ gamma, const float* __restrict__ beta,
                         float Rf, float* __restrict__ scale, float* __restrict__ shift)
{
    int c = blockIdx.x * blockDim.x + threadIdx.x;
    if (c >= DD) return;
    float m = sum[c] / Rf;
    float v = sumsq[c] / Rf - m * m;
    float sc = gamma[c] * rsqrtf(v + 1e-5f);
    scale[c] = sc;
    shift[c] = beta[c] - m * sc;
}
__global__ void colstats_k(const float* __restrict__ X, int R,
                           float* __restrict__ sum, float* __restrict__ sumsq)
{
    int col = blockIdx.x * blockDim.x + threadIdx.x;
    if (col >= DD) return;
    int chunk = (R + gridDim.y - 1) / gridDim.y;
    int r0 = blockIdx.y * chunk;
    int r1 = min(r0 + chunk, R);
    float s = 0.f, q = 0.f;
    for (int r = r0; r < r1; r++) {
        float v = X[(size_t)r * DD + col];
        s += v; q += v * v;
    }
    atomicAdd(&sum[col], s);
    atomicAdd(&sumsq[col], q);
}
__global__ void bnrelu_k(float* __restrict__ X, int n,
                         const float* __restrict__ scale, const float* __restrict__ shift)
{
    int i = blockIdx.x * blockDim.x + threadIdx.x;
    if (i >= n) return;
    int col = i % DD;
    X[i] = fmaxf(fmaf(X[i], scale[col], shift[col]), 0.f);
}
// fused BN-apply + relu + segment-sum
__global__ void bnseg_k(float* __restrict__ X, int M, const int* __restrict__ seg,
                        const float* __restrict__ scale, const float* __restrict__ shift,
                        float* __restrict__ ssum)
{
    extern __shared__ float sm[];
    int c0 = blockIdx.x * 64;
    int cl = threadIdx.x & 63;
    int col = c0 + cl;
    int rg = threadIdx.x >> 6;
    for (int i = threadIdx.x; i < 16384; i += 256) sm[i] = 0.f;
    __syncthreads();
    bool ok = col < DD;
    float sc = ok ? scale[col] : 0.f;
    float sh = ok ? shift[col] : 0.f;
    int chunk = (M + gridDim.y - 1) / gridDim.y;
    int r0 = blockIdx.y * chunk;
    int r1 = min(r0 + chunk, M);
    for (int r = r0 + rg; r < r1; r += 4) {
        int g = seg[r];
        if (ok) {
            float y = fmaxf(fmaf(X[(size_t)r * DD + col], sc, sh), 0.f);
            X[(size_t)r * DD + col] = y;
            atomicAdd(&sm[g * 64 + cl], y);
        }
    }
    __syncthreads();
    for (int i = threadIdx.x; i < 16384; i += 256) {
        int g = i >> 6;
        int c = c0 + (i & 63);
        float v = sm[i];
        if (c < DD && v != 0.f) atomicAdd(&ssum[g * DD + c], v);
    }
}
__global__ void atom_k(float* __restrict__ h_out, const float* __restrict__ P,
                       const float* __restrict__ UFI, const float* __restrict__ e_new,
                       const int* __restrict__ atom_bonds, const int* __restrict__ bond_atoms,
                       const int* __restrict__ atom_graph)
{
    int a = blockIdx.x;
    __shared__ int sh_bond[4];
    __shared__ int sh_other[4];
    if (threadIdx.x < 4) {
        int b = atom_bonds[a * 4 + threadIdx.x];
        sh_bond[threadIdx.x] = b;
        int p0 = bond_atoms[b * 2];
        int p1 = bond_atoms[b * 2 + 1];
        sh_other[threadIdx.x] = (p0 != a) ? p0 : p1;
    }
    __syncthreads();
    int g = atom_graph[a];
    const float* e0 = e_new + (size_t)sh_bond[0] * DD;
    const float* e1 = e_new + (size_t)sh_bond[1] * DD;
    const float* e2p = e_new + (size_t)sh_bond[2] * DD;
    const float* e3 = e_new + (size_t)sh_bond[3] * DD;
    const float* E0 = P + (size_t)sh_other[0] * 2400 + 1600;
    const float* E1 = P + (size_t)sh_other[1] * 2400 + 1600;
    const float* E2 = P + (size_t)sh_other[2] * 2400 + 1600;
    const float* E3 = P + (size_t)sh_other[3] * 2400 + 1600;
    const float* dh = P + (size_t)a * 2400 + 800;
    const float* fu = UFI + (size_t)g * 2400 + 800;
    float* ho = h_out + (size_t)a * DD;
    for (int c = threadIdx.x; c < DD; c += blockDim.x) {
        float s0 = 1.f / (1.f + expf(-e0[c]));
        float s1 = 1.f / (1.f + expf(-e1[c]));
        float s2 = 1.f / (1.f + expf(-e2p[c]));
        float s3 = 1.f / (1.f + expf(-e3[c]));
        float num = s0 * E0[c] + s1 * E1[c] + s2 * E2[c] + s3 * E3[c];
        float den = s0 + s1 + s2 + s3 + 1e-6f;
        ho[c] = dh[c] + num / den + fu[c];
    }
}
__global__ void meanprep_k(const float* __restrict__ ssum, const float* __restrict__ cnts,
                           __half* __restrict__ mH, __half* __restrict__ mE)
{
    int i4 = (blockIdx.x * blockDim.x + threadIdx.x) * 4;
    if (i4 >= NG_ * DD) return;
    int g = i4 / DD;
    float cA1 = fmaxf(cnts[g], 1.f),       cA2 = fmaxf(cnts[512 + g], 1.f);
    float cB1 = fmaxf(cnts[256 + g], 1.f), cB2 = fmaxf(cnts[768 + g], 1.f);
    const float* sh1 = ssum + i4;
    const float* se1 = ssum + 204800 + i4;
    const float* sh2 = ssum + 409600 + i4;
    const float* se2 = ssum + 614400 + i4;
    float4 vh, ve;
    vh.x = sh1[0] / cA1 + sh2[0] / cA2;  ve.x = se1[0] / cB1 + se2[0] / cB2;
    vh.y = sh1[1] / cA1 + sh2[1] / cA2;  ve.y = se1[1] / cB1 + se2[1] / cB2;
    vh.z = sh1[2] / cA1 + sh2[2] / cA2;  ve.z = se1[2] / cB1 + se2[2] / cB2;
    vh.w = sh1[3] / cA1 + sh2[3] / cA2;  ve.w = se1[3] / cB1 + se2[3] / cB2;
    __half2 a = __floats2half2_rn(vh.x, vh.y);
    __half2 b = __floats2half2_rn(vh.z, vh.w);
    *(uint2*)((unsigned short*)mH + i4) = make_uint2(*(uint32_t*)&a, *(uint32_t*)&b);
    a = __floats2half2_rn(ve.x, ve.y);
    b = __floats2half2_rn(ve.z, ve.w);
    *(uint2*)((unsigned short*)mE + i4) = make_uint2(*(uint32_t*)&a, *(uint32_t*)&b);
}
__global__ void ucomb_k(float* __restrict__ un, const float* __restrict__ P6,
                        const float* __restrict__ P7, const float* __restrict__ UFI,
                        const float* __restrict__ cnts, const float* __restrict__ bs)
{
    int i = blockIdx.x * blockDim.x + threadIdx.x;
    if (i >= NG_ * DD) return;
    int g = i / DD, c = i % DD;
    float indA = (cnts[g] > 0.f ? 1.f : 0.f) + (cnts[512 + g] > 0.f ? 1.f : 0.f);
    float indB = (cnts[256 + g] > 0.f ? 1.f : 0.f) + (cnts[768 + g] > 0.f ? 1.f : 0.f);
    un[i] = P6[i] + P7[i] + UFI[(size_t)g * 2400 + 1600 + c]
          + bs[6 * 800 + c] * indA + bs[7 * 800 + c] * indB;
}

// ---------------------------------------------------------------------------
extern "C" void kernel_launch(void* const* d_in, const int* in_sizes, int n_in,
                              void* d_out, int out_size)
{
    const float* h   = (const float*)d_in[0];
    const float* e   = (const float*)d_in[1];
    const float* h2  = (const float*)d_in[2];
    const float* e2  = (const float*)d_in[3];
    const float* u   = (const float*)d_in[4];
    const float* Ws  = (const float*)d_in[5];
    const float* bs  = (const float*)d_in[6];
    const float* gam = (const float*)d_in[7];
    const float* bet = (const float*)d_in[8];
    const int* ba1 = (const int*)d_in[9];
    const int* ab1 = (const int*)d_in[10];
    const int* ag1 = (const int*)d_in[11];
    const int* bg1 = (const int*)d_in[12];
    const int* ba2 = (const int*)d_in[13];
    const int* ab2 = (const int*)d_in[14];
    const int* ag2 = (const int*)d_in[15];
    const int* bg2 = (const int*)d_in[16];

    float* out = (float*)d_out;
    float* h1n = out;
    float* e1n = out + 16000000;
    float* h2n = out + 35200000;
    float* e2n = out + 51200000;
    float* un  = out + 70400000;

    float* sp = nullptr;
    cudaGetSymbolAddress((void**)&sp, g_scratch);

    float* P1  = sp + O_P1;
    float* P2  = sp + O_P2;
    float* SM  = sp + O_SMALL;
    float* UFI = SM;
    float* ssum  = SM + 614400;
    float* cnts  = SM + 1433600;
    float* bnsum = SM + 1434624;
    float* bnsq  = SM + 1438624;
    float* zbias = SM + 1442624;
    float* bnsc  = SM + 1443424;
    float* bnsh  = SM + 1447424;
    __half* mH = (__half*)(SM + 1456224);
    __half* mE = (__half*)(SM + 1661024);
    float* P6 = SM + 1865824;
    float* P7 = SM + 2070624;

    __half* tw   = (__half*)(sp + O_TW);
    __half* thp  = (__half*)(sp + O_THp);
    __half* th2p = (__half*)(sp + O_TH2p);
    __half* tep  = (__half*)(sp + O_TEp);
    __half* te2p = (__half*)(sp + O_TE2p);
    __half* tup  = (__half*)(sp + O_TUp);

    __half* TADE = tw + 0;
    __half* TB1  = tw + 1920000;
    __half* TUFI = tw + 2560000;
    __half* TG   = tw + 4480000;
    __half* TH7  = tw + 5120000;
    __half* TW9  = tw + 5760000;

    const int NH = NA_ * DD, NE = NB_ * DD, NU = NG_ * DD;

    cudaFuncSetAttribute(hgemm_k<0>, cudaFuncAttributeMaxDynamicSharedMemorySize, SMEM_TOT);
    cudaFuncSetAttribute(hgemm_k<1>, cudaFuncAttributeMaxDynamicSharedMemorySize, SMEM_TOT);
    cudaFuncSetAttribute(hgemm_k<3>, cudaFuncAttributeMaxDynamicSharedMemorySize, SMEM_TOT);
    cudaFuncSetAttribute(bnseg_k, cudaFuncAttributeMaxDynamicSharedMemorySize, 65536);

    // 1-5: conversions; launch 6 = ADE GEMM (ncu -s 5 profiles it)
    conv_a_k<<<NH / 1024, 256>>>(h,  NH, thp);
    conv_a_k<<<NH / 1024, 256>>>(h2, NH, th2p);
    conv_a_k<<<NE / 1024, 256>>>(e,  NE, tep);
    conv_a_k<<<NE / 1024, 256>>>(e2, NE, te2p);
    conv_w_k<<<dim3(25, 25, 10), dim3(32, 8)>>>(Ws, tw);

    // 6: ADE projections (both halves)
    hgemm_k<0><<<dim3(15, 157, 2), 256, SMEM_TOT>>>(
        thp, th2p, TADE, TADE, bs, bs, 0, 3, 4,
        P1, P2, NA_, 2400,
        nullptr, nullptr, nullptr, nullptr, nullptr, nullptr, nullptr, nullptr, nullptr);

    // setup
    zero_k<<<(829024 + 255) / 256, 256>>>(ssum, 829024);
    count_all_k<<<dim3(94, 4), 256>>>(ag1, bg1, ag2, bg2, cnts);
    conv_a_k<<<NU / 1024, 256>>>(u, NU, tup);
    hgemm_k<0><<<dim3(15, 2, 1), 256, SMEM_TOT>>>(
        tup, tup, TUFI, TUFI, bs, bs, 2, 5, 8,
        UFI, UFI, NG_, 2400,
        nullptr, nullptr, nullptr, nullptr, nullptr, nullptr, nullptr, nullptr, nullptr);

    // e-projection + fused bond update + BN stats
    hgemm_k<3><<<dim3(5, 188, 2), 256, SMEM_TOT>>>(
        tep, te2p, TB1, TB1, bs, bs, 1, 1, 1,
        e1n, e2n, NB_, 800,
        ba1, ba2, bg1, bg2, P1, P2, UFI,
        bnsum + 0, bnsum + 800);

    // BN(e) prep + apply + segsum
    bnprep_k<<<4, 256>>>(bnsum + 0, bnsq + 0, gam, bet, (float)NB_, bnsc + 0, bnsh + 0);
    bnprep_k<<<4, 256>>>(bnsum + 800, bnsq + 800, gam, bet, (float)NB_, bnsc + 800, bnsh + 800);
    bnseg_k<<<dim3(13, 12), 256, 65536>>>(e1n, NB_, bg1, bnsc + 0, bnsh + 0, ssum + 204800);
    bnseg_k<<<dim3(13, 12), 256, 65536>>>(e2n, NB_, bg2, bnsc + 800, bnsh + 800, ssum + 614400);

    // atom update (pre-mix h)
    atom_k<<<NA_, 256>>>(h1n, P1, UFI, e1n, ab1, ba1, ag1);
    atom_k<<<NA_, 256>>>(h2n, P2, UFI, e2n, ab2, ba2, ag2);

    // cross + mix (fused BN stats)
    crossconv_k<<<NH / 1024, 256>>>(P1, P2, thp, th2p);
    hgemm_k<1><<<dim3(5, 157, 2), 256, SMEM_TOT>>>(
        th2p, thp, TW9, TW9, bs, bs, 9, 9, 9,
        h1n, h2n, NA_, 800,
        nullptr, nullptr, nullptr, nullptr, nullptr, nullptr, nullptr,
        bnsum + 1600, bnsum + 2400);

    // BN(h) prep + apply + segsum
    bnprep_k<<<4, 256>>>(bnsum + 1600, bnsq + 1600, gam + 800, bet + 800, (float)NA_, bnsc + 1600, bnsh + 1600);
    bnprep_k<<<4, 256>>>(bnsum + 2400, bnsq + 2400, gam + 800, bet + 800, (float)NA_, bnsc + 2400, bnsh + 2400);
    bnseg_k<<<dim3(13, 12), 256, 65536>>>(h1n, NA_, ag1, bnsc + 1600, bnsh + 1600, ssum + 0);
    bnseg_k<<<dim3(13, 12), 256, 65536>>>(h2n, NA_, ag2, bnsc + 2400, bnsh + 2400, ssum + 409600);

    // global readout on means
    meanprep_k<<<NU / 1024, 256>>>(ssum, cnts, mH, mE);
    hgemm_k<0><<<dim3(5, 2, 2), 256, SMEM_TOT>>>(
        mH, mE, TG, TH7, zbias, zbias, 0, 0, 0,
        P6, P7, NG_, 800,
        nullptr, nullptr, nullptr, nullptr, nullptr, nullptr, nullptr, nullptr, nullptr);

    // combine + BN(u) + relu
    ucomb_k<<<(NU + 255) / 256, 256>>>(un, P6, P7, UFI, cnts, bs);
    {
        dim3 gs((DD + 255) / 256, 8);
        colstats_k<<<gs, 256>>>(un, NG_, bnsum + 3200, bnsq + 3200);
        bnprep_k<<<4, 256>>>(bnsum + 3200, bnsq + 3200, gam + 1600, bet + 1600, (float)NG_, bnsc + 3200, bnsh + 3200);
        bnrelu_k<<<(NU + 255) / 256, 256>>>(un, NU, bnsc + 3200, bnsh + 3200);
    }
}

// round 8
// speedup vs baseline: 5.3024x; 1.0086x over previous
#include <cuda_runtime.h>
#include <cuda_fp16.h>
#include <cstdint>
#include <math.h>

#define DD 800
#define NA_ 20000
#define NB_ 24000
#define NG_ 256

// ---- HMMA GEMM tiling (pure fp16 single pass) ----
#define BM 128
#define BN 160
#define BK 32
#define SA_ 0
#define SB_ 10240
#define STAGE_B 23040
#define SMEM_TOT (3 * STAGE_B)   // 69120

// ---------------------------------------------------------------------------
// Scratch layout (float offsets)
// ---------------------------------------------------------------------------
static constexpr size_t O_P1 = 0;             // [20000][2400] fp16 A|D|E half1
static constexpr size_t O_P2 = 48000000;      // fp16 half2
static constexpr size_t O_SMALL = 96000000;
static constexpr size_t O_TW   = 98400000;
static constexpr size_t O_THp  = 104800000;
static constexpr size_t O_TH2p = 120800000;
static constexpr size_t O_TEp  = 136800000;
static constexpr size_t O_TE2p = 156000000;
static constexpr size_t O_TUp  = 175200000;
__device__ __align__(1024) float g_scratch[176000000];

// ---------------------------------------------------------------------------
__device__ __forceinline__ uint32_t smem_u32(const void* p) {
    uint32_t a;
    asm("{ .reg .u64 t; cvta.to.shared.u64 t, %1; cvt.u32.u64 %0, t; }" : "=r"(a) : "l"(p));
    return a;
}
__device__ __forceinline__ void cp16(uint32_t saddr, const void* gaddr) {
    asm volatile("cp.async.cg.shared.global [%0], [%1], 16;" :: "r"(saddr), "l"(gaddr));
}
__device__ __forceinline__ void cp_commit() {
    asm volatile("cp.async.commit_group;" ::: "memory");
}
__device__ __forceinline__ void cp_wait1() {
    asm volatile("cp.async.wait_group 1;" ::: "memory");
}
__device__ __forceinline__ void cp_wait0() {
    asm volatile("cp.async.wait_group 0;" ::: "memory");
}
__device__ __forceinline__ void ldsm4(uint32_t* r, uint32_t addr) {
    asm volatile("ldmatrix.sync.aligned.m8n8.x4.shared.b16 {%0,%1,%2,%3}, [%4];"
                 : "=r"(r[0]), "=r"(r[1]), "=r"(r[2]), "=r"(r[3]) : "r"(addr));
}
__device__ __forceinline__ void mma16816(float* c, const uint32_t* a, const uint32_t* b) {
    asm volatile(
        "mma.sync.aligned.m16n8k16.row.col.f32.f16.f16.f32 "
        "{%0,%1,%2,%3}, {%4,%5,%6,%7}, {%8,%9}, {%0,%1,%2,%3};"
        : "+f"(c[0]), "+f"(c[1]), "+f"(c[2]), "+f"(c[3])
        : "r"(a[0]), "r"(a[1]), "r"(a[2]), "r"(a[3]), "r"(b[0]), "r"(b[1]));
}

// ---------------------------------------------------------------------------
// fp16 HMMA GEMM, z-batched pair.
// MODE 0: store fp32 acc+bias
// MODE 1: C = 0.8*C + 0.2*(acc+bias), accumulate BN stats
// MODE 3: C = acc+bias + Ah[i0]+Ah[i1]+Cu[g] (bond fuse; A gathers fp16), BN stats
// MODE 4: store fp16 acc+bias
// ---------------------------------------------------------------------------
template<int MODE>
__global__ __launch_bounds__(256, 2)
void hgemm_k(const __half* __restrict__ Ah0, const __half* __restrict__ Ah1,
             const __half* __restrict__ B0_, const __half* __restrict__ B1_,
             const float* __restrict__ bias0, const float* __restrict__ bias1,
             int bm0, int bm1, int bm2,
             void* __restrict__ C0, void* __restrict__ C1, int M, int ldc,
             const int* __restrict__ ba0, const int* __restrict__ ba1p,
             const int* __restrict__ bg0, const int* __restrict__ bg1p,
             const __half* __restrict__ P0g, const __half* __restrict__ P1g,
             const float* __restrict__ CuB,
             float* __restrict__ st0, float* __restrict__ st1)
{
    extern __shared__ char smem[];
    uint32_t sb = smem_u32(smem);
    int tid = threadIdx.x;
    int lid = tid & 31, wid = tid >> 5;
    int wm = wid & 3, wn = wid >> 2;
    int ntile = blockIdx.x, mtile = blockIdx.y, z = blockIdx.z;

    const __half* Ahp = z ? Ah1 : Ah0;
    const __half* Bp  = z ? B1_ : B0_;
    const float* bias = z ? bias1 : bias0;

    int arow[2], acol[2];
    uint32_t asoff[2];
#pragma unroll
    for (int t = 0; t < 2; t++) {
        int q = tid + t * 256;
        int r = q >> 2, c = q & 3;
        arow[t] = min(mtile * BM + r, M - 1);
        acol[t] = c * 8;
        asoff[t] = r * 80 + c * 16;
    }
    int brow[3], bcol[3];
    uint32_t bsoff[3];
#pragma unroll
    for (int t = 0; t < 3; t++) {
        int q = tid + t * 256;
        int r = q >> 2, c = q & 3;
        brow[t] = ntile * BN + r;
        bcol[t] = c * 8;
        bsoff[t] = r * 80 + c * 16;
    }
    bool b3 = (tid < 128);

    auto load_stage = [&](int s, int kc) {
        uint32_t st = sb + s * STAGE_B;
        int k0 = kc * BK;
#pragma unroll
        for (int t = 0; t < 2; t++)
            cp16(st + SA_ + asoff[t], Ahp + (size_t)arow[t] * DD + k0 + acol[t]);
#pragma unroll
        for (int t = 0; t < 2; t++)
            cp16(st + SB_ + bsoff[t], Bp + (size_t)brow[t] * DD + k0 + bcol[t]);
        if (b3)
            cp16(st + SB_ + bsoff[2], Bp + (size_t)brow[2] * DD + k0 + bcol[2]);
    };

    float acc[2][10][4];
#pragma unroll
    for (int i = 0; i < 2; i++)
#pragma unroll
        for (int j = 0; j < 10; j++)
#pragma unroll
            for (int k = 0; k < 4; k++) acc[i][j][k] = 0.f;

    uint32_t aswz = (lid & 15) * 80 + (lid >> 4) * 16;
    uint32_t bswz = ((lid & 7) + ((lid & 16) ? 8 : 0)) * 80 + ((lid >> 3) & 1) * 16;
    uint32_t a_base = (wm * 32) * 80 + aswz;
    uint32_t b_base = (wn * 80) * 80 + bswz;

    load_stage(0, 0); cp_commit();
    load_stage(1, 1); cp_commit();

#pragma unroll 1
    for (int kc = 0; kc < 25; kc++) {
        int s = kc % 3;
        cp_wait1();
        __syncthreads();
        uint32_t st = sb + s * STAGE_B;
#pragma unroll
        for (int k16 = 0; k16 < 2; k16++) {
            uint32_t aH[2][4];
            ldsm4(aH[0], st + SA_ + a_base + k16 * 32);
            ldsm4(aH[1], st + SA_ + a_base + 16 * 80 + k16 * 32);
#pragma unroll
            for (int g = 0; g < 5; g++) {
                uint32_t bH[4];
                ldsm4(bH, st + SB_ + b_base + g * 16 * 80 + k16 * 32);
                mma16816(acc[0][2 * g],     aH[0], bH);
                mma16816(acc[0][2 * g + 1], aH[0], bH + 2);
                mma16816(acc[1][2 * g],     aH[1], bH);
                mma16816(acc[1][2 * g + 1], aH[1], bH + 2);
            }
        }
        if (kc + 2 < 25) load_stage((kc + 2) % 3, kc + 2);
        cp_commit();
    }

    // ---------------- epilogue ----------------
    cp_wait0();
    __syncthreads();
    float* smst = (float*)smem;
    if (MODE == 1 || MODE == 3) {
        for (int i = tid; i < 320; i += 256) smst[i] = 0.f;
        __syncthreads();
    }

    int bseg = ntile / 5;
    const float* bp = bias + (bseg == 0 ? bm0 : bseg == 1 ? bm1 : bm2) * 800 - bseg * 800;

    float* Cf  = (float*)(z ? C1 : C0);
    __half* Ch = (__half*)(z ? C1 : C0);
    float* st = z ? st1 : st0;
    const int* BA = z ? ba1p : ba0;
    const int* BG = z ? bg1p : bg0;
    const __half* Pg = z ? P1g : P0g;

    int rows[4];
    bool rok[4];
    const __half *pA0[4], *pA1[4];
    const float *pCu[4];
#pragma unroll
    for (int q = 0; q < 4; q++) {
        int i = q >> 1, half = q & 1;
        int r = mtile * BM + wm * 32 + i * 16 + half * 8 + (lid >> 2);
        rows[q] = r;
        rok[q] = r < M;
        if (MODE == 3 && rok[q]) {
            int2 bb = ((const int2*)BA)[r];
            int gg = BG[r];
            pA0[q] = Pg + (size_t)bb.x * 2400;
            pA1[q] = Pg + (size_t)bb.y * 2400;
            pCu[q] = CuB + (size_t)gg * 2400;
        }
    }

#pragma unroll
    for (int j = 0; j < 10; j++) {
        int colloc = wn * 80 + j * 8 + (lid & 3) * 2;
        int col = ntile * 160 + colloc;
        float2 bv = *(const float2*)(bp + col);
        float s0 = 0.f, s1 = 0.f, q0 = 0.f, q1 = 0.f;
#pragma unroll
        for (int q = 0; q < 4; q++) {
            if (!rok[q]) continue;
            int i = q >> 1, half = q & 1;
            float v0 = acc[i][j][half * 2 + 0] + bv.x;
            float v1 = acc[i][j][half * 2 + 1] + bv.y;
            if (MODE == 3) {
                float2 a0v = __half22float2(*(const __half2*)(pA0[q] + col));
                float2 a1v = __half22float2(*(const __half2*)(pA1[q] + col));
                float2 cuv = *(const float2*)(pCu[q] + col);
                v0 += a0v.x + a1v.x + cuv.x;
                v1 += a0v.y + a1v.y + cuv.y;
            }
            if (MODE == 4) {
                *(__half2*)(Ch + (size_t)rows[q] * ldc + col) = __floats2half2_rn(v0, v1);
            } else {
                size_t co = (size_t)rows[q] * ldc + col;
                if (MODE == 1) {
                    float2 o = *(float2*)&Cf[co];
                    v0 = o.x * 0.8f + 0.2f * v0;
                    v1 = o.y * 0.8f + 0.2f * v1;
                }
                *(float2*)&Cf[co] = make_float2(v0, v1);
            }
            if (MODE == 1 || MODE == 3) {
                s0 += v0; q0 += v0 * v0;
                s1 += v1; q1 += v1 * v1;
            }
        }
        if (MODE == 1 || MODE == 3) {
#pragma unroll
            for (int d = 4; d < 32; d <<= 1) {
                s0 += __shfl_xor_sync(0xFFFFFFFFu, s0, d);
                s1 += __shfl_xor_sync(0xFFFFFFFFu, s1, d);
                q0 += __shfl_xor_sync(0xFFFFFFFFu, q0, d);
                q1 += __shfl_xor_sync(0xFFFFFFFFu, q1, d);
            }
            if (lid < 4) {
                atomicAdd(&smst[colloc], s0);
                atomicAdd(&smst[colloc + 1], s1);
                atomicAdd(&smst[160 + colloc], q0);
                atomicAdd(&smst[160 + colloc + 1], q1);
            }
        }
    }
    if (MODE == 1 || MODE == 3) {
        __syncthreads();
        for (int i = tid; i < 160; i += 256) {
            atomicAdd(&st[ntile * 160 + i], smst[i]);
            atomicAdd(&st[4000 + ntile * 160 + i], smst[160 + i]);
        }
    }
}

// ---------------------------------------------------------------------------
// conversions
// ---------------------------------------------------------------------------
__global__ void conv_all_k(const float* __restrict__ h, const float* __restrict__ h2,
                           const float* __restrict__ e, const float* __restrict__ e2,
                           __half* __restrict__ th, __half* __restrict__ th2,
                           __half* __restrict__ te, __half* __restrict__ te2)
{
    int z = blockIdx.y;
    const float* A = (z == 0) ? h : (z == 1) ? h2 : (z == 2) ? e : e2;
    __half* T = (z == 0) ? th : (z == 1) ? th2 : (z == 2) ? te : te2;
    int n = (z < 2) ? NA_ * DD : NB_ * DD;
    int i4 = (blockIdx.x * blockDim.x + threadIdx.x) * 4;
    if (i4 >= n) return;
    float4 v = *(const float4*)(A + i4);
    __half2 a = __floats2half2_rn(v.x, v.y);
    __half2 b = __floats2half2_rn(v.z, v.w);
    *(uint2*)((unsigned short*)T + i4) = make_uint2(*(uint32_t*)&a, *(uint32_t*)&b);
}
__global__ void conv_a_k(const float* __restrict__ A, int n, __half* __restrict__ T)
{
    int i4 = (blockIdx.x * blockDim.x + threadIdx.x) * 4;
    if (i4 >= n) return;
    float4 v = *(const float4*)(A + i4);
    __half2 a = __floats2half2_rn(v.x, v.y);
    __half2 b = __floats2half2_rn(v.z, v.w);
    *(uint2*)((unsigned short*)T + i4) = make_uint2(*(uint32_t*)&a, *(uint32_t*)&b);
}

// weight transpose -> fp16 plane, packed groups
__global__ void conv_w_k(const float* __restrict__ Ws, __half* __restrict__ TW)
{
    static const int BASE[10]   = {0, 1920000, 2560000, 0, 0, 2560000, 4480000, 5120000, 2560000, 5760000};
    static const int ROWOFF[10] = {0, 0, 0, 800, 1600, 800, 0, 0, 1600, 0};
    __shared__ float t[32][33];
    int wi = blockIdx.z;
    const float* W = Ws + (size_t)wi * (DD * DD);
    __half* hi = TW + BASE[wi] + (size_t)ROWOFF[wi] * DD;
    int tx = threadIdx.x, ty = threadIdx.y;
    int kb = blockIdx.y * 32, nb = blockIdx.x * 32;
#pragma unroll
    for (int r = 0; r < 4; r++)
        t[ty + r * 8][tx] = W[(size_t)(kb + ty + r * 8) * DD + nb + tx];
    __syncthreads();
#pragma unroll
    for (int r = 0; r < 4; r++) {
        int nrow = nb + ty + r * 8;
        int kcol = kb + tx;
        hi[(size_t)nrow * DD + kcol] = __float2half_rn(t[tx][ty + r * 8]);
    }
}

// fused cross-gate + cast from fp16 P planes
__global__ void crossconv_k(const __half* __restrict__ P1, const __half* __restrict__ P2,
                            __half* __restrict__ T1, __half* __restrict__ T2)
{
    int i4 = (blockIdx.x * blockDim.x + threadIdx.x) * 4;
    if (i4 >= NA_ * DD) return;
    int r = i4 / DD, c = i4 % DD;
    size_t po = (size_t)r * 2400 + 800 + c;
    float2 d1a = __half22float2(*(const __half2*)(P1 + po));
    float2 d1b = __half22float2(*(const __half2*)(P1 + po + 2));
    float2 d2a = __half22float2(*(const __half2*)(P2 + po));
    float2 d2b = __half22float2(*(const __half2*)(P2 + po + 2));
    float4 t1v, t2v;
    float f;
    f = 1.f / (fabsf(d1a.x - d2a.x) + 1.f); t1v.x = f * d1a.x; t2v.x = f * d2a.x;
    f = 1.f / (fabsf(d1a.y - d2a.y) + 1.f); t1v.y = f * d1a.y; t2v.y = f * d2a.y;
    f = 1.f / (fabsf(d1b.x - d2b.x) + 1.f); t1v.z = f * d1b.x; t2v.z = f * d2b.x;
    f = 1.f / (fabsf(d1b.y - d2b.y) + 1.f); t1v.w = f * d1b.y; t2v.w = f * d2b.y;
    __half2 a = __floats2half2_rn(t1v.x, t1v.y);
    __half2 b = __floats2half2_rn(t1v.z, t1v.w);
    *(uint2*)((unsigned short*)T1 + i4) = make_uint2(*(uint32_t*)&a, *(uint32_t*)&b);
    a = __floats2half2_rn(t2v.x, t2v.y);
    b = __floats2half2_rn(t2v.z, t2v.w);
    *(uint2*)((unsigned short*)T2 + i4) = make_uint2(*(uint32_t*)&a, *(uint32_t*)&b);
}

// ---------------------------------------------------------------------------
__global__ void zero_k(float* p, int n) {
    int i = blockIdx.x * blockDim.x + threadIdx.x;
    if (i < n) p[i] = 0.f;
}
__global__ void count_all_k(const int* __restrict__ ag1, const int* __restrict__ bg1,
                            const int* __restrict__ ag2, const int* __restrict__ bg2,
                            float* __restrict__ cnts)
{
    int y = blockIdx.y;
    int i = blockIdx.x * blockDim.x + threadIdx.x;
    const int* s = (y == 0) ? ag1 : (y == 1) ? bg1 : (y == 2) ? ag2 : bg2;
    int n = (y & 1) ? NB_ : NA_;
    if (i < n) atomicAdd(&cnts[y * 256 + s[i]], 1.0f);
}
__global__ void bnprep_k(const float* __restrict__ sum, const float* __restrict__ sumsq,
                         const float* __restrict__ gamma, const float* __restrict__ beta,
                         float Rf, float* __restrict__ scale, float* __restrict__ shift)
{
    int c = blockIdx.x * blockDim.x + threadIdx.x;
    if (c >= DD) return;
    float m = sum[c] / Rf;
    float v = sumsq[c] / Rf - m * m;
    float sc = gamma[c] * rsqrtf(v + 1e-5f);
    scale[c] = sc;
    shift[c] = beta[c] - m * sc;
}
__global__ void bnrelu_k(float* __restrict__ X, int n,
                         const float* __restrict__ scale, const float* __restrict__ shift)
{
    int i = blockIdx.x * blockDim.x + threadIdx.x;
    if (i >= n) return;
    int col = i % DD;
    X[i] = fmaxf(fmaf(X[i], scale[col], shift[col]), 0.f);
}
// fused BN-apply + relu + segment-sum
__global__ void bnseg_k(float* __restrict__ X, int M, const int* __restrict__ seg,
                        const float* __restrict__ scale, const float* __restrict__ shift,
                        float* __restrict__ ssum)
{
    extern __shared__ float sm[];
    int c0 = blockIdx.x * 64;
    int cl = threadIdx.x & 63;
    int col = c0 + cl;
    int rg = threadIdx.x >> 6;
    for (int i = threadIdx.x; i < 16384; i += 256) sm[i] = 0.f;
    __syncthreads();
    bool ok = col < DD;
    float sc = ok ? scale[col] : 0.f;
    float sh = ok ? shift[col] : 0.f;
    int chunk = (M + gridDim.y - 1) / gridDim.y;
    int r0 = blockIdx.y * chunk;
    int r1 = min(r0 + chunk, M);
    for (int r = r0 + rg; r < r1; r += 4) {
        int g = seg[r];
        if (ok) {
            float y = fmaxf(fmaf(X[(size_t)r * DD + col], sc, sh), 0.f);
            X[(size_t)r * DD + col] = y;
            atomicAdd(&sm[g * 64 + cl], y);
        }
    }
    __syncthreads();
    for (int i = threadIdx.x; i < 16384; i += 256) {
        int g = i >> 6;
        int c = c0 + (i & 63);
        float v = sm[i];
        if (c < DD && v != 0.f) atomicAdd(&ssum[g * DD + c], v);
    }
}
__global__ void atom_k(float* __restrict__ h_out, const __half* __restrict__ P,
                       const float* __restrict__ UFI, const float* __restrict__ e_new,
                       const int* __restrict__ atom_bonds, const int* __restrict__ bond_atoms,
                       const int* __restrict__ atom_graph)
{
    int a = blockIdx.x;
    __shared__ int sh_bond[4];
    __shared__ int sh_other[4];
    if (threadIdx.x < 4) {
        int b = atom_bonds[a * 4 + threadIdx.x];
        sh_bond[threadIdx.x] = b;
        int p0 = bond_atoms[b * 2];
        int p1 = bond_atoms[b * 2 + 1];
        sh_other[threadIdx.x] = (p0 != a) ? p0 : p1;
    }
    __syncthreads();
    int g = atom_graph[a];
    const float* e0 = e_new + (size_t)sh_bond[0] * DD;
    const float* e1 = e_new + (size_t)sh_bond[1] * DD;
    const float* e2p = e_new + (size_t)sh_bond[2] * DD;
    const float* e3 = e_new + (size_t)sh_bond[3] * DD;
    const __half* E0 = P + (size_t)sh_other[0] * 2400 + 1600;
    const __half* E1 = P + (size_t)sh_other[1] * 2400 + 1600;
    const __half* E2 = P + (size_t)sh_other[2] * 2400 + 1600;
    const __half* E3 = P + (size_t)sh_other[3] * 2400 + 1600;
    const __half* dh = P + (size_t)a * 2400 + 800;
    const float* fu = UFI + (size_t)g * 2400 + 800;
    float* ho = h_out + (size_t)a * DD;
    for (int c = threadIdx.x; c < DD; c += blockDim.x) {
        float s0 = 1.f / (1.f + expf(-e0[c]));
        float s1 = 1.f / (1.f + expf(-e1[c]));
        float s2 = 1.f / (1.f + expf(-e2p[c]));
        float s3 = 1.f / (1.f + expf(-e3[c]));
        float num = s0 * __half2float(E0[c]) + s1 * __half2float(E1[c])
                  + s2 * __half2float(E2[c]) + s3 * __half2float(E3[c]);
        float den = s0 + s1 + s2 + s3 + 1e-6f;
        ho[c] = __half2float(dh[c]) + num / den + fu[c];
    }
}
__global__ void meanprep_k(const float* __restrict__ ssum, const float* __restrict__ cnts,
                           __half* __restrict__ mH, __half* __restrict__ mE)
{
    int i4 = (blockIdx.x * blockDim.x + threadIdx.x) * 4;
    if (i4 >= NG_ * DD) return;
    int g = i4 / DD;
    float cA1 = fmaxf(cnts[g], 1.f),       cA2 = fmaxf(cnts[512 + g], 1.f);
    float cB1 = fmaxf(cnts[256 + g], 1.f), cB2 = fmaxf(cnts[768 + g], 1.f);
    const float* sh1 = ssum + i4;
    const float* se1 = ssum + 204800 + i4;
    const float* sh2 = ssum + 409600 + i4;
    const float* se2 = ssum + 614400 + i4;
    float4 vh, ve;
    vh.x = sh1[0] / cA1 + sh2[0] / cA2;  ve.x = se1[0] / cB1 + se2[0] / cB2;
    vh.y = sh1[1] / cA1 + sh2[1] / cA2;  ve.y = se1[1] / cB1 + se2[1] / cB2;
    vh.z = sh1[2] / cA1 + sh2[2] / cA2;  ve.z = se1[2] / cB1 + se2[2] / cB2;
    vh.w = sh1[3] / cA1 + sh2[3] / cA2;  ve.w = se1[3] / cB1 + se2[3] / cB2;
    __half2 a = __floats2half2_rn(vh.x, vh.y);
    __half2 b = __floats2half2_rn(vh.z, vh.w);
    *(uint2*)((unsigned short*)mH + i4) = make_uint2(*(uint32_t*)&a, *(uint32_t*)&b);
    a = __floats2half2_rn(ve.x, ve.y);
    b = __floats2half2_rn(ve.z, ve.w);
    *(uint2*)((unsigned short*)mE + i4) = make_uint2(*(uint32_t*)&a, *(uint32_t*)&b);
}
// fused: un = P6+P7+Iu+ind-bias, plus direct column stats (single wave, no atomics)
__global__ void ucombstats_k(float* __restrict__ un, const float* __restrict__ P6,
                             const float* __restrict__ P7, const float* __restrict__ UFI,
                             const float* __restrict__ cnts, const float* __restrict__ bs,
                             float* __restrict__ sum, float* __restrict__ sumsq)
{
    __shared__ float ssm[8][32], sqm[8][32];
    int cl = threadIdx.x & 31, rg = threadIdx.x >> 5;
    int col = blockIdx.x * 32 + cl;
    bool ok = col < DD;
    float s = 0.f, q = 0.f;
    if (ok) {
        float b6 = bs[6 * 800 + col], b7 = bs[7 * 800 + col];
        for (int g = rg; g < NG_; g += 8) {
            float indA = (cnts[g] > 0.f ? 1.f : 0.f) + (cnts[512 + g] > 0.f ? 1.f : 0.f);
            float indB = (cnts[256 + g] > 0.f ? 1.f : 0.f) + (cnts[768 + g] > 0.f ? 1.f : 0.f);
            float v = P6[(size_t)g * DD + col] + P7[(size_t)g * DD + col]
                    + UFI[(size_t)g * 2400 + 1600 + col] + b6 * indA + b7 * indB;
            un[(size_t)g * DD + col] = v;
            s += v; q += v * v;
        }
    }
    ssm[rg][cl] = s; sqm[rg][cl] = q;
    __syncthreads();
    if (rg == 0 && ok) {
        float S = 0.f, Q = 0.f;
#pragma unroll
        for (int r = 0; r < 8; r++) { S += ssm[r][cl]; Q += sqm[r][cl]; }
        sum[col] = S; sumsq[col] = Q;
    }
}

// ---------------------------------------------------------------------------
extern "C" void kernel_launch(void* const* d_in, const int* in_sizes, int n_in,
                              void* d_out, int out_size)
{
    const float* h   = (const float*)d_in[0];
    const float* e   = (const float*)d_in[1];
    const float* h2  = (const float*)d_in[2];
    const float* e2  = (const float*)d_in[3];
    const float* u   = (const float*)d_in[4];
    const float* Ws  = (const float*)d_in[5];
    const float* bs  = (const float*)d_in[6];
    const float* gam = (const float*)d_in[7];
    const float* bet = (const float*)d_in[8];
    const int* ba1 = (const int*)d_in[9];
    const int* ab1 = (const int*)d_in[10];
    const int* ag1 = (const int*)d_in[11];
    const int* bg1 = (const int*)d_in[12];
    const int* ba2 = (const int*)d_in[13];
    const int* ab2 = (const int*)d_in[14];
    const int* ag2 = (const int*)d_in[15];
    const int* bg2 = (const int*)d_in[16];

    float* out = (float*)d_out;
    float* h1n = out;
    float* e1n = out + 16000000;
    float* h2n = out + 35200000;
    float* e2n = out + 51200000;
    float* un  = out + 70400000;

    float* sp = nullptr;
    cudaGetSymbolAddress((void**)&sp, g_scratch);

    __half* P1 = (__half*)(sp + O_P1);
    __half* P2 = (__half*)(sp + O_P2);
    float* SM  = sp + O_SMALL;
    float* UFI = SM;
    float* ssum  = SM + 614400;
    float* cnts  = SM + 1433600;
    float* bnsum = SM + 1434624;
    float* bnsq  = SM + 1438624;
    float* zbias = SM + 1442624;
    float* bnsc  = SM + 1443424;
    float* bnsh  = SM + 1447424;
    __half* mH = (__half*)(SM + 1456224);
    __half* mE = (__half*)(SM + 1661024);
    float* P6 = SM + 1865824;
    float* P7 = SM + 2070624;

    __half* tw   = (__half*)(sp + O_TW);
    __half* thp  = (__half*)(sp + O_THp);
    __half* th2p = (__half*)(sp + O_TH2p);
    __half* tep  = (__half*)(sp + O_TEp);
    __half* te2p = (__half*)(sp + O_TE2p);
    __half* tup  = (__half*)(sp + O_TUp);

    __half* TADE = tw + 0;
    __half* TB1  = tw + 1920000;
    __half* TUFI = tw + 2560000;
    __half* TG   = tw + 4480000;
    __half* TH7  = tw + 5120000;
    __half* TW9  = tw + 5760000;

    const int NH = NA_ * DD, NE = NB_ * DD, NU = NG_ * DD;

    cudaFuncSetAttribute(hgemm_k<0>, cudaFuncAttributeMaxDynamicSharedMemorySize, SMEM_TOT);
    cudaFuncSetAttribute(hgemm_k<1>, cudaFuncAttributeMaxDynamicSharedMemorySize, SMEM_TOT);
    cudaFuncSetAttribute(hgemm_k<3>, cudaFuncAttributeMaxDynamicSharedMemorySize, SMEM_TOT);
    cudaFuncSetAttribute(hgemm_k<4>, cudaFuncAttributeMaxDynamicSharedMemorySize, SMEM_TOT);
    cudaFuncSetAttribute(bnseg_k, cudaFuncAttributeMaxDynamicSharedMemorySize, 65536);

    // launches 1-5 (so #6 = ADE GEMM for ncu -s 5)
    conv_all_k<<<dim3(18750, 4), 256>>>(h, h2, e, e2, thp, th2p, tep, te2p);
    conv_w_k<<<dim3(25, 25, 10), dim3(32, 8)>>>(Ws, tw);
    zero_k<<<(829024 + 255) / 256, 256>>>(ssum, 829024);
    count_all_k<<<dim3(94, 4), 256>>>(ag1, bg1, ag2, bg2, cnts);
    conv_a_k<<<NU / 1024, 256>>>(u, NU, tup);

    // 6: ADE projections -> fp16 P
    hgemm_k<4><<<dim3(15, 157, 2), 256, SMEM_TOT>>>(
        thp, th2p, TADE, TADE, bs, bs, 0, 3, 4,
        P1, P2, NA_, 2400,
        nullptr, nullptr, nullptr, nullptr, nullptr, nullptr, nullptr, nullptr, nullptr);

    // UFI projections (fp32, small)
    hgemm_k<0><<<dim3(15, 2, 1), 256, SMEM_TOT>>>(
        tup, tup, TUFI, TUFI, bs, bs, 2, 5, 8,
        UFI, UFI, NG_, 2400,
        nullptr, nullptr, nullptr, nullptr, nullptr, nullptr, nullptr, nullptr, nullptr);

    // e-projection + fused bond update + BN stats
    hgemm_k<3><<<dim3(5, 188, 2), 256, SMEM_TOT>>>(
        tep, te2p, TB1, TB1, bs, bs, 1, 1, 1,
        e1n, e2n, NB_, 800,
        ba1, ba2, bg1, bg2, P1, P2, UFI,
        bnsum + 0, bnsum + 800);

    // BN(e) prep + apply + segsum
    bnprep_k<<<4, 256>>>(bnsum + 0, bnsq + 0, gam, bet, (float)NB_, bnsc + 0, bnsh + 0);
    bnprep_k<<<4, 256>>>(bnsum + 800, bnsq + 800, gam, bet, (float)NB_, bnsc + 800, bnsh + 800);
    bnseg_k<<<dim3(13, 12), 256, 65536>>>(e1n, NB_, bg1, bnsc + 0, bnsh + 0, ssum + 204800);
    bnseg_k<<<dim3(13, 12), 256, 65536>>>(e2n, NB_, bg2, bnsc + 800, bnsh + 800, ssum + 614400);

    // atom update (pre-mix h)
    atom_k<<<NA_, 256>>>(h1n, P1, UFI, e1n, ab1, ba1, ag1);
    atom_k<<<NA_, 256>>>(h2n, P2, UFI, e2n, ab2, ba2, ag2);

    // cross + mix (fused BN stats)
    crossconv_k<<<NH / 1024, 256>>>(P1, P2, thp, th2p);
    hgemm_k<1><<<dim3(5, 157, 2), 256, SMEM_TOT>>>(
        th2p, thp, TW9, TW9, bs, bs, 9, 9, 9,
        h1n, h2n, NA_, 800,
        nullptr, nullptr, nullptr, nullptr, nullptr, nullptr, nullptr,
        bnsum + 1600, bnsum + 2400);

    // BN(h) prep + apply + segsum
    bnprep_k<<<4, 256>>>(bnsum + 1600, bnsq + 1600, gam + 800, bet + 800, (float)NA_, bnsc + 1600, bnsh + 1600);
    bnprep_k<<<4, 256>>>(bnsum + 2400, bnsq + 2400, gam + 800, bet + 800, (float)NA_, bnsc + 2400, bnsh + 2400);
    bnseg_k<<<dim3(13, 12), 256, 65536>>>(h1n, NA_, ag1, bnsc + 1600, bnsh + 1600, ssum + 0);
    bnseg_k<<<dim3(13, 12), 256, 65536>>>(h2n, NA_, ag2, bnsc + 2400, bnsh + 2400, ssum + 409600);

    // global readout on means
    meanprep_k<<<NU / 1024, 256>>>(ssum, cnts, mH, mE);
    hgemm_k<0><<<dim3(5, 2, 2), 256, SMEM_TOT>>>(
        mH, mE, TG, TH7, zbias, zbias, 0, 0, 0,
        P6, P7, NG_, 800,
        nullptr, nullptr, nullptr, nullptr, nullptr, nullptr, nullptr, nullptr, nullptr);

    // fused combine + stats, then BN(u) + relu
    ucombstats_k<<<25, 256>>>(un, P6, P7, UFI, cnts, bs, bnsum + 3200, bnsq + 3200);
    bnprep_k<<<4, 256>>>(bnsum + 3200, bnsq + 3200, gam + 1600, bet + 1600, (float)NG_, bnsc + 3200, bnsh + 3200);
    bnrelu_k<<<(NU + 255) / 256, 256>>>(un, NU, bnsc + 3200, bnsh + 3200);
}

// round 9
// speedup vs baseline: 5.5453x; 1.0458x over previous
#include <cuda_runtime.h>
#include <cuda_fp16.h>
#include <cstdint>
#include <math.h>

#define DD 800
#define NA_ 20000
#define NB_ 24000
#define NG_ 256

// ---- HMMA GEMM tiling (pure fp16 single pass) ----
#define BM 128
#define BN 160
#define BK 32
#define SA_ 0
#define SB_ 10240
#define STAGE_B 23040
#define SMEM_TOT (3 * STAGE_B)   // 69120

// ---------------------------------------------------------------------------
// Scratch layout (float offsets)
// ---------------------------------------------------------------------------
static constexpr size_t O_P1 = 0;             // [20000][2400] fp16 A|D|E half1
static constexpr size_t O_P2 = 48000000;      // fp16 half2
static constexpr size_t O_SMALL = 96000000;
static constexpr size_t O_TW   = 98400000;
static constexpr size_t O_THp  = 104800000;
static constexpr size_t O_TH2p = 120800000;
static constexpr size_t O_TEp  = 136800000;   // e fp16 plane; later sig1
static constexpr size_t O_TE2p = 156000000;   // e2 fp16 plane; later sig2
static constexpr size_t O_TUp  = 175200000;
__device__ __align__(1024) float g_scratch[176000000];

// ---------------------------------------------------------------------------
__device__ __forceinline__ uint32_t smem_u32(const void* p) {
    uint32_t a;
    asm("{ .reg .u64 t; cvta.to.shared.u64 t, %1; cvt.u32.u64 %0, t; }" : "=r"(a) : "l"(p));
    return a;
}
__device__ __forceinline__ void cp16(uint32_t saddr, const void* gaddr) {
    asm volatile("cp.async.cg.shared.global [%0], [%1], 16;" :: "r"(saddr), "l"(gaddr));
}
__device__ __forceinline__ void cp_commit() {
    asm volatile("cp.async.commit_group;" ::: "memory");
}
__device__ __forceinline__ void cp_wait1() {
    asm volatile("cp.async.wait_group 1;" ::: "memory");
}
__device__ __forceinline__ void cp_wait0() {
    asm volatile("cp.async.wait_group 0;" ::: "memory");
}
__device__ __forceinline__ void ldsm4(uint32_t* r, uint32_t addr) {
    asm volatile("ldmatrix.sync.aligned.m8n8.x4.shared.b16 {%0,%1,%2,%3}, [%4];"
                 : "=r"(r[0]), "=r"(r[1]), "=r"(r[2]), "=r"(r[3]) : "r"(addr));
}
__device__ __forceinline__ void mma16816(float* c, const uint32_t* a, const uint32_t* b) {
    asm volatile(
        "mma.sync.aligned.m16n8k16.row.col.f32.f16.f16.f32 "
        "{%0,%1,%2,%3}, {%4,%5,%6,%7}, {%8,%9}, {%0,%1,%2,%3};"
        : "+f"(c[0]), "+f"(c[1]), "+f"(c[2]), "+f"(c[3])
        : "r"(a[0]), "r"(a[1]), "r"(a[2]), "r"(a[3]), "r"(b[0]), "r"(b[1]));
}

// ---------------------------------------------------------------------------
// fp16 HMMA GEMM, z-batched pair.
// MODE 0: store fp32 acc+bias
// MODE 1: C = 0.8*C + 0.2*(acc+bias), accumulate BN stats
// MODE 3: C = acc+bias + Ah[i0]+Ah[i1]+Cu[g] (bond fuse; A gathers fp16), BN stats
// MODE 4: store fp16 acc+bias
// ---------------------------------------------------------------------------
template<int MODE>
__global__ __launch_bounds__(256, 2)
void hgemm_k(const __half* __restrict__ Ah0, const __half* __restrict__ Ah1,
             const __half* __restrict__ B0_, const __half* __restrict__ B1_,
             const float* __restrict__ bias0, const float* __restrict__ bias1,
             int bm0, int bm1, int bm2,
             void* __restrict__ C0, void* __restrict__ C1, int M, int ldc,
             const int* __restrict__ ba0, const int* __restrict__ ba1p,
             const int* __restrict__ bg0, const int* __restrict__ bg1p,
             const __half* __restrict__ P0g, const __half* __restrict__ P1g,
             const float* __restrict__ CuB,
             float* __restrict__ st0, float* __restrict__ st1)
{
    extern __shared__ char smem[];
    uint32_t sb = smem_u32(smem);
    int tid = threadIdx.x;
    int lid = tid & 31, wid = tid >> 5;
    int wm = wid & 3, wn = wid >> 2;
    int ntile = blockIdx.x, mtile = blockIdx.y, z = blockIdx.z;

    const __half* Ahp = z ? Ah1 : Ah0;
    const __half* Bp  = z ? B1_ : B0_;
    const float* bias = z ? bias1 : bias0;

    int arow[2], acol[2];
    uint32_t asoff[2];
#pragma unroll
    for (int t = 0; t < 2; t++) {
        int q = tid + t * 256;
        int r = q >> 2, c = q & 3;
        arow[t] = min(mtile * BM + r, M - 1);
        acol[t] = c * 8;
        asoff[t] = r * 80 + c * 16;
    }
    int brow[3], bcol[3];
    uint32_t bsoff[3];
#pragma unroll
    for (int t = 0; t < 3; t++) {
        int q = tid + t * 256;
        int r = q >> 2, c = q & 3;
        brow[t] = ntile * BN + r;
        bcol[t] = c * 8;
        bsoff[t] = r * 80 + c * 16;
    }
    bool b3 = (tid < 128);

    auto load_stage = [&](int s, int kc) {
        uint32_t st = sb + s * STAGE_B;
        int k0 = kc * BK;
#pragma unroll
        for (int t = 0; t < 2; t++)
            cp16(st + SA_ + asoff[t], Ahp + (size_t)arow[t] * DD + k0 + acol[t]);
#pragma unroll
        for (int t = 0; t < 2; t++)
            cp16(st + SB_ + bsoff[t], Bp + (size_t)brow[t] * DD + k0 + bcol[t]);
        if (b3)
            cp16(st + SB_ + bsoff[2], Bp + (size_t)brow[2] * DD + k0 + bcol[2]);
    };

    float acc[2][10][4];
#pragma unroll
    for (int i = 0; i < 2; i++)
#pragma unroll
        for (int j = 0; j < 10; j++)
#pragma unroll
            for (int k = 0; k < 4; k++) acc[i][j][k] = 0.f;

    uint32_t aswz = (lid & 15) * 80 + (lid >> 4) * 16;
    uint32_t bswz = ((lid & 7) + ((lid & 16) ? 8 : 0)) * 80 + ((lid >> 3) & 1) * 16;
    uint32_t a_base = (wm * 32) * 80 + aswz;
    uint32_t b_base = (wn * 80) * 80 + bswz;

    load_stage(0, 0); cp_commit();
    load_stage(1, 1); cp_commit();

#pragma unroll 1
    for (int kc = 0; kc < 25; kc++) {
        int s = kc % 3;
        cp_wait1();
        __syncthreads();
        uint32_t st = sb + s * STAGE_B;
#pragma unroll
        for (int k16 = 0; k16 < 2; k16++) {
            uint32_t aH[2][4];
            ldsm4(aH[0], st + SA_ + a_base + k16 * 32);
            ldsm4(aH[1], st + SA_ + a_base + 16 * 80 + k16 * 32);
#pragma unroll
            for (int g = 0; g < 5; g++) {
                uint32_t bH[4];
                ldsm4(bH, st + SB_ + b_base + g * 16 * 80 + k16 * 32);
                mma16816(acc[0][2 * g],     aH[0], bH);
                mma16816(acc[0][2 * g + 1], aH[0], bH + 2);
                mma16816(acc[1][2 * g],     aH[1], bH);
                mma16816(acc[1][2 * g + 1], aH[1], bH + 2);
            }
        }
        if (kc + 2 < 25) load_stage((kc + 2) % 3, kc + 2);
        cp_commit();
    }

    // ---------------- epilogue ----------------
    cp_wait0();
    __syncthreads();
    float* smst = (float*)smem;
    if (MODE == 1 || MODE == 3) {
        for (int i = tid; i < 320; i += 256) smst[i] = 0.f;
        __syncthreads();
    }

    int bseg = ntile / 5;
    const float* bp = bias + (bseg == 0 ? bm0 : bseg == 1 ? bm1 : bm2) * 800 - bseg * 800;

    float* Cf  = (float*)(z ? C1 : C0);
    __half* Ch = (__half*)(z ? C1 : C0);
    float* st = z ? st1 : st0;
    const int* BA = z ? ba1p : ba0;
    const int* BG = z ? bg1p : bg0;
    const __half* Pg = z ? P1g : P0g;

    int rows[4];
    bool rok[4];
    const __half *pA0[4], *pA1[4];
    const float *pCu[4];
#pragma unroll
    for (int q = 0; q < 4; q++) {
        int i = q >> 1, half = q & 1;
        int r = mtile * BM + wm * 32 + i * 16 + half * 8 + (lid >> 2);
        rows[q] = r;
        rok[q] = r < M;
        if (MODE == 3 && rok[q]) {
            int2 bb = ((const int2*)BA)[r];
            int gg = BG[r];
            pA0[q] = Pg + (size_t)bb.x * 2400;
            pA1[q] = Pg + (size_t)bb.y * 2400;
            pCu[q] = CuB + (size_t)gg * 2400;
        }
    }

#pragma unroll
    for (int j = 0; j < 10; j++) {
        int colloc = wn * 80 + j * 8 + (lid & 3) * 2;
        int col = ntile * 160 + colloc;
        float2 bv = *(const float2*)(bp + col);
        float s0 = 0.f, s1 = 0.f, q0 = 0.f, q1 = 0.f;
#pragma unroll
        for (int q = 0; q < 4; q++) {
            if (!rok[q]) continue;
            int i = q >> 1, half = q & 1;
            float v0 = acc[i][j][half * 2 + 0] + bv.x;
            float v1 = acc[i][j][half * 2 + 1] + bv.y;
            if (MODE == 3) {
                float2 a0v = __half22float2(*(const __half2*)(pA0[q] + col));
                float2 a1v = __half22float2(*(const __half2*)(pA1[q] + col));
                float2 cuv = *(const float2*)(pCu[q] + col);
                v0 += a0v.x + a1v.x + cuv.x;
                v1 += a0v.y + a1v.y + cuv.y;
            }
            if (MODE == 4) {
                *(__half2*)(Ch + (size_t)rows[q] * ldc + col) = __floats2half2_rn(v0, v1);
            } else {
                size_t co = (size_t)rows[q] * ldc + col;
                if (MODE == 1) {
                    float2 o = *(float2*)&Cf[co];
                    v0 = o.x * 0.8f + 0.2f * v0;
                    v1 = o.y * 0.8f + 0.2f * v1;
                }
                *(float2*)&Cf[co] = make_float2(v0, v1);
            }
            if (MODE == 1 || MODE == 3) {
                s0 += v0; q0 += v0 * v0;
                s1 += v1; q1 += v1 * v1;
            }
        }
        if (MODE == 1 || MODE == 3) {
#pragma unroll
            for (int d = 4; d < 32; d <<= 1) {
                s0 += __shfl_xor_sync(0xFFFFFFFFu, s0, d);
                s1 += __shfl_xor_sync(0xFFFFFFFFu, s1, d);
                q0 += __shfl_xor_sync(0xFFFFFFFFu, q0, d);
                q1 += __shfl_xor_sync(0xFFFFFFFFu, q1, d);
            }
            if (lid < 4) {
                atomicAdd(&smst[colloc], s0);
                atomicAdd(&smst[colloc + 1], s1);
                atomicAdd(&smst[160 + colloc], q0);
                atomicAdd(&smst[160 + colloc + 1], q1);
            }
        }
    }
    if (MODE == 1 || MODE == 3) {
        __syncthreads();
        for (int i = tid; i < 160; i += 256) {
            atomicAdd(&st[ntile * 160 + i], smst[i]);
            atomicAdd(&st[4000 + ntile * 160 + i], smst[160 + i]);
        }
    }
}

// ---------------------------------------------------------------------------
// conversions
// ---------------------------------------------------------------------------
__global__ void conv_all_k(const float* __restrict__ h, const float* __restrict__ h2,
                           const float* __restrict__ e, const float* __restrict__ e2,
                           __half* __restrict__ th, __half* __restrict__ th2,
                           __half* __restrict__ te, __half* __restrict__ te2)
{
    int z = blockIdx.y;
    const float* A = (z == 0) ? h : (z == 1) ? h2 : (z == 2) ? e : e2;
    __half* T = (z == 0) ? th : (z == 1) ? th2 : (z == 2) ? te : te2;
    int n = (z < 2) ? NA_ * DD : NB_ * DD;
    int i4 = (blockIdx.x * blockDim.x + threadIdx.x) * 4;
    if (i4 >= n) return;
    float4 v = *(const float4*)(A + i4);
    __half2 a = __floats2half2_rn(v.x, v.y);
    __half2 b = __floats2half2_rn(v.z, v.w);
    *(uint2*)((unsigned short*)T + i4) = make_uint2(*(uint32_t*)&a, *(uint32_t*)&b);
}
__global__ void conv_a_k(const float* __restrict__ A, int n, __half* __restrict__ T)
{
    int i4 = (blockIdx.x * blockDim.x + threadIdx.x) * 4;
    if (i4 >= n) return;
    float4 v = *(const float4*)(A + i4);
    __half2 a = __floats2half2_rn(v.x, v.y);
    __half2 b = __floats2half2_rn(v.z, v.w);
    *(uint2*)((unsigned short*)T + i4) = make_uint2(*(uint32_t*)&a, *(uint32_t*)&b);
}

// weight transpose -> fp16 plane, packed groups
__global__ void conv_w_k(const float* __restrict__ Ws, __half* __restrict__ TW)
{
    static const int BASE[10]   = {0, 1920000, 2560000, 0, 0, 2560000, 4480000, 5120000, 2560000, 5760000};
    static const int ROWOFF[10] = {0, 0, 0, 800, 1600, 800, 0, 0, 1600, 0};
    __shared__ float t[32][33];
    int wi = blockIdx.z;
    const float* W = Ws + (size_t)wi * (DD * DD);
    __half* hi = TW + BASE[wi] + (size_t)ROWOFF[wi] * DD;
    int tx = threadIdx.x, ty = threadIdx.y;
    int kb = blockIdx.y * 32, nb = blockIdx.x * 32;
#pragma unroll
    for (int r = 0; r < 4; r++)
        t[ty + r * 8][tx] = W[(size_t)(kb + ty + r * 8) * DD + nb + tx];
    __syncthreads();
#pragma unroll
    for (int r = 0; r < 4; r++) {
        int nrow = nb + ty + r * 8;
        int kcol = kb + tx;
        hi[(size_t)nrow * DD + kcol] = __float2half_rn(t[tx][ty + r * 8]);
    }
}

// fused cross-gate + cast from fp16 P planes
__global__ void crossconv_k(const __half* __restrict__ P1, const __half* __restrict__ P2,
                            __half* __restrict__ T1, __half* __restrict__ T2)
{
    int i4 = (blockIdx.x * blockDim.x + threadIdx.x) * 4;
    if (i4 >= NA_ * DD) return;
    int r = i4 / DD, c = i4 % DD;
    size_t po = (size_t)r * 2400 + 800 + c;
    float2 d1a = __half22float2(*(const __half2*)(P1 + po));
    float2 d1b = __half22float2(*(const __half2*)(P1 + po + 2));
    float2 d2a = __half22float2(*(const __half2*)(P2 + po));
    float2 d2b = __half22float2(*(const __half2*)(P2 + po + 2));
    float4 t1v, t2v;
    float f;
    f = 1.f / (fabsf(d1a.x - d2a.x) + 1.f); t1v.x = f * d1a.x; t2v.x = f * d2a.x;
    f = 1.f / (fabsf(d1a.y - d2a.y) + 1.f); t1v.y = f * d1a.y; t2v.y = f * d2a.y;
    f = 1.f / (fabsf(d1b.x - d2b.x) + 1.f); t1v.z = f * d1b.x; t2v.z = f * d2b.x;
    f = 1.f / (fabsf(d1b.y - d2b.y) + 1.f); t1v.w = f * d1b.y; t2v.w = f * d2b.y;
    __half2 a = __floats2half2_rn(t1v.x, t1v.y);
    __half2 b = __floats2half2_rn(t1v.z, t1v.w);
    *(uint2*)((unsigned short*)T1 + i4) = make_uint2(*(uint32_t*)&a, *(uint32_t*)&b);
    a = __floats2half2_rn(t2v.x, t2v.y);
    b = __floats2half2_rn(t2v.z, t2v.w);
    *(uint2*)((unsigned short*)T2 + i4) = make_uint2(*(uint32_t*)&a, *(uint32_t*)&b);
}

// ---------------------------------------------------------------------------
__global__ void zero_k(float* p, int n) {
    int i = blockIdx.x * blockDim.x + threadIdx.x;
    if (i < n) p[i] = 0.f;
}
__global__ void count_all_k(const int* __restrict__ ag1, const int* __restrict__ bg1,
                            const int* __restrict__ ag2, const int* __restrict__ bg2,
                            float* __restrict__ cnts)
{
    int y = blockIdx.y;
    int i = blockIdx.x * blockDim.x + threadIdx.x;
    const int* s = (y == 0) ? ag1 : (y == 1) ? bg1 : (y == 2) ? ag2 : bg2;
    int n = (y & 1) ? NB_ : NA_;
    if (i < n) atomicAdd(&cnts[y * 256 + s[i]], 1.0f);
}
__global__ void bnprep_k(const float* __restrict__ sum, const float* __restrict__ sumsq,
                         const float* __restrict__ gamma, const float* __restrict__ beta,
                         float Rf, float* __restrict__ scale, float* __restrict__ shift)
{
    int c = blockIdx.x * blockDim.x + threadIdx.x;
    if (c >= DD) return;
    float m = sum[c] / Rf;
    float v = sumsq[c] / Rf - m * m;
    float sc = gamma[c] * rsqrtf(v + 1e-5f);
    scale[c] = sc;
    shift[c] = beta[c] - m * sc;
}
__global__ void bnrelu_k(float* __restrict__ X, int n,
                         const float* __restrict__ scale, const float* __restrict__ shift)
{
    int i = blockIdx.x * blockDim.x + threadIdx.x;
    if (i >= n) return;
    int col = i % DD;
    X[i] = fmaxf(fmaf(X[i], scale[col], shift[col]), 0.f);
}
// fused BN-apply + relu + segment-sum (+ optional fp16 sigmoid emit)
__global__ void bnseg_k(float* __restrict__ X, int M, const int* __restrict__ seg,
                        const float* __restrict__ scale, const float* __restrict__ shift,
                        float* __restrict__ ssum, __half* __restrict__ sigout)
{
    extern __shared__ float sm[];
    int c0 = blockIdx.x * 64;
    int cl = threadIdx.x & 63;
    int col = c0 + cl;
    int rg = threadIdx.x >> 6;
    for (int i = threadIdx.x; i < 16384; i += 256) sm[i] = 0.f;
    __syncthreads();
    bool ok = col < DD;
    float sc = ok ? scale[col] : 0.f;
    float sh = ok ? shift[col] : 0.f;
    int chunk = (M + gridDim.y - 1) / gridDim.y;
    int r0 = blockIdx.y * chunk;
    int r1 = min(r0 + chunk, M);
    for (int r = r0 + rg; r < r1; r += 4) {
        int g = seg[r];
        if (ok) {
            float y = fmaxf(fmaf(X[(size_t)r * DD + col], sc, sh), 0.f);
            X[(size_t)r * DD + col] = y;
            if (sigout) {
                float s = __fdividef(1.f, 1.f + __expf(-y));
                sigout[(size_t)r * DD + col] = __float2half_rn(s);
            }
            atomicAdd(&sm[g * 64 + cl], y);
        }
    }
    __syncthreads();
    for (int i = threadIdx.x; i < 16384; i += 256) {
        int g = i >> 6;
        int c = c0 + (i & 63);
        float v = sm[i];
        if (c < DD && v != 0.f) atomicAdd(&ssum[g * DD + c], v);
    }
}
// gated mailbox aggregation using precomputed fp16 sigmoids; z-batched halves
__global__ void atom_k(float* __restrict__ h1n, float* __restrict__ h2n,
                       const __half* __restrict__ P1, const __half* __restrict__ P2,
                       const float* __restrict__ UFI,
                       const __half* __restrict__ sig1, const __half* __restrict__ sig2,
                       const int* __restrict__ ab1, const int* __restrict__ ba1,
                       const int* __restrict__ ag1,
                       const int* __restrict__ ab2, const int* __restrict__ ba2,
                       const int* __restrict__ ag2)
{
    int z = blockIdx.y;
    float* h_out = z ? h2n : h1n;
    const __half* P = z ? P2 : P1;
    const __half* sig = z ? sig2 : sig1;
    const int* atom_bonds = z ? ab2 : ab1;
    const int* bond_atoms = z ? ba2 : ba1;
    const int* atom_graph = z ? ag2 : ag1;

    int a = blockIdx.x;
    __shared__ int sh_bond[4];
    __shared__ int sh_other[4];
    if (threadIdx.x < 4) {
        int b = atom_bonds[a * 4 + threadIdx.x];
        sh_bond[threadIdx.x] = b;
        int p0 = bond_atoms[b * 2];
        int p1 = bond_atoms[b * 2 + 1];
        sh_other[threadIdx.x] = (p0 != a) ? p0 : p1;
    }
    __syncthreads();
    int g = atom_graph[a];
    const __half* s0p = sig + (size_t)sh_bond[0] * DD;
    const __half* s1p = sig + (size_t)sh_bond[1] * DD;
    const __half* s2p = sig + (size_t)sh_bond[2] * DD;
    const __half* s3p = sig + (size_t)sh_bond[3] * DD;
    const __half* E0 = P + (size_t)sh_other[0] * 2400 + 1600;
    const __half* E1 = P + (size_t)sh_other[1] * 2400 + 1600;
    const __half* E2 = P + (size_t)sh_other[2] * 2400 + 1600;
    const __half* E3 = P + (size_t)sh_other[3] * 2400 + 1600;
    const __half* dh = P + (size_t)a * 2400 + 800;
    const float* fu = UFI + (size_t)g * 2400 + 800;
    float* ho = h_out + (size_t)a * DD;
    for (int c = threadIdx.x; c < DD; c += blockDim.x) {
        float w0 = __half2float(s0p[c]);
        float w1 = __half2float(s1p[c]);
        float w2 = __half2float(s2p[c]);
        float w3 = __half2float(s3p[c]);
        float num = w0 * __half2float(E0[c]) + w1 * __half2float(E1[c])
                  + w2 * __half2float(E2[c]) + w3 * __half2float(E3[c]);
        float den = w0 + w1 + w2 + w3 + 1e-6f;
        ho[c] = __half2float(dh[c]) + __fdividef(num, den) + fu[c];
    }
}
__global__ void meanprep_k(const float* __restrict__ ssum, const float* __restrict__ cnts,
                           __half* __restrict__ mH, __half* __restrict__ mE)
{
    int i4 = (blockIdx.x * blockDim.x + threadIdx.x) * 4;
    if (i4 >= NG_ * DD) return;
    int g = i4 / DD;
    float cA1 = fmaxf(cnts[g], 1.f),       cA2 = fmaxf(cnts[512 + g], 1.f);
    float cB1 = fmaxf(cnts[256 + g], 1.f), cB2 = fmaxf(cnts[768 + g], 1.f);
    const float* sh1 = ssum + i4;
    const float* se1 = ssum + 204800 + i4;
    const float* sh2 = ssum + 409600 + i4;
    const float* se2 = ssum + 614400 + i4;
    float4 vh, ve;
    vh.x = sh1[0] / cA1 + sh2[0] / cA2;  ve.x = se1[0] / cB1 + se2[0] / cB2;
    vh.y = sh1[1] / cA1 + sh2[1] / cA2;  ve.y = se1[1] / cB1 + se2[1] / cB2;
    vh.z = sh1[2] / cA1 + sh2[2] / cA2;  ve.z = se1[2] / cB1 + se2[2] / cB2;
    vh.w = sh1[3] / cA1 + sh2[3] / cA2;  ve.w = se1[3] / cB1 + se2[3] / cB2;
    __half2 a = __floats2half2_rn(vh.x, vh.y);
    __half2 b = __floats2half2_rn(vh.z, vh.w);
    *(uint2*)((unsigned short*)mH + i4) = make_uint2(*(uint32_t*)&a, *(uint32_t*)&b);
    a = __floats2half2_rn(ve.x, ve.y);
    b = __floats2half2_rn(ve.z, ve.w);
    *(uint2*)((unsigned short*)mE + i4) = make_uint2(*(uint32_t*)&a, *(uint32_t*)&b);
}
// fused: un = P6+P7+Iu+ind-bias, plus direct column stats
__global__ void ucombstats_k(float* __restrict__ un, const float* __restrict__ P6,
                             const float* __restrict__ P7, const float* __restrict__ UFI,
                             const float* __restrict__ cnts, const float* __restrict__ bs,
                             float* __restrict__ sum, float* __restrict__ sumsq)
{
    __shared__ float ssm[8][32], sqm[8][32];
    int cl = threadIdx.x & 31, rg = threadIdx.x >> 5;
    int col = blockIdx.x * 32 + cl;
    bool ok = col < DD;
    float s = 0.f, q = 0.f;
    if (ok) {
        float b6 = bs[6 * 800 + col], b7 = bs[7 * 800 + col];
        for (int g = rg; g < NG_; g += 8) {
            float indA = (cnts[g] > 0.f ? 1.f : 0.f) + (cnts[512 + g] > 0.f ? 1.f : 0.f);
            float indB = (cnts[256 + g] > 0.f ? 1.f : 0.f) + (cnts[768 + g] > 0.f ? 1.f : 0.f);
            float v = P6[(size_t)g * DD + col] + P7[(size_t)g * DD + col]
                    + UFI[(size_t)g * 2400 + 1600 + col] + b6 * indA + b7 * indB;
            un[(size_t)g * DD + col] = v;
            s += v; q += v * v;
        }
    }
    ssm[rg][cl] = s; sqm[rg][cl] = q;
    __syncthreads();
    if (rg == 0 && ok) {
        float S = 0.f, Q = 0.f;
#pragma unroll
        for (int r = 0; r < 8; r++) { S += ssm[r][cl]; Q += sqm[r][cl]; }
        sum[col] = S; sumsq[col] = Q;
    }
}

// ---------------------------------------------------------------------------
extern "C" void kernel_launch(void* const* d_in, const int* in_sizes, int n_in,
                              void* d_out, int out_size)
{
    const float* h   = (const float*)d_in[0];
    const float* e   = (const float*)d_in[1];
    const float* h2  = (const float*)d_in[2];
    const float* e2  = (const float*)d_in[3];
    const float* u   = (const float*)d_in[4];
    const float* Ws  = (const float*)d_in[5];
    const float* bs  = (const float*)d_in[6];
    const float* gam = (const float*)d_in[7];
    const float* bet = (const float*)d_in[8];
    const int* ba1 = (const int*)d_in[9];
    const int* ab1 = (const int*)d_in[10];
    const int* ag1 = (const int*)d_in[11];
    const int* bg1 = (const int*)d_in[12];
    const int* ba2 = (const int*)d_in[13];
    const int* ab2 = (const int*)d_in[14];
    const int* ag2 = (const int*)d_in[15];
    const int* bg2 = (const int*)d_in[16];

    float* out = (float*)d_out;
    float* h1n = out;
    float* e1n = out + 16000000;
    float* h2n = out + 35200000;
    float* e2n = out + 51200000;
    float* un  = out + 70400000;

    float* sp = nullptr;
    cudaGetSymbolAddress((void**)&sp, g_scratch);

    __half* P1 = (__half*)(sp + O_P1);
    __half* P2 = (__half*)(sp + O_P2);
    float* SM  = sp + O_SMALL;
    float* UFI = SM;
    float* ssum  = SM + 614400;
    float* cnts  = SM + 1433600;
    float* bnsum = SM + 1434624;
    float* bnsq  = SM + 1438624;
    float* zbias = SM + 1442624;
    float* bnsc  = SM + 1443424;
    float* bnsh  = SM + 1447424;
    __half* mH = (__half*)(SM + 1456224);
    __half* mE = (__half*)(SM + 1661024);
    float* P6 = SM + 1865824;
    float* P7 = SM + 2070624;

    __half* tw   = (__half*)(sp + O_TW);
    __half* thp  = (__half*)(sp + O_THp);
    __half* th2p = (__half*)(sp + O_TH2p);
    __half* tep  = (__half*)(sp + O_TEp);
    __half* te2p = (__half*)(sp + O_TE2p);
    __half* tup  = (__half*)(sp + O_TUp);
    __half* sig1 = tep;    // reuse: e planes dead after e-GEMM
    __half* sig2 = te2p;

    __half* TADE = tw + 0;
    __half* TB1  = tw + 1920000;
    __half* TUFI = tw + 2560000;
    __half* TG   = tw + 4480000;
    __half* TH7  = tw + 5120000;
    __half* TW9  = tw + 5760000;

    const int NH = NA_ * DD, NE = NB_ * DD, NU = NG_ * DD;

    cudaFuncSetAttribute(hgemm_k<0>, cudaFuncAttributeMaxDynamicSharedMemorySize, SMEM_TOT);
    cudaFuncSetAttribute(hgemm_k<1>, cudaFuncAttributeMaxDynamicSharedMemorySize, SMEM_TOT);
    cudaFuncSetAttribute(hgemm_k<3>, cudaFuncAttributeMaxDynamicSharedMemorySize, SMEM_TOT);
    cudaFuncSetAttribute(hgemm_k<4>, cudaFuncAttributeMaxDynamicSharedMemorySize, SMEM_TOT);
    cudaFuncSetAttribute(bnseg_k, cudaFuncAttributeMaxDynamicSharedMemorySize, 65536);

    // conversions + setup
    conv_all_k<<<dim3(18750, 4), 256>>>(h, h2, e, e2, thp, th2p, tep, te2p);
    conv_w_k<<<dim3(25, 25, 10), dim3(32, 8)>>>(Ws, tw);
    zero_k<<<(829024 + 255) / 256, 256>>>(ssum, 829024);
    count_all_k<<<dim3(94, 4), 256>>>(ag1, bg1, ag2, bg2, cnts);
    conv_a_k<<<NU / 1024, 256>>>(u, NU, tup);

    // ADE projections -> fp16 P
    hgemm_k<4><<<dim3(15, 157, 2), 256, SMEM_TOT>>>(
        thp, th2p, TADE, TADE, bs, bs, 0, 3, 4,
        P1, P2, NA_, 2400,
        nullptr, nullptr, nullptr, nullptr, nullptr, nullptr, nullptr, nullptr, nullptr);

    // UFI projections (fp32, small)
    hgemm_k<0><<<dim3(15, 2, 1), 256, SMEM_TOT>>>(
        tup, tup, TUFI, TUFI, bs, bs, 2, 5, 8,
        UFI, UFI, NG_, 2400,
        nullptr, nullptr, nullptr, nullptr, nullptr, nullptr, nullptr, nullptr, nullptr);

    // e-projection + fused bond update + BN stats
    hgemm_k<3><<<dim3(5, 188, 2), 256, SMEM_TOT>>>(
        tep, te2p, TB1, TB1, bs, bs, 1, 1, 1,
        e1n, e2n, NB_, 800,
        ba1, ba2, bg1, bg2, P1, P2, UFI,
        bnsum + 0, bnsum + 800);

    // BN(e) prep + apply + segsum + sigmoid emit (tep/te2p now reused as sig)
    bnprep_k<<<4, 256>>>(bnsum + 0, bnsq + 0, gam, bet, (float)NB_, bnsc + 0, bnsh + 0);
    bnprep_k<<<4, 256>>>(bnsum + 800, bnsq + 800, gam, bet, (float)NB_, bnsc + 800, bnsh + 800);
    bnseg_k<<<dim3(13, 12), 256, 65536>>>(e1n, NB_, bg1, bnsc + 0, bnsh + 0, ssum + 204800, sig1);
    bnseg_k<<<dim3(13, 12), 256, 65536>>>(e2n, NB_, bg2, bnsc + 800, bnsh + 800, ssum + 614400, sig2);

    // atom update, both halves (no exp: precomputed sig weights)
    atom_k<<<dim3(NA_, 2), 256>>>(h1n, h2n, P1, P2, UFI, sig1, sig2,
                                  ab1, ba1, ag1, ab2, ba2, ag2);

    // cross + mix (fused BN stats)
    crossconv_k<<<NH / 1024, 256>>>(P1, P2, thp, th2p);
    hgemm_k<1><<<dim3(5, 157, 2), 256, SMEM_TOT>>>(
        th2p, thp, TW9, TW9, bs, bs, 9, 9, 9,
        h1n, h2n, NA_, 800,
        nullptr, nullptr, nullptr, nullptr, nullptr, nullptr, nullptr,
        bnsum + 1600, bnsum + 2400);

    // BN(h) prep + apply + segsum
    bnprep_k<<<4, 256>>>(bnsum + 1600, bnsq + 1600, gam + 800, bet + 800, (float)NA_, bnsc + 1600, bnsh + 1600);
    bnprep_k<<<4, 256>>>(bnsum + 2400, bnsq + 2400, gam + 800, bet + 800, (float)NA_, bnsc + 2400, bnsh + 2400);
    bnseg_k<<<dim3(13, 12), 256, 65536>>>(h1n, NA_, ag1, bnsc + 1600, bnsh + 1600, ssum + 0, nullptr);
    bnseg_k<<<dim3(13, 12), 256, 65536>>>(h2n, NA_, ag2, bnsc + 2400, bnsh + 2400, ssum + 409600, nullptr);

    // global readout on means
    meanprep_k<<<NU / 1024, 256>>>(ssum, cnts, mH, mE);
    hgemm_k<0><<<dim3(5, 2, 2), 256, SMEM_TOT>>>(
        mH, mE, TG, TH7, zbias, zbias, 0, 0, 0,
        P6, P7, NG_, 800,
        nullptr, nullptr, nullptr, nullptr, nullptr, nullptr, nullptr, nullptr, nullptr);

    // fused combine + stats, then BN(u) + relu
    ucombstats_k<<<25, 256>>>(un, P6, P7, UFI, cnts, bs, bnsum + 3200, bnsq + 3200);
    bnprep_k<<<4, 256>>>(bnsum + 3200, bnsq + 3200, gam + 1600, bet + 1600, (float)NG_, bnsc + 3200, bnsh + 3200);
    bnrelu_k<<<(NU + 255) / 256, 256>>>(un, NU, bnsc + 3200, bnsh + 3200);
}

// round 10
// speedup vs baseline: 7.0252x; 1.2669x over previous
#include <cuda_runtime.h>
#include <cuda_fp16.h>
#include <cstdint>
#include <math.h>

#define DD 800
#define NA_ 20000
#define NB_ 24000
#define NG_ 256

// ---- HMMA GEMM tiling (pure fp16 single pass) ----
#define BM 128
#define BN 160
#define BK 32
#define SA_ 0
#define SB_ 10240
#define STAGE_B 23040
#define SMEM_TOT (3 * STAGE_B)   // 69120

// ---------------------------------------------------------------------------
// Scratch layout (float offsets)
// ---------------------------------------------------------------------------
static constexpr size_t O_P1 = 0;             // [20000][2400] fp16 A|D|E half1
static constexpr size_t O_P2 = 48000000;      // fp16 half2
static constexpr size_t O_SMALL = 96000000;
static constexpr size_t O_TW   = 98400000;
static constexpr size_t O_THp  = 104800000;
static constexpr size_t O_TH2p = 120800000;
static constexpr size_t O_TEp  = 136800000;   // e fp16 plane; later sig1
static constexpr size_t O_TE2p = 156000000;   // e2 fp16 plane; later sig2
static constexpr size_t O_TUp  = 175200000;
__device__ __align__(1024) float g_scratch[176000000];

// ---------------------------------------------------------------------------
__device__ __forceinline__ uint32_t smem_u32(const void* p) {
    uint32_t a;
    asm("{ .reg .u64 t; cvta.to.shared.u64 t, %1; cvt.u32.u64 %0, t; }" : "=r"(a) : "l"(p));
    return a;
}
__device__ __forceinline__ void cp16(uint32_t saddr, const void* gaddr) {
    asm volatile("cp.async.cg.shared.global [%0], [%1], 16;" :: "r"(saddr), "l"(gaddr));
}
__device__ __forceinline__ void cp_commit() {
    asm volatile("cp.async.commit_group;" ::: "memory");
}
__device__ __forceinline__ void cp_wait1() {
    asm volatile("cp.async.wait_group 1;" ::: "memory");
}
__device__ __forceinline__ void cp_wait0() {
    asm volatile("cp.async.wait_group 0;" ::: "memory");
}
__device__ __forceinline__ void ldsm4(uint32_t* r, uint32_t addr) {
    asm volatile("ldmatrix.sync.aligned.m8n8.x4.shared.b16 {%0,%1,%2,%3}, [%4];"
                 : "=r"(r[0]), "=r"(r[1]), "=r"(r[2]), "=r"(r[3]) : "r"(addr));
}
__device__ __forceinline__ void mma16816(float* c, const uint32_t* a, const uint32_t* b) {
    asm volatile(
        "mma.sync.aligned.m16n8k16.row.col.f32.f16.f16.f32 "
        "{%0,%1,%2,%3}, {%4,%5,%6,%7}, {%8,%9}, {%0,%1,%2,%3};"
        : "+f"(c[0]), "+f"(c[1]), "+f"(c[2]), "+f"(c[3])
        : "r"(a[0]), "r"(a[1]), "r"(a[2]), "r"(a[3]), "r"(b[0]), "r"(b[1]));
}

// ---------------------------------------------------------------------------
// fp16 HMMA GEMM, z-batched pair.
// MODE 0: store fp32 acc+bias
// MODE 3: C = acc+bias + Ah[i0]+Ah[i1]+Cu[g] (bond fuse), BN stats
// MODE 4: store fp16 acc+bias
// MODE 5: fused atom update + mix:
//         C = 0.8*(dh + gated_agg + Fu[g]) + 0.2*(acc+bias), BN stats
// ---------------------------------------------------------------------------
template<int MODE>
__global__ __launch_bounds__(256, 2)
void hgemm_k(const __half* __restrict__ Ah0, const __half* __restrict__ Ah1,
             const __half* __restrict__ B0_, const __half* __restrict__ B1_,
             const float* __restrict__ bias0, const float* __restrict__ bias1,
             int bm0, int bm1, int bm2,
             void* __restrict__ C0, void* __restrict__ C1, int M, int ldc,
             const int* __restrict__ ba0, const int* __restrict__ ba1p,
             const int* __restrict__ bg0, const int* __restrict__ bg1p,
             const __half* __restrict__ P0g, const __half* __restrict__ P1g,
             const float* __restrict__ CuB,
             float* __restrict__ st0, float* __restrict__ st1,
             const int* __restrict__ ab0_, const int* __restrict__ ab1_,
             const int* __restrict__ ag0_, const int* __restrict__ ag1_,
             const __half* __restrict__ sg0, const __half* __restrict__ sg1)
{
    constexpr bool STATS = (MODE == 3 || MODE == 5);
    extern __shared__ char smem[];
    uint32_t sb = smem_u32(smem);
    int tid = threadIdx.x;
    int lid = tid & 31, wid = tid >> 5;
    int wm = wid & 3, wn = wid >> 2;
    int ntile = blockIdx.x, mtile = blockIdx.y, z = blockIdx.z;

    const __half* Ahp = z ? Ah1 : Ah0;
    const __half* Bp  = z ? B1_ : B0_;
    const float* bias = z ? bias1 : bias0;

    int arow[2], acol[2];
    uint32_t asoff[2];
#pragma unroll
    for (int t = 0; t < 2; t++) {
        int q = tid + t * 256;
        int r = q >> 2, c = q & 3;
        arow[t] = min(mtile * BM + r, M - 1);
        acol[t] = c * 8;
        asoff[t] = r * 80 + c * 16;
    }
    int brow[3], bcol[3];
    uint32_t bsoff[3];
#pragma unroll
    for (int t = 0; t < 3; t++) {
        int q = tid + t * 256;
        int r = q >> 2, c = q & 3;
        brow[t] = ntile * BN + r;
        bcol[t] = c * 8;
        bsoff[t] = r * 80 + c * 16;
    }
    bool b3 = (tid < 128);

    auto load_stage = [&](int s, int kc) {
        uint32_t st = sb + s * STAGE_B;
        int k0 = kc * BK;
#pragma unroll
        for (int t = 0; t < 2; t++)
            cp16(st + SA_ + asoff[t], Ahp + (size_t)arow[t] * DD + k0 + acol[t]);
#pragma unroll
        for (int t = 0; t < 2; t++)
            cp16(st + SB_ + bsoff[t], Bp + (size_t)brow[t] * DD + k0 + bcol[t]);
        if (b3)
            cp16(st + SB_ + bsoff[2], Bp + (size_t)brow[2] * DD + k0 + bcol[2]);
    };

    float acc[2][10][4];
#pragma unroll
    for (int i = 0; i < 2; i++)
#pragma unroll
        for (int j = 0; j < 10; j++)
#pragma unroll
            for (int k = 0; k < 4; k++) acc[i][j][k] = 0.f;

    uint32_t aswz = (lid & 15) * 80 + (lid >> 4) * 16;
    uint32_t bswz = ((lid & 7) + ((lid & 16) ? 8 : 0)) * 80 + ((lid >> 3) & 1) * 16;
    uint32_t a_base = (wm * 32) * 80 + aswz;
    uint32_t b_base = (wn * 80) * 80 + bswz;

    load_stage(0, 0); cp_commit();
    load_stage(1, 1); cp_commit();

#pragma unroll 1
    for (int kc = 0; kc < 25; kc++) {
        int s = kc % 3;
        cp_wait1();
        __syncthreads();
        uint32_t st = sb + s * STAGE_B;
#pragma unroll
        for (int k16 = 0; k16 < 2; k16++) {
            uint32_t aH[2][4];
            ldsm4(aH[0], st + SA_ + a_base + k16 * 32);
            ldsm4(aH[1], st + SA_ + a_base + 16 * 80 + k16 * 32);
#pragma unroll
            for (int g = 0; g < 5; g++) {
                uint32_t bH[4];
                ldsm4(bH, st + SB_ + b_base + g * 16 * 80 + k16 * 32);
                mma16816(acc[0][2 * g],     aH[0], bH);
                mma16816(acc[0][2 * g + 1], aH[0], bH + 2);
                mma16816(acc[1][2 * g],     aH[1], bH);
                mma16816(acc[1][2 * g + 1], aH[1], bH + 2);
            }
        }
        if (kc + 2 < 25) load_stage((kc + 2) % 3, kc + 2);
        cp_commit();
    }

    // ---------------- epilogue ----------------
    cp_wait0();
    __syncthreads();
    float* smst = (float*)smem;
    if (STATS) {
        for (int i = tid; i < 320; i += 256) smst[i] = 0.f;
        __syncthreads();
    }

    int bseg = ntile / 5;
    const float* bp = bias + (bseg == 0 ? bm0 : bseg == 1 ? bm1 : bm2) * 800 - bseg * 800;

    float* Cf  = (float*)(z ? C1 : C0);
    __half* Ch = (__half*)(z ? C1 : C0);
    float* st = z ? st1 : st0;

    if (MODE == 5) {
        const int* AB  = z ? ab1_ : ab0_;
        const int* BAm = z ? ba1p : ba0;
        const int* AG  = z ? ag1_ : ag0_;
        const __half* SG = z ? sg1 : sg0;
        const __half* Pm = z ? P1g : P0g;
#pragma unroll
        for (int q = 0; q < 4; q++) {
            const int iq = q >> 1, half = q & 1;
            int r = mtile * BM + wm * 32 + iq * 16 + half * 8 + (lid >> 2);
            bool ok = r < M;
            int b0 = 0, b1 = 0, b2 = 0, b3i = 0, o0 = 0, o1 = 0, o2 = 0, o3 = 0, gg = 0;
            if (ok) {
                int4 bb = ((const int4*)AB)[r];
                b0 = bb.x; b1 = bb.y; b2 = bb.z; b3i = bb.w;
                int2 p;
                p = ((const int2*)BAm)[b0];  o0 = (p.x != r) ? p.x : p.y;
                p = ((const int2*)BAm)[b1];  o1 = (p.x != r) ? p.x : p.y;
                p = ((const int2*)BAm)[b2];  o2 = (p.x != r) ? p.x : p.y;
                p = ((const int2*)BAm)[b3i]; o3 = (p.x != r) ? p.x : p.y;
                gg = AG[r];
            }
#pragma unroll
            for (int j = 0; j < 10; j++) {
                int colloc = wn * 80 + j * 8 + (lid & 3) * 2;
                int col = ntile * 160 + colloc;
                float v0 = 0.f, v1 = 0.f;
                if (ok) {
                    float2 bv = *(const float2*)(bp + col);
                    float a0 = acc[iq][j][half * 2 + 0] + bv.x;
                    float a1 = acc[iq][j][half * 2 + 1] + bv.y;
                    float2 w0 = __half22float2(*(const __half2*)(SG + (size_t)b0 * DD + col));
                    float2 w1 = __half22float2(*(const __half2*)(SG + (size_t)b1 * DD + col));
                    float2 w2 = __half22float2(*(const __half2*)(SG + (size_t)b2 * DD + col));
                    float2 w3 = __half22float2(*(const __half2*)(SG + (size_t)b3i * DD + col));
                    float2 e0 = __half22float2(*(const __half2*)(Pm + (size_t)o0 * 2400 + 1600 + col));
                    float2 e1v = __half22float2(*(const __half2*)(Pm + (size_t)o1 * 2400 + 1600 + col));
                    float2 e2v = __half22float2(*(const __half2*)(Pm + (size_t)o2 * 2400 + 1600 + col));
                    float2 e3v = __half22float2(*(const __half2*)(Pm + (size_t)o3 * 2400 + 1600 + col));
                    float2 dh = __half22float2(*(const __half2*)(Pm + (size_t)r * 2400 + 800 + col));
                    float2 fu = *(const float2*)(CuB + (size_t)gg * 2400 + 800 + col);
                    float num0 = w0.x * e0.x + w1.x * e1v.x + w2.x * e2v.x + w3.x * e3v.x;
                    float den0 = w0.x + w1.x + w2.x + w3.x + 1e-6f;
                    float num1 = w0.y * e0.y + w1.y * e1v.y + w2.y * e2v.y + w3.y * e3v.y;
                    float den1 = w0.y + w1.y + w2.y + w3.y + 1e-6f;
                    float h0 = dh.x + __fdividef(num0, den0) + fu.x;
                    float h1v = dh.y + __fdividef(num1, den1) + fu.y;
                    v0 = h0 * 0.8f + 0.2f * a0;
                    v1 = h1v * 0.8f + 0.2f * a1;
                    *(float2*)&Cf[(size_t)r * ldc + col] = make_float2(v0, v1);
                }
                float s0 = v0, s1 = v1, q0 = v0 * v0, q1 = v1 * v1;
#pragma unroll
                for (int d = 4; d < 32; d <<= 1) {
                    s0 += __shfl_xor_sync(0xFFFFFFFFu, s0, d);
                    s1 += __shfl_xor_sync(0xFFFFFFFFu, s1, d);
                    q0 += __shfl_xor_sync(0xFFFFFFFFu, q0, d);
                    q1 += __shfl_xor_sync(0xFFFFFFFFu, q1, d);
                }
                if (lid < 4) {
                    atomicAdd(&smst[colloc], s0);
                    atomicAdd(&smst[colloc + 1], s1);
                    atomicAdd(&smst[160 + colloc], q0);
                    atomicAdd(&smst[160 + colloc + 1], q1);
                }
            }
        }
    } else {
        const int* BA = z ? ba1p : ba0;
        const int* BG = z ? bg1p : bg0;
        const __half* Pg = z ? P1g : P0g;
        int rows[4];
        bool rok[4];
        const __half *pA0[4], *pA1[4];
        const float *pCu[4];
#pragma unroll
        for (int q = 0; q < 4; q++) {
            int i = q >> 1, half = q & 1;
            int r = mtile * BM + wm * 32 + i * 16 + half * 8 + (lid >> 2);
            rows[q] = r;
            rok[q] = r < M;
            if (MODE == 3 && rok[q]) {
                int2 bb = ((const int2*)BA)[r];
                int gg = BG[r];
                pA0[q] = Pg + (size_t)bb.x * 2400;
                pA1[q] = Pg + (size_t)bb.y * 2400;
                pCu[q] = CuB + (size_t)gg * 2400;
            }
        }
#pragma unroll
        for (int j = 0; j < 10; j++) {
            int colloc = wn * 80 + j * 8 + (lid & 3) * 2;
            int col = ntile * 160 + colloc;
            float2 bv = *(const float2*)(bp + col);
            float s0 = 0.f, s1 = 0.f, q0 = 0.f, q1 = 0.f;
#pragma unroll
            for (int q = 0; q < 4; q++) {
                if (!rok[q]) continue;
                int i = q >> 1, half = q & 1;
                float v0 = acc[i][j][half * 2 + 0] + bv.x;
                float v1 = acc[i][j][half * 2 + 1] + bv.y;
                if (MODE == 3) {
                    float2 a0v = __half22float2(*(const __half2*)(pA0[q] + col));
                    float2 a1v = __half22float2(*(const __half2*)(pA1[q] + col));
                    float2 cuv = *(const float2*)(pCu[q] + col);
                    v0 += a0v.x + a1v.x + cuv.x;
                    v1 += a0v.y + a1v.y + cuv.y;
                }
                if (MODE == 4) {
                    *(__half2*)(Ch + (size_t)rows[q] * ldc + col) = __floats2half2_rn(v0, v1);
                } else {
                    *(float2*)&Cf[(size_t)rows[q] * ldc + col] = make_float2(v0, v1);
                }
                if (STATS) {
                    s0 += v0; q0 += v0 * v0;
                    s1 += v1; q1 += v1 * v1;
                }
            }
            if (STATS) {
#pragma unroll
                for (int d = 4; d < 32; d <<= 1) {
                    s0 += __shfl_xor_sync(0xFFFFFFFFu, s0, d);
                    s1 += __shfl_xor_sync(0xFFFFFFFFu, s1, d);
                    q0 += __shfl_xor_sync(0xFFFFFFFFu, q0, d);
                    q1 += __shfl_xor_sync(0xFFFFFFFFu, q1, d);
                }
                if (lid < 4) {
                    atomicAdd(&smst[colloc], s0);
                    atomicAdd(&smst[colloc + 1], s1);
                    atomicAdd(&smst[160 + colloc], q0);
                    atomicAdd(&smst[160 + colloc + 1], q1);
                }
            }
        }
    }
    if (STATS) {
        __syncthreads();
        for (int i = tid; i < 160; i += 256) {
            atomicAdd(&st[ntile * 160 + i], smst[i]);
            atomicAdd(&st[4000 + ntile * 160 + i], smst[160 + i]);
        }
    }
}

// ---------------------------------------------------------------------------
// conversions
// ---------------------------------------------------------------------------
__global__ void conv_all_k(const float* __restrict__ h, const float* __restrict__ h2,
                           const float* __restrict__ e, const float* __restrict__ e2,
                           __half* __restrict__ th, __half* __restrict__ th2,
                           __half* __restrict__ te, __half* __restrict__ te2)
{
    int z = blockIdx.y;
    const float* A = (z == 0) ? h : (z == 1) ? h2 : (z == 2) ? e : e2;
    __half* T = (z == 0) ? th : (z == 1) ? th2 : (z == 2) ? te : te2;
    int n = (z < 2) ? NA_ * DD : NB_ * DD;
    int i4 = (blockIdx.x * blockDim.x + threadIdx.x) * 4;
    if (i4 >= n) return;
    float4 v = *(const float4*)(A + i4);
    __half2 a = __floats2half2_rn(v.x, v.y);
    __half2 b = __floats2half2_rn(v.z, v.w);
    *(uint2*)((unsigned short*)T + i4) = make_uint2(*(uint32_t*)&a, *(uint32_t*)&b);
}
__global__ void conv_a_k(const float* __restrict__ A, int n, __half* __restrict__ T)
{
    int i4 = (blockIdx.x * blockDim.x + threadIdx.x) * 4;
    if (i4 >= n) return;
    float4 v = *(const float4*)(A + i4);
    __half2 a = __floats2half2_rn(v.x, v.y);
    __half2 b = __floats2half2_rn(v.z, v.w);
    *(uint2*)((unsigned short*)T + i4) = make_uint2(*(uint32_t*)&a, *(uint32_t*)&b);
}

// weight transpose -> fp16 plane, packed groups
__global__ void conv_w_k(const float* __restrict__ Ws, __half* __restrict__ TW)
{
    static const int BASE[10]   = {0, 1920000, 2560000, 0, 0, 2560000, 4480000, 5120000, 2560000, 5760000};
    static const int ROWOFF[10] = {0, 0, 0, 800, 1600, 800, 0, 0, 1600, 0};
    __shared__ float t[32][33];
    int wi = blockIdx.z;
    const float* W = Ws + (size_t)wi * (DD * DD);
    __half* hi = TW + BASE[wi] + (size_t)ROWOFF[wi] * DD;
    int tx = threadIdx.x, ty = threadIdx.y;
    int kb = blockIdx.y * 32, nb = blockIdx.x * 32;
#pragma unroll
    for (int r = 0; r < 4; r++)
        t[ty + r * 8][tx] = W[(size_t)(kb + ty + r * 8) * DD + nb + tx];
    __syncthreads();
#pragma unroll
    for (int r = 0; r < 4; r++) {
        int nrow = nb + ty + r * 8;
        int kcol = kb + tx;
        hi[(size_t)nrow * DD + kcol] = __float2half_rn(t[tx][ty + r * 8]);
    }
}

// fused cross-gate + cast from fp16 P planes
__global__ void crossconv_k(const __half* __restrict__ P1, const __half* __restrict__ P2,
                            __half* __restrict__ T1, __half* __restrict__ T2)
{
    int i4 = (blockIdx.x * blockDim.x + threadIdx.x) * 4;
    if (i4 >= NA_ * DD) return;
    int r = i4 / DD, c = i4 % DD;
    size_t po = (size_t)r * 2400 + 800 + c;
    float2 d1a = __half22float2(*(const __half2*)(P1 + po));
    float2 d1b = __half22float2(*(const __half2*)(P1 + po + 2));
    float2 d2a = __half22float2(*(const __half2*)(P2 + po));
    float2 d2b = __half22float2(*(const __half2*)(P2 + po + 2));
    float4 t1v, t2v;
    float f;
    f = 1.f / (fabsf(d1a.x - d2a.x) + 1.f); t1v.x = f * d1a.x; t2v.x = f * d2a.x;
    f = 1.f / (fabsf(d1a.y - d2a.y) + 1.f); t1v.y = f * d1a.y; t2v.y = f * d2a.y;
    f = 1.f / (fabsf(d1b.x - d2b.x) + 1.f); t1v.z = f * d1b.x; t2v.z = f * d2b.x;
    f = 1.f / (fabsf(d1b.y - d2b.y) + 1.f); t1v.w = f * d1b.y; t2v.w = f * d2b.y;
    __half2 a = __floats2half2_rn(t1v.x, t1v.y);
    __half2 b = __floats2half2_rn(t1v.z, t1v.w);
    *(uint2*)((unsigned short*)T1 + i4) = make_uint2(*(uint32_t*)&a, *(uint32_t*)&b);
    a = __floats2half2_rn(t2v.x, t2v.y);
    b = __floats2half2_rn(t2v.z, t2v.w);
    *(uint2*)((unsigned short*)T2 + i4) = make_uint2(*(uint32_t*)&a, *(uint32_t*)&b);
}

// ---------------------------------------------------------------------------
__global__ void zero_k(float* p, int n) {
    int i = blockIdx.x * blockDim.x + threadIdx.x;
    if (i < n) p[i] = 0.f;
}
__global__ void count_all_k(const int* __restrict__ ag1, const int* __restrict__ bg1,
                            const int* __restrict__ ag2, const int* __restrict__ bg2,
                            float* __restrict__ cnts)
{
    int y = blockIdx.y;
    int i = blockIdx.x * blockDim.x + threadIdx.x;
    const int* s = (y == 0) ? ag1 : (y == 1) ? bg1 : (y == 2) ? ag2 : bg2;
    int n = (y & 1) ? NB_ : NA_;
    if (i < n) atomicAdd(&cnts[y * 256 + s[i]], 1.0f);
}
// bnprep over a PAIR of stat sets (blockIdx.y selects)
__global__ void bnprep2_k(const float* __restrict__ sum, const float* __restrict__ sumsq,
                          const float* __restrict__ gamma, const float* __restrict__ beta,
                          float Rf, float* __restrict__ scale, float* __restrict__ shift)
{
    int zz = blockIdx.y;
    int c = blockIdx.x * blockDim.x + threadIdx.x;
    if (c >= DD) return;
    float m = sum[zz * 800 + c] / Rf;
    float v = sumsq[zz * 800 + c] / Rf - m * m;
    float sc = gamma[c] * rsqrtf(v + 1e-5f);
    scale[zz * 800 + c] = sc;
    shift[zz * 800 + c] = beta[c] - m * sc;
}
__global__ void bnprep_k(const float* __restrict__ sum, const float* __restrict__ sumsq,
                         const float* __restrict__ gamma, const float* __restrict__ beta,
                         float Rf, float* __restrict__ scale, float* __restrict__ shift)
{
    int c = blockIdx.x * blockDim.x + threadIdx.x;
    if (c >= DD) return;
    float m = sum[c] / Rf;
    float v = sumsq[c] / Rf - m * m;
    float sc = gamma[c] * rsqrtf(v + 1e-5f);
    scale[c] = sc;
    shift[c] = beta[c] - m * sc;
}
__global__ void bnrelu_k(float* __restrict__ X, int n,
                         const float* __restrict__ scale, const float* __restrict__ shift)
{
    int i = blockIdx.x * blockDim.x + threadIdx.x;
    if (i >= n) return;
    int col = i % DD;
    X[i] = fmaxf(fmaf(X[i], scale[col], shift[col]), 0.f);
}
// fused BN-apply + relu + segment-sum (+ optional fp16 sigmoid emit), z-pair
__global__ void bnseg2_k(float* __restrict__ X0, float* __restrict__ X1, int M,
                         const int* __restrict__ seg0, const int* __restrict__ seg1,
                         const float* __restrict__ scale, const float* __restrict__ shift,
                         float* __restrict__ ssum0, float* __restrict__ ssum1,
                         __half* __restrict__ sg0, __half* __restrict__ sg1)
{
    extern __shared__ float sm[];
    int zz = blockIdx.z;
    float* X = zz ? X1 : X0;
    const int* seg = zz ? seg1 : seg0;
    float* ssum = zz ? ssum1 : ssum0;
    __half* sigout = zz ? sg1 : sg0;
    int c0 = blockIdx.x * 64;
    int cl = threadIdx.x & 63;
    int col = c0 + cl;
    int rg = threadIdx.x >> 6;
    for (int i = threadIdx.x; i < 16384; i += 256) sm[i] = 0.f;
    __syncthreads();
    bool ok = col < DD;
    float sc = ok ? scale[zz * 800 + col] : 0.f;
    float sh = ok ? shift[zz * 800 + col] : 0.f;
    int chunk = (M + gridDim.y - 1) / gridDim.y;
    int r0 = blockIdx.y * chunk;
    int r1 = min(r0 + chunk, M);
    for (int r = r0 + rg; r < r1; r += 4) {
        int g = seg[r];
        if (ok) {
            float y = fmaxf(fmaf(X[(size_t)r * DD + col], sc, sh), 0.f);
            X[(size_t)r * DD + col] = y;
            if (sigout) {
                float s = __fdividef(1.f, 1.f + __expf(-y));
                sigout[(size_t)r * DD + col] = __float2half_rn(s);
            }
            atomicAdd(&sm[g * 64 + cl], y);
        }
    }
    __syncthreads();
    for (int i = threadIdx.x; i < 16384; i += 256) {
        int g = i >> 6;
        int c = c0 + (i & 63);
        float v = sm[i];
        if (c < DD && v != 0.f) atomicAdd(&ssum[g * DD + c], v);
    }
}
__global__ void meanprep_k(const float* __restrict__ ssum, const float* __restrict__ cnts,
                           __half* __restrict__ mH, __half* __restrict__ mE)
{
    int i4 = (blockIdx.x * blockDim.x + threadIdx.x) * 4;
    if (i4 >= NG_ * DD) return;
    int g = i4 / DD;
    float cA1 = fmaxf(cnts[g], 1.f),       cA2 = fmaxf(cnts[512 + g], 1.f);
    float cB1 = fmaxf(cnts[256 + g], 1.f), cB2 = fmaxf(cnts[768 + g], 1.f);
    const float* sh1 = ssum + i4;
    const float* se1 = ssum + 204800 + i4;
    const float* sh2 = ssum + 409600 + i4;
    const float* se2 = ssum + 614400 + i4;
    float4 vh, ve;
    vh.x = sh1[0] / cA1 + sh2[0] / cA2;  ve.x = se1[0] / cB1 + se2[0] / cB2;
    vh.y = sh1[1] / cA1 + sh2[1] / cA2;  ve.y = se1[1] / cB1 + se2[1] / cB2;
    vh.z = sh1[2] / cA1 + sh2[2] / cA2;  ve.z = se1[2] / cB1 + se2[2] / cB2;
    vh.w = sh1[3] / cA1 + sh2[3] / cA2;  ve.w = se1[3] / cB1 + se2[3] / cB2;
    __half2 a = __floats2half2_rn(vh.x, vh.y);
    __half2 b = __floats2half2_rn(vh.z, vh.w);
    *(uint2*)((unsigned short*)mH + i4) = make_uint2(*(uint32_t*)&a, *(uint32_t*)&b);
    a = __floats2half2_rn(ve.x, ve.y);
    b = __floats2half2_rn(ve.z, ve.w);
    *(uint2*)((unsigned short*)mE + i4) = make_uint2(*(uint32_t*)&a, *(uint32_t*)&b);
}
// fused: un = P6+P7+Iu+ind-bias, plus direct column stats
__global__ void ucombstats_k(float* __restrict__ un, const float* __restrict__ P6,
                             const float* __restrict__ P7, const float* __restrict__ UFI,
                             const float* __restrict__ cnts, const float* __restrict__ bs,
                             float* __restrict__ sum, float* __restrict__ sumsq)
{
    __shared__ float ssm[8][32], sqm[8][32];
    int cl = threadIdx.x & 31, rg = threadIdx.x >> 5;
    int col = blockIdx.x * 32 + cl;
    bool ok = col < DD;
    float s = 0.f, q = 0.f;
    if (ok) {
        float b6 = bs[6 * 800 + col], b7 = bs[7 * 800 + col];
        for (int g = rg; g < NG_; g += 8) {
            float indA = (cnts[g] > 0.f ? 1.f : 0.f) + (cnts[512 + g] > 0.f ? 1.f : 0.f);
            float indB = (cnts[256 + g] > 0.f ? 1.f : 0.f) + (cnts[768 + g] > 0.f ? 1.f : 0.f);
            float v = P6[(size_t)g * DD + col] + P7[(size_t)g * DD + col]
                    + UFI[(size_t)g * 2400 + 1600 + col] + b6 * indA + b7 * indB;
            un[(size_t)g * DD + col] = v;
            s += v; q += v * v;
        }
    }
    ssm[rg][cl] = s; sqm[rg][cl] = q;
    __syncthreads();
    if (rg == 0 && ok) {
        float S = 0.f, Q = 0.f;
#pragma unroll
        for (int r = 0; r < 8; r++) { S += ssm[r][cl]; Q += sqm[r][cl]; }
        sum[col] = S; sumsq[col] = Q;
    }
}

// ---------------------------------------------------------------------------
extern "C" void kernel_launch(void* const* d_in, const int* in_sizes, int n_in,
                              void* d_out, int out_size)
{
    const float* h   = (const float*)d_in[0];
    const float* e   = (const float*)d_in[1];
    const float* h2  = (const float*)d_in[2];
    const float* e2  = (const float*)d_in[3];
    const float* u   = (const float*)d_in[4];
    const float* Ws  = (const float*)d_in[5];
    const float* bs  = (const float*)d_in[6];
    const float* gam = (const float*)d_in[7];
    const float* bet = (const float*)d_in[8];
    const int* ba1 = (const int*)d_in[9];
    const int* ab1 = (const int*)d_in[10];
    const int* ag1 = (const int*)d_in[11];
    const int* bg1 = (const int*)d_in[12];
    const int* ba2 = (const int*)d_in[13];
    const int* ab2 = (const int*)d_in[14];
    const int* ag2 = (const int*)d_in[15];
    const int* bg2 = (const int*)d_in[16];

    float* out = (float*)d_out;
    float* h1n = out;
    float* e1n = out + 16000000;
    float* h2n = out + 35200000;
    float* e2n = out + 51200000;
    float* un  = out + 70400000;

    float* sp = nullptr;
    cudaGetSymbolAddress((void**)&sp, g_scratch);

    __half* P1 = (__half*)(sp + O_P1);
    __half* P2 = (__half*)(sp + O_P2);
    float* SM  = sp + O_SMALL;
    float* UFI = SM;
    float* ssum  = SM + 614400;
    float* cnts  = SM + 1433600;
    float* bnsum = SM + 1434624;
    float* bnsq  = SM + 1438624;
    float* zbias = SM + 1442624;
    float* bnsc  = SM + 1443424;
    float* bnsh  = SM + 1447424;
    __half* mH = (__half*)(SM + 1456224);
    __half* mE = (__half*)(SM + 1661024);
    float* P6 = SM + 1865824;
    float* P7 = SM + 2070624;

    __half* tw   = (__half*)(sp + O_TW);
    __half* thp  = (__half*)(sp + O_THp);
    __half* th2p = (__half*)(sp + O_TH2p);
    __half* tep  = (__half*)(sp + O_TEp);
    __half* te2p = (__half*)(sp + O_TE2p);
    __half* tup  = (__half*)(sp + O_TUp);
    __half* sig1 = tep;    // reuse: e planes dead after e-GEMM
    __half* sig2 = te2p;

    __half* TADE = tw + 0;
    __half* TB1  = tw + 1920000;
    __half* TUFI = tw + 2560000;
    __half* TG   = tw + 4480000;
    __half* TH7  = tw + 5120000;
    __half* TW9  = tw + 5760000;

    const int NH = NA_ * DD, NU = NG_ * DD;

    cudaFuncSetAttribute(hgemm_k<0>, cudaFuncAttributeMaxDynamicSharedMemorySize, SMEM_TOT);
    cudaFuncSetAttribute(hgemm_k<3>, cudaFuncAttributeMaxDynamicSharedMemorySize, SMEM_TOT);
    cudaFuncSetAttribute(hgemm_k<4>, cudaFuncAttributeMaxDynamicSharedMemorySize, SMEM_TOT);
    cudaFuncSetAttribute(hgemm_k<5>, cudaFuncAttributeMaxDynamicSharedMemorySize, SMEM_TOT);
    cudaFuncSetAttribute(bnseg2_k, cudaFuncAttributeMaxDynamicSharedMemorySize, 65536);

    #define NIL6 nullptr, nullptr, nullptr, nullptr, nullptr, nullptr

    // conversions + setup
    conv_all_k<<<dim3(18750, 4), 256>>>(h, h2, e, e2, thp, th2p, tep, te2p);
    conv_w_k<<<dim3(25, 25, 10), dim3(32, 8)>>>(Ws, tw);
    zero_k<<<(829024 + 255) / 256, 256>>>(ssum, 829024);
    count_all_k<<<dim3(94, 4), 256>>>(ag1, bg1, ag2, bg2, cnts);
    conv_a_k<<<NU / 1024, 256>>>(u, NU, tup);

    // ADE projections -> fp16 P
    hgemm_k<4><<<dim3(15, 157, 2), 256, SMEM_TOT>>>(
        thp, th2p, TADE, TADE, bs, bs, 0, 3, 4,
        P1, P2, NA_, 2400,
        nullptr, nullptr, nullptr, nullptr, nullptr, nullptr, nullptr, nullptr, nullptr, NIL6);

    // UFI projections (fp32, small)
    hgemm_k<0><<<dim3(15, 2, 1), 256, SMEM_TOT>>>(
        tup, tup, TUFI, TUFI, bs, bs, 2, 5, 8,
        UFI, UFI, NG_, 2400,
        nullptr, nullptr, nullptr, nullptr, nullptr, nullptr, nullptr, nullptr, nullptr, NIL6);

    // cross-gate (needs only P) -> thp/th2p reused as t1/t2
    crossconv_k<<<NH / 1024, 256>>>(P1, P2, thp, th2p);

    // e-projection + fused bond update + BN stats
    hgemm_k<3><<<dim3(5, 188, 2), 256, SMEM_TOT>>>(
        tep, te2p, TB1, TB1, bs, bs, 1, 1, 1,
        e1n, e2n, NB_, 800,
        ba1, ba2, bg1, bg2, P1, P2, UFI,
        bnsum + 0, bnsum + 800, NIL6);

    // BN(e) prep + apply + segsum + sigmoid emit
    bnprep2_k<<<dim3(4, 2), 256>>>(bnsum + 0, bnsq + 0, gam, bet, (float)NB_, bnsc + 0, bnsh + 0);
    bnseg2_k<<<dim3(13, 12, 2), 256, 65536>>>(e1n, e2n, NB_, bg1, bg2,
                                              bnsc + 0, bnsh + 0,
                                              ssum + 204800, ssum + 614400, sig1, sig2);

    // fused atom update + cross mix + BN stats (MODE 5)
    hgemm_k<5><<<dim3(5, 157, 2), 256, SMEM_TOT>>>(
        th2p, thp, TW9, TW9, bs, bs, 9, 9, 9,
        h1n, h2n, NA_, 800,
        ba1, ba2, nullptr, nullptr, P1, P2, UFI,
        bnsum + 1600, bnsum + 2400,
        ab1, ab2, ag1, ag2, sig1, sig2);

    // BN(h) prep + apply + segsum
    bnprep2_k<<<dim3(4, 2), 256>>>(bnsum + 1600, bnsq + 1600, gam + 800, bet + 800,
                                   (float)NA_, bnsc + 1600, bnsh + 1600);
    bnseg2_k<<<dim3(13, 12, 2), 256, 65536>>>(h1n, h2n, NA_, ag1, ag2,
                                              bnsc + 1600, bnsh + 1600,
                                              ssum + 0, ssum + 409600, nullptr, nullptr);

    // global readout on means
    meanprep_k<<<NU / 1024, 256>>>(ssum, cnts, mH, mE);
    hgemm_k<0><<<dim3(5, 2, 2), 256, SMEM_TOT>>>(
        mH, mE, TG, TH7, zbias, zbias, 0, 0, 0,
        P6, P7, NG_, 800,
        nullptr, nullptr, nullptr, nullptr, nullptr, nullptr, nullptr, nullptr, nullptr, NIL6);

    // fused combine + stats, then BN(u) + relu
    ucombstats_k<<<25, 256>>>(un, P6, P7, UFI, cnts, bs, bnsum + 3200, bnsq + 3200);
    bnprep_k<<<4, 256>>>(bnsum + 3200, bnsq + 3200, gam + 1600, bet + 1600, (float)NG_, bnsc + 3200, bnsh + 3200);
    bnrelu_k<<<(NU + 255) / 256, 256>>>(un, NU, bnsc + 3200, bnsh + 3200);
    #undef NIL6
}

// round 13
// speedup vs baseline: 7.0672x; 1.0060x over previous
#include <cuda_runtime.h>
#include <cuda_fp16.h>
#include <cstdint>
#include <math.h>

#define DD 800
#define NA_ 20000
#define NB_ 24000
#define NG_ 256

// ---- HMMA GEMM tiling (pure fp16 single pass, 4-stage) ----
#define BM 128
#define BN 160
#define BK 32
#define SA_ 0
#define SB_ 10240
#define STAGE_B 23040
#define SMEM_TOT (4 * STAGE_B)   // 92160

// ---------------------------------------------------------------------------
// Scratch layout (float offsets)
// ---------------------------------------------------------------------------
static constexpr size_t O_P1 = 0;             // [20000][2400] fp16 A|D|E half1
static constexpr size_t O_P2 = 48000000;      // fp16 half2
static constexpr size_t O_SMALL = 96000000;
static constexpr size_t O_TW   = 98400000;
static constexpr size_t O_THp  = 104800000;
static constexpr size_t O_TH2p = 120800000;
static constexpr size_t O_TEp  = 136800000;   // e fp16 plane; later sig1
static constexpr size_t O_TE2p = 156000000;   // e2 fp16 plane; later sig2
static constexpr size_t O_TUp  = 175200000;
__device__ __align__(1024) float g_scratch[176000000];

// ---------------------------------------------------------------------------
__device__ __forceinline__ uint32_t smem_u32(const void* p) {
    uint32_t a;
    asm("{ .reg .u64 t; cvta.to.shared.u64 t, %1; cvt.u32.u64 %0, t; }" : "=r"(a) : "l"(p));
    return a;
}
__device__ __forceinline__ void cp16(uint32_t saddr, const void* gaddr) {
    asm volatile("cp.async.cg.shared.global [%0], [%1], 16;" :: "r"(saddr), "l"(gaddr));
}
__device__ __forceinline__ void cp_commit() {
    asm volatile("cp.async.commit_group;" ::: "memory");
}
__device__ __forceinline__ void cp_wait2() {
    asm volatile("cp.async.wait_group 2;" ::: "memory");
}
__device__ __forceinline__ void cp_wait0() {
    asm volatile("cp.async.wait_group 0;" ::: "memory");
}
__device__ __forceinline__ void ldsm4(uint32_t* r, uint32_t addr) {
    asm volatile("ldmatrix.sync.aligned.m8n8.x4.shared.b16 {%0,%1,%2,%3}, [%4];"
                 : "=r"(r[0]), "=r"(r[1]), "=r"(r[2]), "=r"(r[3]) : "r"(addr));
}
__device__ __forceinline__ void mma16816(float* c, const uint32_t* a, const uint32_t* b) {
    asm volatile(
        "mma.sync.aligned.m16n8k16.row.col.f32.f16.f16.f32 "
        "{%0,%1,%2,%3}, {%4,%5,%6,%7}, {%8,%9}, {%0,%1,%2,%3};"
        : "+f"(c[0]), "+f"(c[1]), "+f"(c[2]), "+f"(c[3])
        : "r"(a[0]), "r"(a[1]), "r"(a[2]), "r"(a[3]), "r"(b[0]), "r"(b[1]));
}

// ---------------------------------------------------------------------------
// fp16 HMMA GEMM, z-batched pair.
// MODE 0: store fp32 acc+bias
// MODE 3: C = acc+bias + Ah[i0]+Ah[i1]+Cu[g] (bond fuse; fp16 gathers), BN stats
// MODE 4: store fp16 acc+bias; extra mtiles >= nmt compute the UFI projection
// MODE 5: fused atom update + mix, BN stats
// ---------------------------------------------------------------------------
template<int MODE>
__global__ __launch_bounds__(256, 2)
void hgemm_k(const __half* __restrict__ Ah0, const __half* __restrict__ Ah1,
             const __half* __restrict__ B0_, const __half* __restrict__ B1_,
             const float* __restrict__ bias0, const float* __restrict__ bias1,
             int bm0, int bm1, int bm2,
             void* __restrict__ C0, void* __restrict__ C1, int M, int ldc,
             const int* __restrict__ ba0, const int* __restrict__ ba1p,
             const int* __restrict__ bg0, const int* __restrict__ bg1p,
             const __half* __restrict__ P0g, const __half* __restrict__ P1g,
             const __half* __restrict__ CuB,
             float* __restrict__ st0, float* __restrict__ st1,
             const int* __restrict__ ab0_, const int* __restrict__ ab1_,
             const int* __restrict__ ag0_, const int* __restrict__ ag1_,
             const __half* __restrict__ sg0, const __half* __restrict__ sg1,
             const __half* __restrict__ AhU, const __half* __restrict__ BU,
             __half* __restrict__ CU, int bmu0, int bmu1, int bmu2)
{
    constexpr bool STATS = (MODE == 3 || MODE == 5);
    extern __shared__ char smem[];
    uint32_t sb = smem_u32(smem);
    int tid = threadIdx.x;
    int lid = tid & 31, wid = tid >> 5;
    int wm = wid & 3, wn = wid >> 2;
    int ntile = blockIdx.x, mtile = blockIdx.y, z = blockIdx.z;

    // UFI fold (MODE 4 only): last two mtiles compute u-projection (z=0 only)
    int uf = 0, mt = mtile, Mloc = M;
    if (MODE == 4 && AhU != nullptr) {
        int nmt = (M + BM - 1) / BM;
        if (mtile >= nmt) {
            if (z) return;
            uf = 1;
            mt = mtile - nmt;
            Mloc = NG_;
        }
    }

    const __half* Ahp = uf ? AhU : (z ? Ah1 : Ah0);
    const __half* Bp  = uf ? BU  : (z ? B1_ : B0_);
    const float* bias = z ? bias1 : bias0;

    int arow[2], acol[2];
    uint32_t asoff[2];
#pragma unroll
    for (int t = 0; t < 2; t++) {
        int q = tid + t * 256;
        int r = q >> 2, c = q & 3;
        arow[t] = min(mt * BM + r, Mloc - 1);
        acol[t] = c * 8;
        asoff[t] = r * 80 + c * 16;
    }
    int brow[3], bcol[3];
    uint32_t bsoff[3];
#pragma unroll
    for (int t = 0; t < 3; t++) {
        int q = tid + t * 256;
        int r = q >> 2, c = q & 3;
        brow[t] = ntile * BN + r;
        bcol[t] = c * 8;
        bsoff[t] = r * 80 + c * 16;
    }
    bool b3 = (tid < 128);

    auto load_stage = [&](int s, int kc) {
        uint32_t st = sb + s * STAGE_B;
        int k0 = kc * BK;
#pragma unroll
        for (int t = 0; t < 2; t++)
            cp16(st + SA_ + asoff[t], Ahp + (size_t)arow[t] * DD + k0 + acol[t]);
#pragma unroll
        for (int t = 0; t < 2; t++)
            cp16(st + SB_ + bsoff[t], Bp + (size_t)brow[t] * DD + k0 + bcol[t]);
        if (b3)
            cp16(st + SB_ + bsoff[2], Bp + (size_t)brow[2] * DD + k0 + bcol[2]);
    };

    float acc[2][10][4];
#pragma unroll
    for (int i = 0; i < 2; i++)
#pragma unroll
        for (int j = 0; j < 10; j++)
#pragma unroll
            for (int k = 0; k < 4; k++) acc[i][j][k] = 0.f;

    uint32_t aswz = (lid & 15) * 80 + (lid >> 4) * 16;
    uint32_t bswz = ((lid & 7) + ((lid & 16) ? 8 : 0)) * 80 + ((lid >> 3) & 1) * 16;
    uint32_t a_base = (wm * 32) * 80 + aswz;
    uint32_t b_base = (wn * 80) * 80 + bswz;

    load_stage(0, 0); cp_commit();
    load_stage(1, 1); cp_commit();
    load_stage(2, 2); cp_commit();

#pragma unroll 1
    for (int kc = 0; kc < 25; kc++) {
        int s = kc & 3;
        cp_wait2();
        __syncthreads();
        uint32_t st = sb + s * STAGE_B;
#pragma unroll
        for (int k16 = 0; k16 < 2; k16++) {
            uint32_t aH[2][4];
            ldsm4(aH[0], st + SA_ + a_base + k16 * 32);
            ldsm4(aH[1], st + SA_ + a_base + 16 * 80 + k16 * 32);
#pragma unroll
            for (int g = 0; g < 5; g++) {
                uint32_t bH[4];
                ldsm4(bH, st + SB_ + b_base + g * 16 * 80 + k16 * 32);
                mma16816(acc[0][2 * g],     aH[0], bH);
                mma16816(acc[0][2 * g + 1], aH[0], bH + 2);
                mma16816(acc[1][2 * g],     aH[1], bH);
                mma16816(acc[1][2 * g + 1], aH[1], bH + 2);
            }
        }
        if (kc + 3 < 25) load_stage((kc + 3) & 3, kc + 3);
        cp_commit();
    }

    // ---------------- epilogue ----------------
    cp_wait0();
    __syncthreads();
    float* smst = (float*)smem;
    if (STATS) {
        for (int i = tid; i < 320; i += 256) smst[i] = 0.f;
        __syncthreads();
    }

    int bseg = ntile / 5;
    int bsel = uf ? (bseg == 0 ? bmu0 : bseg == 1 ? bmu1 : bmu2)
                  : (bseg == 0 ? bm0 : bseg == 1 ? bm1 : bm2);
    const float* bp = bias + bsel * 800 - bseg * 800;

    float* Cf  = (float*)(z ? C1 : C0);
    __half* Ch = uf ? CU : (__half*)(z ? C1 : C0);
    float* st = z ? st1 : st0;

    if (MODE == 5) {
        const int* AB  = z ? ab1_ : ab0_;
        const int* BAm = z ? ba1p : ba0;
        const int* AG  = z ? ag1_ : ag0_;
        const __half* SG = z ? sg1 : sg0;
        const __half* Pm = z ? P1g : P0g;
#pragma unroll
        for (int q = 0; q < 4; q++) {
            const int iq = q >> 1, half = q & 1;
            int r = mt * BM + wm * 32 + iq * 16 + half * 8 + (lid >> 2);
            bool ok = r < Mloc;
            int b0 = 0, b1 = 0, b2 = 0, b3i = 0, o0 = 0, o1 = 0, o2 = 0, o3 = 0, gg = 0;
            if (ok) {
                int4 bb = ((const int4*)AB)[r];
                b0 = bb.x; b1 = bb.y; b2 = bb.z; b3i = bb.w;
                int2 p;
                p = ((const int2*)BAm)[b0];  o0 = (p.x != r) ? p.x : p.y;
                p = ((const int2*)BAm)[b1];  o1 = (p.x != r) ? p.x : p.y;
                p = ((const int2*)BAm)[b2];  o2 = (p.x != r) ? p.x : p.y;
                p = ((const int2*)BAm)[b3i]; o3 = (p.x != r) ? p.x : p.y;
                gg = AG[r];
            }
#pragma unroll
            for (int j = 0; j < 10; j++) {
                int colloc = wn * 80 + j * 8 + (lid & 3) * 2;
                int col = ntile * 160 + colloc;
                float v0 = 0.f, v1 = 0.f;
                if (ok) {
                    float2 bv = *(const float2*)(bp + col);
                    float a0 = acc[iq][j][half * 2 + 0] + bv.x;
                    float a1 = acc[iq][j][half * 2 + 1] + bv.y;
                    float2 w0 = __half22float2(*(const __half2*)(SG + (size_t)b0 * DD + col));
                    float2 w1 = __half22float2(*(const __half2*)(SG + (size_t)b1 * DD + col));
                    float2 w2 = __half22float2(*(const __half2*)(SG + (size_t)b2 * DD + col));
                    float2 w3 = __half22float2(*(const __half2*)(SG + (size_t)b3i * DD + col));
                    float2 e0 = __half22float2(*(const __half2*)(Pm + (size_t)o0 * 2400 + 1600 + col));
                    float2 e1v = __half22float2(*(const __half2*)(Pm + (size_t)o1 * 2400 + 1600 + col));
                    float2 e2v = __half22float2(*(const __half2*)(Pm + (size_t)o2 * 2400 + 1600 + col));
                    float2 e3v = __half22float2(*(const __half2*)(Pm + (size_t)o3 * 2400 + 1600 + col));
                    float2 dh = __half22float2(*(const __half2*)(Pm + (size_t)r * 2400 + 800 + col));
                    float2 fu = __half22float2(*(const __half2*)(CuB + (size_t)gg * 2400 + 800 + col));
                    float num0 = w0.x * e0.x + w1.x * e1v.x + w2.x * e2v.x + w3.x * e3v.x;
                    float den0 = w0.x + w1.x + w2.x + w3.x + 1e-6f;
                    float num1 = w0.y * e0.y + w1.y * e1v.y + w2.y * e2v.y + w3.y * e3v.y;
                    float den1 = w0.y + w1.y + w2.y + w3.y + 1e-6f;
                    float h0 = dh.x + __fdividef(num0, den0) + fu.x;
                    float h1v = dh.y + __fdividef(num1, den1) + fu.y;
                    v0 = h0 * 0.8f + 0.2f * a0;
                    v1 = h1v * 0.8f + 0.2f * a1;
                    *(float2*)&Cf[(size_t)r * ldc + col] = make_float2(v0, v1);
                }
                float s0 = v0, s1 = v1, q0 = v0 * v0, q1 = v1 * v1;
#pragma unroll
                for (int d = 4; d < 32; d <<= 1) {
                    s0 += __shfl_xor_sync(0xFFFFFFFFu, s0, d);
                    s1 += __shfl_xor_sync(0xFFFFFFFFu, s1, d);
                    q0 += __shfl_xor_sync(0xFFFFFFFFu, q0, d);
                    q1 += __shfl_xor_sync(0xFFFFFFFFu, q1, d);
                }
                if (lid < 4) {
                    atomicAdd(&smst[colloc], s0);
                    atomicAdd(&smst[colloc + 1], s1);
                    atomicAdd(&smst[160 + colloc], q0);
                    atomicAdd(&smst[160 + colloc + 1], q1);
                }
            }
        }
    } else {
        const int* BA = z ? ba1p : ba0;
        const int* BG = z ? bg1p : bg0;
        const __half* Pg = z ? P1g : P0g;
        int rows[4];
        bool rok[4];
        const __half *pA0[4], *pA1[4], *pCu[4];
#pragma unroll
        for (int q = 0; q < 4; q++) {
            int i = q >> 1, half = q & 1;
            int r = mt * BM + wm * 32 + i * 16 + half * 8 + (lid >> 2);
            rows[q] = r;
            rok[q] = r < Mloc;
            if (MODE == 3 && rok[q]) {
                int2 bb = ((const int2*)BA)[r];
                int gg = BG[r];
                pA0[q] = Pg + (size_t)bb.x * 2400;
                pA1[q] = Pg + (size_t)bb.y * 2400;
                pCu[q] = CuB + (size_t)gg * 2400;
            }
        }
#pragma unroll
        for (int j = 0; j < 10; j++) {
            int colloc = wn * 80 + j * 8 + (lid & 3) * 2;
            int col = ntile * 160 + colloc;
            float2 bv = *(const float2*)(bp + col);
            float s0 = 0.f, s1 = 0.f, q0 = 0.f, q1 = 0.f;
#pragma unroll
            for (int q = 0; q < 4; q++) {
                if (!rok[q]) continue;
                int i = q >> 1, half = q & 1;
                float v0 = acc[i][j][half * 2 + 0] + bv.x;
                float v1 = acc[i][j][half * 2 + 1] + bv.y;
                if (MODE == 3) {
                    float2 a0v = __half22float2(*(const __half2*)(pA0[q] + col));
                    float2 a1v = __half22float2(*(const __half2*)(pA1[q] + col));
                    float2 cuv = __half22float2(*(const __half2*)(pCu[q] + col));
                    v0 += a0v.x + a1v.x + cuv.x;
                    v1 += a0v.y + a1v.y + cuv.y;
                }
                if (MODE == 4) {
                    *(__half2*)(Ch + (size_t)rows[q] * ldc + col) = __floats2half2_rn(v0, v1);
                } else {
                    *(float2*)&Cf[(size_t)rows[q] * ldc + col] = make_float2(v0, v1);
                }
                if (STATS) {
                    s0 += v0; q0 += v0 * v0;
                    s1 += v1; q1 += v1 * v1;
                }
            }
            if (STATS) {
#pragma unroll
                for (int d = 4; d < 32; d <<= 1) {
                    s0 += __shfl_xor_sync(0xFFFFFFFFu, s0, d);
                    s1 += __shfl_xor_sync(0xFFFFFFFFu, s1, d);
                    q0 += __shfl_xor_sync(0xFFFFFFFFu, q0, d);
                    q1 += __shfl_xor_sync(0xFFFFFFFFu, q1, d);
                }
                if (lid < 4) {
                    atomicAdd(&smst[colloc], s0);
                    atomicAdd(&smst[colloc + 1], s1);
                    atomicAdd(&smst[160 + colloc], q0);
                    atomicAdd(&smst[160 + colloc + 1], q1);
                }
            }
        }
    }
    if (STATS) {
        __syncthreads();
        for (int i = tid; i < 160; i += 256) {
            atomicAdd(&st[ntile * 160 + i], smst[i]);
            atomicAdd(&st[4000 + ntile * 160 + i], smst[160 + i]);
        }
    }
}

// ---------------------------------------------------------------------------
// conversions
// ---------------------------------------------------------------------------
__global__ void conv_all_k(const float* __restrict__ h, const float* __restrict__ h2,
                           const float* __restrict__ e, const float* __restrict__ e2,
                           __half* __restrict__ th, __half* __restrict__ th2,
                           __half* __restrict__ te, __half* __restrict__ te2)
{
    int z = blockIdx.y;
    const float* A = (z == 0) ? h : (z == 1) ? h2 : (z == 2) ? e : e2;
    __half* T = (z == 0) ? th : (z == 1) ? th2 : (z == 2) ? te : te2;
    int n = (z < 2) ? NA_ * DD : NB_ * DD;
    int i4 = (blockIdx.x * blockDim.x + threadIdx.x) * 4;
    if (i4 >= n) return;
    float4 v = *(const float4*)(A + i4);
    __half2 a = __floats2half2_rn(v.x, v.y);
    __half2 b = __floats2half2_rn(v.z, v.w);
    *(uint2*)((unsigned short*)T + i4) = make_uint2(*(uint32_t*)&a, *(uint32_t*)&b);
}
// counts (y=0..3) + u conversion (y=4). grid.x must cover NG_*DD/4/256 = 200.
__global__ void setup_k(const int* __restrict__ ag1, const int* __restrict__ bg1,
                        const int* __restrict__ ag2, const int* __restrict__ bg2,
                        float* __restrict__ cnts,
                        const float* __restrict__ u, __half* __restrict__ tup)
{
    int y = blockIdx.y;
    int i = blockIdx.x * blockDim.x + threadIdx.x;
    if (y < 4) {
        const int* s = (y == 0) ? ag1 : (y == 1) ? bg1 : (y == 2) ? ag2 : bg2;
        int n = (y & 1) ? NB_ : NA_;
        if (i < n) atomicAdd(&cnts[y * 256 + s[i]], 1.0f);
    } else {
        int i4 = i * 4;
        if (i4 >= NG_ * DD) return;
        float4 v = *(const float4*)(u + i4);
        __half2 a = __floats2half2_rn(v.x, v.y);
        __half2 b = __floats2half2_rn(v.z, v.w);
        *(uint2*)((unsigned short*)tup + i4) = make_uint2(*(uint32_t*)&a, *(uint32_t*)&b);
    }
}

// weight transpose -> fp16 plane, packed groups
__global__ void conv_w_k(const float* __restrict__ Ws, __half* __restrict__ TW)
{
    static const int BASE[10]   = {0, 1920000, 2560000, 0, 0, 2560000, 4480000, 5120000, 2560000, 5760000};
    static const int ROWOFF[10] = {0, 0, 0, 800, 1600, 800, 0, 0, 1600, 0};
    __shared__ float t[32][33];
    int wi = blockIdx.z;
    const float* W = Ws + (size_t)wi * (DD * DD);
    __half* hi = TW + BASE[wi] + (size_t)ROWOFF[wi] * DD;
    int tx = threadIdx.x, ty = threadIdx.y;
    int kb = blockIdx.y * 32, nb = blockIdx.x * 32;
#pragma unroll
    for (int r = 0; r < 4; r++)
        t[ty + r * 8][tx] = W[(size_t)(kb + ty + r * 8) * DD + nb + tx];
    __syncthreads();
#pragma unroll
    for (int r = 0; r < 4; r++) {
        int nrow = nb + ty + r * 8;
        int kcol = kb + tx;
        hi[(size_t)nrow * DD + kcol] = __float2half_rn(t[tx][ty + r * 8]);
    }
}

// fused cross-gate + cast from fp16 P planes
__global__ void crossconv_k(const __half* __restrict__ P1, const __half* __restrict__ P2,
                            __half* __restrict__ T1, __half* __restrict__ T2)
{
    int i4 = (blockIdx.x * blockDim.x + threadIdx.x) * 4;
    if (i4 >= NA_ * DD) return;
    int r = i4 / DD, c = i4 % DD;
    size_t po = (size_t)r * 2400 + 800 + c;
    float2 d1a = __half22float2(*(const __half2*)(P1 + po));
    float2 d1b = __half22float2(*(const __half2*)(P1 + po + 2));
    float2 d2a = __half22float2(*(const __half2*)(P2 + po));
    float2 d2b = __half22float2(*(const __half2*)(P2 + po + 2));
    float4 t1v, t2v;
    float f;
    f = 1.f / (fabsf(d1a.x - d2a.x) + 1.f); t1v.x = f * d1a.x; t2v.x = f * d2a.x;
    f = 1.f / (fabsf(d1a.y - d2a.y) + 1.f); t1v.y = f * d1a.y; t2v.y = f * d2a.y;
    f = 1.f / (fabsf(d1b.x - d2b.x) + 1.f); t1v.z = f * d1b.x; t2v.z = f * d2b.x;
    f = 1.f / (fabsf(d1b.y - d2b.y) + 1.f); t1v.w = f * d1b.y; t2v.w = f * d2b.y;
    __half2 a = __floats2half2_rn(t1v.x, t1v.y);
    __half2 b = __floats2half2_rn(t1v.z, t1v.w);
    *(uint2*)((unsigned short*)T1 + i4) = make_uint2(*(uint32_t*)&a, *(uint32_t*)&b);
    a = __floats2half2_rn(t2v.x, t2v.y);
    b = __floats2half2_rn(t2v.z, t2v.w);
    *(uint2*)((unsigned short*)T2 + i4) = make_uint2(*(uint32_t*)&a, *(uint32_t*)&b);
}

// ---------------------------------------------------------------------------
__global__ void zero_k(float* p, int n) {
    int i = blockIdx.x * blockDim.x + threadIdx.x;
    if (i < n) p[i] = 0.f;
}
__global__ void bnprep2_k(const float* __restrict__ sum, const float* __restrict__ sumsq,
                          const float* __restrict__ gamma, const float* __restrict__ beta,
                          float Rf, float* __restrict__ scale, float* __restrict__ shift)
{
    int zz = blockIdx.y;
    int c = blockIdx.x * blockDim.x + threadIdx.x;
    if (c >= DD) return;
    float m = sum[zz * 800 + c] / Rf;
    float v = sumsq[zz * 800 + c] / Rf - m * m;
    float sc = gamma[c] * rsqrtf(v + 1e-5f);
    scale[zz * 800 + c] = sc;
    shift[zz * 800 + c] = beta[c] - m * sc;
}
__global__ void bnprep_k(const float* __restrict__ sum, const float* __restrict__ sumsq,
                         const float* __restrict__ gamma, const float* __restrict__ beta,
                         float Rf, float* __restrict__ scale, float* __restrict__ shift)
{
    int c = blockIdx.x * blockDim.x + threadIdx.x;
    if (c >= DD) return;
    float m = sum[c] / Rf;
    float v = sumsq[c] / Rf - m * m;
    float sc = gamma[c] * rsqrtf(v + 1e-5f);
    scale[c] = sc;
    shift[c] = beta[c] - m * sc;
}
__global__ void bnrelu_k(float* __restrict__ X, int n,
                         const float* __restrict__ scale, const float* __restrict__ shift)
{
    int i = blockIdx.x * blockDim.x + threadIdx.x;
    if (i >= n) return;
    int col = i % DD;
    X[i] = fmaxf(fmaf(X[i], scale[col], shift[col]), 0.f);
}
// fused BN-apply + relu + segment-sum (+ optional fp16 sigmoid emit), z-pair
__global__ void bnseg2_k(float* __restrict__ X0, float* __restrict__ X1, int M,
                         const int* __restrict__ seg0, const int* __restrict__ seg1,
                         const float* __restrict__ scale, const float* __restrict__ shift,
                         float* __restrict__ ssum0, float* __restrict__ ssum1,
                         __half* __restrict__ sg0, __half* __restrict__ sg1)
{
    extern __shared__ float sm[];
    int zz = blockIdx.z;
    float* X = zz ? X1 : X0;
    const int* seg = zz ? seg1 : seg0;
    float* ssum = zz ? ssum1 : ssum0;
    __half* sigout = zz ? sg1 : sg0;
    int c0 = blockIdx.x * 64;
    int cl = threadIdx.x & 63;
    int col = c0 + cl;
    int rg = threadIdx.x >> 6;
    for (int i = threadIdx.x; i < 16384; i += 256) sm[i] = 0.f;
    __syncthreads();
    bool ok = col < DD;
    float sc = ok ? scale[zz * 800 + col] : 0.f;
    float sh = ok ? shift[zz * 800 + col] : 0.f;
    int chunk = (M + gridDim.y - 1) / gridDim.y;
    int r0 = blockIdx.y * chunk;
    int r1 = min(r0 + chunk, M);
    for (int r = r0 + rg; r < r1; r += 4) {
        int g = seg[r];
        if (ok) {
            float y = fmaxf(fmaf(X[(size_t)r * DD + col], sc, sh), 0.f);
            X[(size_t)r * DD + col] = y;
            if (sigout) {
                float s = __fdividef(1.f, 1.f + __expf(-y));
                sigout[(size_t)r * DD + col] = __float2half_rn(s);
            }
            atomicAdd(&sm[g * 64 + cl], y);
        }
    }
    __syncthreads();
    for (int i = threadIdx.x; i < 16384; i += 256) {
        int g = i >> 6;
        int c = c0 + (i & 63);
        float v = sm[i];
        if (c < DD && v != 0.f) atomicAdd(&ssum[g * DD + c], v);
    }
}
__global__ void meanprep_k(const float* __restrict__ ssum, const float* __restrict__ cnts,
                           __half* __restrict__ mH, __half* __restrict__ mE)
{
    int i4 = (blockIdx.x * blockDim.x + threadIdx.x) * 4;
    if (i4 >= NG_ * DD) return;
    int g = i4 / DD;
    float cA1 = fmaxf(cnts[g], 1.f),       cA2 = fmaxf(cnts[512 + g], 1.f);
    float cB1 = fmaxf(cnts[256 + g], 1.f), cB2 = fmaxf(cnts[768 + g], 1.f);
    const float* sh1 = ssum + i4;
    const float* se1 = ssum + 204800 + i4;
    const float* sh2 = ssum + 409600 + i4;
    const float* se2 = ssum + 614400 + i4;
    float4 vh, ve;
    vh.x = sh1[0] / cA1 + sh2[0] / cA2;  ve.x = se1[0] / cB1 + se2[0] / cB2;
    vh.y = sh1[1] / cA1 + sh2[1] / cA2;  ve.y = se1[1] / cB1 + se2[1] / cB2;
    vh.z = sh1[2] / cA1 + sh2[2] / cA2;  ve.z = se1[2] / cB1 + se2[2] / cB2;
    vh.w = sh1[3] / cA1 + sh2[3] / cA2;  ve.w = se1[3] / cB1 + se2[3] / cB2;
    __half2 a = __floats2half2_rn(vh.x, vh.y);
    __half2 b = __floats2half2_rn(vh.z, vh.w);
    *(uint2*)((unsigned short*)mH + i4) = make_uint2(*(uint32_t*)&a, *(uint32_t*)&b);
    a = __floats2half2_rn(ve.x, ve.y);
    b = __floats2half2_rn(ve.z, ve.w);
    *(uint2*)((unsigned short*)mE + i4) = make_uint2(*(uint32_t*)&a, *(uint32_t*)&b);
}
// fused: un = P6+P7+Iu+ind-bias, plus direct column stats
__global__ void ucombstats_k(float* __restrict__ un, const float* __restrict__ P6,
                             const float* __restrict__ P7, const __half* __restrict__ UFIh,
                             const float* __restrict__ cnts, const float* __restrict__ bs,
                             float* __restrict__ sum, float* __restrict__ sumsq)
{
    __shared__ float ssm[8][32], sqm[8][32];
    int cl = threadIdx.x & 31, rg = threadIdx.x >> 5;
    int col = blockIdx.x * 32 + cl;
    bool ok = col < DD;
    float s = 0.f, q = 0.f;
    if (ok) {
        float b6 = bs[6 * 800 + col], b7 = bs[7 * 800 + col];
        for (int g = rg; g < NG_; g += 8) {
            float indA = (cnts[g] > 0.f ? 1.f : 0.f) + (cnts[512 + g] > 0.f ? 1.f : 0.f);
            float indB = (cnts[256 + g] > 0.f ? 1.f : 0.f) + (cnts[768 + g] > 0.f ? 1.f : 0.f);
            float v = P6[(size_t)g * DD + col] + P7[(size_t)g * DD + col]
                    + __half2float(UFIh[(size_t)g * 2400 + 1600 + col])
                    + b6 * indA + b7 * indB;
            un[(size_t)g * DD + col] = v;
            s += v; q += v * v;
        }
    }
    ssm[rg][cl] = s; sqm[rg][cl] = q;
    __syncthreads();
    if (rg == 0 && ok) {
        float S = 0.f, Q = 0.f;
#pragma unroll
        for (int r = 0; r < 8; r++) { S += ssm[r][cl]; Q += sqm[r][cl]; }
        sum[col] = S; sumsq[col] = Q;
    }
}

// ---------------------------------------------------------------------------
extern "C" void kernel_launch(void* const* d_in, const int* in_sizes, int n_in,
                              void* d_out, int out_size)
{
    const float* h   = (const float*)d_in[0];
    const float* e   = (const float*)d_in[1];
    const float* h2  = (const float*)d_in[2];
    const float* e2  = (const float*)d_in[3];
    const float* u   = (const float*)d_in[4];
    const float* Ws  = (const float*)d_in[5];
    const float* bs  = (const float*)d_in[6];
    const float* gam = (const float*)d_in[7];
    const float* bet = (const float*)d_in[8];
    const int* ba1 = (const int*)d_in[9];
    const int* ab1 = (const int*)d_in[10];
    const int* ag1 = (const int*)d_in[11];
    const int* bg1 = (const int*)d_in[12];
    const int* ba2 = (const int*)d_in[13];
    const int* ab2 = (const int*)d_in[14];
    const int* ag2 = (const int*)d_in[15];
    const int* bg2 = (const int*)d_in[16];

    float* out = (float*)d_out;
    float* h1n = out;
    float* e1n = out + 16000000;
    float* h2n = out + 35200000;
    float* e2n = out + 51200000;
    float* un  = out + 70400000;

    float* sp = nullptr;
    cudaGetSymbolAddress((void**)&sp, g_scratch);

    __half* P1 = (__half*)(sp + O_P1);
    __half* P2 = (__half*)(sp + O_P2);
    float* SM  = sp + O_SMALL;
    __half* UFIh = (__half*)SM;               // [256][2400] fp16
    float* ssum  = SM + 614400;
    float* cnts  = SM + 1433600;
    float* bnsum = SM + 1434624;
    float* bnsq  = SM + 1438624;
    float* zbias = SM + 1442624;
    float* bnsc  = SM + 1443424;
    float* bnsh  = SM + 1447424;
    __half* mH = (__half*)(SM + 1456224);
    __half* mE = (__half*)(SM + 1661024);
    float* P6 = SM + 1865824;
    float* P7 = SM + 2070624;

    __half* tw   = (__half*)(sp + O_TW);
    __half* thp  = (__half*)(sp + O_THp);
    __half* th2p = (__half*)(sp + O_TH2p);
    __half* tep  = (__half*)(sp + O_TEp);
    __half* te2p = (__half*)(sp + O_TE2p);
    __half* tup  = (__half*)(sp + O_TUp);
    __half* sig1 = tep;    // reuse: e planes dead after e-GEMM
    __half* sig2 = te2p;

    __half* TADE = tw + 0;
    __half* TB1  = tw + 1920000;
    __half* TUFI = tw + 2560000;
    __half* TG   = tw + 4480000;
    __half* TH7  = tw + 5120000;
    __half* TW9  = tw + 5760000;

    const int NH = NA_ * DD, NU = NG_ * DD;

    cudaFuncSetAttribute(hgemm_k<0>, cudaFuncAttributeMaxDynamicSharedMemorySize, SMEM_TOT);
    cudaFuncSetAttribute(hgemm_k<3>, cudaFuncAttributeMaxDynamicSharedMemorySize, SMEM_TOT);
    cudaFuncSetAttribute(hgemm_k<4>, cudaFuncAttributeMaxDynamicSharedMemorySize, SMEM_TOT);
    cudaFuncSetAttribute(hgemm_k<5>, cudaFuncAttributeMaxDynamicSharedMemorySize, SMEM_TOT);
    cudaFuncSetAttribute(bnseg2_k, cudaFuncAttributeMaxDynamicSharedMemorySize, 65536);

    #define NIL6 nullptr, nullptr, nullptr, nullptr, nullptr, nullptr
    #define NILU nullptr, nullptr, nullptr, 0, 0, 0

    // setup + conversions  (setup_k grid.x=200 covers u conversion: 51200 threads)
    zero_k<<<(829024 + 255) / 256, 256>>>(ssum, 829024);
    conv_all_k<<<dim3(18750, 4), 256>>>(h, h2, e, e2, thp, th2p, tep, te2p);
    setup_k<<<dim3(200, 5), 256>>>(ag1, bg1, ag2, bg2, cnts, u, tup);
    conv_w_k<<<dim3(25, 25, 10), dim3(32, 8)>>>(Ws, tw);

    // ADE projections -> fp16 P, with UFI fold (mtiles 157,158)
    hgemm_k<4><<<dim3(15, 159, 2), 256, SMEM_TOT>>>(
        thp, th2p, TADE, TADE, bs, bs, 0, 3, 4,
        P1, P2, NA_, 2400,
        nullptr, nullptr, nullptr, nullptr, nullptr, nullptr, nullptr, nullptr, nullptr, NIL6,
        tup, TUFI, UFIh, 2, 5, 8);

    // cross-gate (needs only P) -> thp/th2p reused as t1/t2
    crossconv_k<<<NH / 1024, 256>>>(P1, P2, thp, th2p);

    // e-projection + fused bond update + BN stats
    hgemm_k<3><<<dim3(5, 188, 2), 256, SMEM_TOT>>>(
        tep, te2p, TB1, TB1, bs, bs, 1, 1, 1,
        e1n, e2n, NB_, 800,
        ba1, ba2, bg1, bg2, P1, P2, UFIh,
        bnsum + 0, bnsum + 800, NIL6, NILU);

    // BN(e) prep + apply + segsum + sigmoid emit
    bnprep2_k<<<dim3(4, 2), 256>>>(bnsum + 0, bnsq + 0, gam, bet, (float)NB_, bnsc + 0, bnsh + 0);
    bnseg2_k<<<dim3(13, 12, 2), 256, 65536>>>(e1n, e2n, NB_, bg1, bg2,
                                              bnsc + 0, bnsh + 0,
                                              ssum + 204800, ssum + 614400, sig1, sig2);

    // fused atom update + cross mix + BN stats (MODE 5)
    hgemm_k<5><<<dim3(5, 157, 2), 256, SMEM_TOT>>>(
        th2p, thp, TW9, TW9, bs, bs, 9, 9, 9,
        h1n, h2n, NA_, 800,
        ba1, ba2, nullptr, nullptr, P1, P2, UFIh,
        bnsum + 1600, bnsum + 2400,
        ab1, ab2, ag1, ag2, sig1, sig2, NILU);

    // BN(h) prep + apply + segsum
    bnprep2_k<<<dim3(4, 2), 256>>>(bnsum + 1600, bnsq + 1600, gam + 800, bet + 800,
                                   (float)NA_, bnsc + 1600, bnsh + 1600);
    bnseg2_k<<<dim3(13, 12, 2), 256, 65536>>>(h1n, h2n, NA_, ag1, ag2,
                                              bnsc + 1600, bnsh + 1600,
                                              ssum + 0, ssum + 409600, nullptr, nullptr);

    // global readout on means
    meanprep_k<<<NU / 1024, 256>>>(ssum, cnts, mH, mE);
    hgemm_k<0><<<dim3(5, 2, 2), 256, SMEM_TOT>>>(
        mH, mE, TG, TH7, zbias, zbias, 0, 0, 0,
        P6, P7, NG_, 800,
        nullptr, nullptr, nullptr, nullptr, nullptr, nullptr, nullptr, nullptr, nullptr, NIL6, NILU);

    // fused combine + stats, then BN(u) + relu
    ucombstats_k<<<25, 256>>>(un, P6, P7, UFIh, cnts, bs, bnsum + 3200, bnsq + 3200);
    bnprep_k<<<4, 256>>>(bnsum + 3200, bnsq + 3200, gam + 1600, bet + 1600, (float)NG_, bnsc + 3200, bnsh + 3200);
    bnrelu_k<<<(NU + 255) / 256, 256>>>(un, NU, bnsc + 3200, bnsh + 3200);
    #undef NIL6
    #undef NILU
}

// round 15
// speedup vs baseline: 7.0858x; 1.0026x over previous
#include <cuda_runtime.h>
#include <cuda_fp16.h>
#include <cstdint>
#include <math.h>

#define DD 800
#define NA_ 20000
#define NB_ 24000
#define NG_ 256

// ---- HMMA GEMM tiling (pure fp16 single pass, 4-stage) ----
#define BM 128
#define BN 160
#define BK 32
#define SA_ 0
#define SB_ 10240
#define STAGE_B 23040
#define SMEM_TOT (4 * STAGE_B)   // 92160

// ---------------------------------------------------------------------------
// Scratch layout (float offsets)
// ---------------------------------------------------------------------------
static constexpr size_t O_P1 = 0;             // [20000][2400] fp16 A|D|E half1
static constexpr size_t O_P2 = 48000000;      // fp16 half2
static constexpr size_t O_SMALL = 96000000;
static constexpr size_t O_TW   = 98400000;
static constexpr size_t O_THp  = 104800000;
static constexpr size_t O_TH2p = 120800000;
static constexpr size_t O_TEp  = 136800000;   // e fp16 plane; later sig1
static constexpr size_t O_TE2p = 156000000;   // e2 fp16 plane; later sig2
static constexpr size_t O_TUp  = 175200000;
__device__ __align__(1024) float g_scratch[176000000];

// ---------------------------------------------------------------------------
__device__ __forceinline__ uint32_t smem_u32(const void* p) {
    uint32_t a;
    asm("{ .reg .u64 t; cvta.to.shared.u64 t, %1; cvt.u32.u64 %0, t; }" : "=r"(a) : "l"(p));
    return a;
}
__device__ __forceinline__ void cp16(uint32_t saddr, const void* gaddr) {
    asm volatile("cp.async.cg.shared.global [%0], [%1], 16;" :: "r"(saddr), "l"(gaddr));
}
__device__ __forceinline__ void cp_commit() {
    asm volatile("cp.async.commit_group;" ::: "memory");
}
__device__ __forceinline__ void cp_wait2() {
    asm volatile("cp.async.wait_group 2;" ::: "memory");
}
__device__ __forceinline__ void cp_wait0() {
    asm volatile("cp.async.wait_group 0;" ::: "memory");
}
__device__ __forceinline__ void ldsm4(uint32_t* r, uint32_t addr) {
    asm volatile("ldmatrix.sync.aligned.m8n8.x4.shared.b16 {%0,%1,%2,%3}, [%4];"
                 : "=r"(r[0]), "=r"(r[1]), "=r"(r[2]), "=r"(r[3]) : "r"(addr));
}
__device__ __forceinline__ void mma16816(float* c, const uint32_t* a, const uint32_t* b) {
    asm volatile(
        "mma.sync.aligned.m16n8k16.row.col.f32.f16.f16.f32 "
        "{%0,%1,%2,%3}, {%4,%5,%6,%7}, {%8,%9}, {%0,%1,%2,%3};"
        : "+f"(c[0]), "+f"(c[1]), "+f"(c[2]), "+f"(c[3])
        : "r"(a[0]), "r"(a[1]), "r"(a[2]), "r"(a[3]), "r"(b[0]), "r"(b[1]));
}

// ---------------------------------------------------------------------------
// fp16 HMMA GEMM, z-batched pair.
// MODE 0: store fp32 acc+bias
// MODE 3: C = acc+bias + Ah[i0]+Ah[i1]+Cu[g] (bond fuse; fp16 gathers), BN stats
// MODE 4: store fp16 acc+bias; extra mtiles >= nmt compute the UFI projection
// MODE 5: fused atom update + mix, BN stats
// ---------------------------------------------------------------------------
template<int MODE>
__global__ __launch_bounds__(256, 2)
void hgemm_k(const __half* __restrict__ Ah0, const __half* __restrict__ Ah1,
             const __half* __restrict__ B0_, const __half* __restrict__ B1_,
             const float* __restrict__ bias0, const float* __restrict__ bias1,
             int bm0, int bm1, int bm2,
             void* __restrict__ C0, void* __restrict__ C1, int M, int ldc,
             const int* __restrict__ ba0, const int* __restrict__ ba1p,
             const int* __restrict__ bg0, const int* __restrict__ bg1p,
             const __half* __restrict__ P0g, const __half* __restrict__ P1g,
             const __half* __restrict__ CuB,
             float* __restrict__ st0, float* __restrict__ st1,
             const int* __restrict__ ab0_, const int* __restrict__ ab1_,
             const int* __restrict__ ag0_, const int* __restrict__ ag1_,
             const __half* __restrict__ sg0, const __half* __restrict__ sg1,
             const __half* __restrict__ AhU, const __half* __restrict__ BU,
             __half* __restrict__ CU, int bmu0, int bmu1, int bmu2)
{
    constexpr bool STATS = (MODE == 3 || MODE == 5);
    extern __shared__ char smem[];
    uint32_t sb = smem_u32(smem);
    int tid = threadIdx.x;
    int lid = tid & 31, wid = tid >> 5;
    int wm = wid & 3, wn = wid >> 2;
    int ntile = blockIdx.x, mtile = blockIdx.y, z = blockIdx.z;

    // UFI fold (MODE 4 only): last two mtiles compute u-projection (z=0 only)
    int uf = 0, mt = mtile, Mloc = M;
    if (MODE == 4 && AhU != nullptr) {
        int nmt = (M + BM - 1) / BM;
        if (mtile >= nmt) {
            if (z) return;
            uf = 1;
            mt = mtile - nmt;
            Mloc = NG_;
        }
    }

    const __half* Ahp = uf ? AhU : (z ? Ah1 : Ah0);
    const __half* Bp  = uf ? BU  : (z ? B1_ : B0_);
    const float* bias = z ? bias1 : bias0;

    int arow[2], acol[2];
    uint32_t asoff[2];
#pragma unroll
    for (int t = 0; t < 2; t++) {
        int q = tid + t * 256;
        int r = q >> 2, c = q & 3;
        arow[t] = min(mt * BM + r, Mloc - 1);
        acol[t] = c * 8;
        asoff[t] = r * 80 + c * 16;
    }
    int brow[3], bcol[3];
    uint32_t bsoff[3];
#pragma unroll
    for (int t = 0; t < 3; t++) {
        int q = tid + t * 256;
        int r = q >> 2, c = q & 3;
        brow[t] = ntile * BN + r;
        bcol[t] = c * 8;
        bsoff[t] = r * 80 + c * 16;
    }
    bool b3 = (tid < 128);

    auto load_stage = [&](int s, int kc) {
        uint32_t st = sb + s * STAGE_B;
        int k0 = kc * BK;
#pragma unroll
        for (int t = 0; t < 2; t++)
            cp16(st + SA_ + asoff[t], Ahp + (size_t)arow[t] * DD + k0 + acol[t]);
#pragma unroll
        for (int t = 0; t < 2; t++)
            cp16(st + SB_ + bsoff[t], Bp + (size_t)brow[t] * DD + k0 + bcol[t]);
        if (b3)
            cp16(st + SB_ + bsoff[2], Bp + (size_t)brow[2] * DD + k0 + bcol[2]);
    };

    float acc[2][10][4];
#pragma unroll
    for (int i = 0; i < 2; i++)
#pragma unroll
        for (int j = 0; j < 10; j++)
#pragma unroll
            for (int k = 0; k < 4; k++) acc[i][j][k] = 0.f;

    uint32_t aswz = (lid & 15) * 80 + (lid >> 4) * 16;
    uint32_t bswz = ((lid & 7) + ((lid & 16) ? 8 : 0)) * 80 + ((lid >> 3) & 1) * 16;
    uint32_t a_base = (wm * 32) * 80 + aswz;
    uint32_t b_base = (wn * 80) * 80 + bswz;

    load_stage(0, 0); cp_commit();
    load_stage(1, 1); cp_commit();
    load_stage(2, 2); cp_commit();

#pragma unroll 1
    for (int kc = 0; kc < 25; kc++) {
        int s = kc & 3;
        cp_wait2();
        __syncthreads();
        uint32_t st = sb + s * STAGE_B;
#pragma unroll
        for (int k16 = 0; k16 < 2; k16++) {
            uint32_t aH[2][4];
            ldsm4(aH[0], st + SA_ + a_base + k16 * 32);
            ldsm4(aH[1], st + SA_ + a_base + 16 * 80 + k16 * 32);
#pragma unroll
            for (int g = 0; g < 5; g++) {
                uint32_t bH[4];
                ldsm4(bH, st + SB_ + b_base + g * 16 * 80 + k16 * 32);
                mma16816(acc[0][2 * g],     aH[0], bH);
                mma16816(acc[0][2 * g + 1], aH[0], bH + 2);
                mma16816(acc[1][2 * g],     aH[1], bH);
                mma16816(acc[1][2 * g + 1], aH[1], bH + 2);
            }
        }
        if (kc + 3 < 25) load_stage((kc + 3) & 3, kc + 3);
        cp_commit();
    }

    // ---------------- epilogue ----------------
    cp_wait0();
    __syncthreads();
    float* smst = (float*)smem;
    if (STATS) {
        for (int i = tid; i < 320; i += 256) smst[i] = 0.f;
        __syncthreads();
    }

    int bseg = ntile / 5;
    int bsel = uf ? (bseg == 0 ? bmu0 : bseg == 1 ? bmu1 : bmu2)
                  : (bseg == 0 ? bm0 : bseg == 1 ? bm1 : bm2);
    const float* bp = bias + bsel * 800 - bseg * 800;

    float* Cf  = (float*)(z ? C1 : C0);
    __half* Ch = uf ? CU : (__half*)(z ? C1 : C0);
    float* st = z ? st1 : st0;

    if (MODE == 5) {
        const int* AB  = z ? ab1_ : ab0_;
        const int* BAm = z ? ba1p : ba0;
        const int* AG  = z ? ag1_ : ag0_;
        const __half* SG = z ? sg1 : sg0;
        const __half* Pm = z ? P1g : P0g;
#pragma unroll
        for (int q = 0; q < 4; q++) {
            const int iq = q >> 1, half = q & 1;
            int r = mt * BM + wm * 32 + iq * 16 + half * 8 + (lid >> 2);
            bool ok = r < Mloc;
            int b0 = 0, b1 = 0, b2 = 0, b3i = 0, o0 = 0, o1 = 0, o2 = 0, o3 = 0, gg = 0;
            if (ok) {
                int4 bb = ((const int4*)AB)[r];
                b0 = bb.x; b1 = bb.y; b2 = bb.z; b3i = bb.w;
                int2 p;
                p = ((const int2*)BAm)[b0];  o0 = (p.x != r) ? p.x : p.y;
                p = ((const int2*)BAm)[b1];  o1 = (p.x != r) ? p.x : p.y;
                p = ((const int2*)BAm)[b2];  o2 = (p.x != r) ? p.x : p.y;
                p = ((const int2*)BAm)[b3i]; o3 = (p.x != r) ? p.x : p.y;
                gg = AG[r];
            }
#pragma unroll
            for (int j = 0; j < 10; j++) {
                int colloc = wn * 80 + j * 8 + (lid & 3) * 2;
                int col = ntile * 160 + colloc;
                float v0 = 0.f, v1 = 0.f;
                if (ok) {
                    float2 bv = *(const float2*)(bp + col);
                    float a0 = acc[iq][j][half * 2 + 0] + bv.x;
                    float a1 = acc[iq][j][half * 2 + 1] + bv.y;
                    float2 w0 = __half22float2(*(const __half2*)(SG + (size_t)b0 * DD + col));
                    float2 w1 = __half22float2(*(const __half2*)(SG + (size_t)b1 * DD + col));
                    float2 w2 = __half22float2(*(const __half2*)(SG + (size_t)b2 * DD + col));
                    float2 w3 = __half22float2(*(const __half2*)(SG + (size_t)b3i * DD + col));
                    float2 e0 = __half22float2(*(const __half2*)(Pm + (size_t)o0 * 2400 + 1600 + col));
                    float2 e1v = __half22float2(*(const __half2*)(Pm + (size_t)o1 * 2400 + 1600 + col));
                    float2 e2v = __half22float2(*(const __half2*)(Pm + (size_t)o2 * 2400 + 1600 + col));
                    float2 e3v = __half22float2(*(const __half2*)(Pm + (size_t)o3 * 2400 + 1600 + col));
                    float2 dh = __half22float2(*(const __half2*)(Pm + (size_t)r * 2400 + 800 + col));
                    float2 fu = __half22float2(*(const __half2*)(CuB + (size_t)gg * 2400 + 800 + col));
                    float num0 = w0.x * e0.x + w1.x * e1v.x + w2.x * e2v.x + w3.x * e3v.x;
                    float den0 = w0.x + w1.x + w2.x + w3.x + 1e-6f;
                    float num1 = w0.y * e0.y + w1.y * e1v.y + w2.y * e2v.y + w3.y * e3v.y;
                    float den1 = w0.y + w1.y + w2.y + w3.y + 1e-6f;
                    float h0 = dh.x + __fdividef(num0, den0) + fu.x;
                    float h1v = dh.y + __fdividef(num1, den1) + fu.y;
                    v0 = h0 * 0.8f + 0.2f * a0;
                    v1 = h1v * 0.8f + 0.2f * a1;
                    *(float2*)&Cf[(size_t)r * ldc + col] = make_float2(v0, v1);
                }
                float s0 = v0, s1 = v1, q0 = v0 * v0, q1 = v1 * v1;
#pragma unroll
                for (int d = 4; d < 32; d <<= 1) {
                    s0 += __shfl_xor_sync(0xFFFFFFFFu, s0, d);
                    s1 += __shfl_xor_sync(0xFFFFFFFFu, s1, d);
                    q0 += __shfl_xor_sync(0xFFFFFFFFu, q0, d);
                    q1 += __shfl_xor_sync(0xFFFFFFFFu, q1, d);
                }
                if (lid < 4) {
                    atomicAdd(&smst[colloc], s0);
                    atomicAdd(&smst[colloc + 1], s1);
                    atomicAdd(&smst[160 + colloc], q0);
                    atomicAdd(&smst[160 + colloc + 1], q1);
                }
            }
        }
    } else {
        const int* BA = z ? ba1p : ba0;
        const int* BG = z ? bg1p : bg0;
        const __half* Pg = z ? P1g : P0g;
        int rows[4];
        bool rok[4];
        const __half *pA0[4], *pA1[4], *pCu[4];
#pragma unroll
        for (int q = 0; q < 4; q++) {
            int i = q >> 1, half = q & 1;
            int r = mt * BM + wm * 32 + i * 16 + half * 8 + (lid >> 2);
            rows[q] = r;
            rok[q] = r < Mloc;
            if (MODE == 3 && rok[q]) {
                int2 bb = ((const int2*)BA)[r];
                int gg = BG[r];
                pA0[q] = Pg + (size_t)bb.x * 2400;
                pA1[q] = Pg + (size_t)bb.y * 2400;
                pCu[q] = CuB + (size_t)gg * 2400;
            }
        }
#pragma unroll
        for (int j = 0; j < 10; j++) {
            int colloc = wn * 80 + j * 8 + (lid & 3) * 2;
            int col = ntile * 160 + colloc;
            float2 bv = *(const float2*)(bp + col);
            float s0 = 0.f, s1 = 0.f, q0 = 0.f, q1 = 0.f;
#pragma unroll
            for (int q = 0; q < 4; q++) {
                if (!rok[q]) continue;
                int i = q >> 1, half = q & 1;
                float v0 = acc[i][j][half * 2 + 0] + bv.x;
                float v1 = acc[i][j][half * 2 + 1] + bv.y;
                if (MODE == 3) {
                    float2 a0v = __half22float2(*(const __half2*)(pA0[q] + col));
                    float2 a1v = __half22float2(*(const __half2*)(pA1[q] + col));
                    float2 cuv = __half22float2(*(const __half2*)(pCu[q] + col));
                    v0 += a0v.x + a1v.x + cuv.x;
                    v1 += a0v.y + a1v.y + cuv.y;
                }
                if (MODE == 4) {
                    *(__half2*)(Ch + (size_t)rows[q] * ldc + col) = __floats2half2_rn(v0, v1);
                } else {
                    *(float2*)&Cf[(size_t)rows[q] * ldc + col] = make_float2(v0, v1);
                }
                if (STATS) {
                    s0 += v0; q0 += v0 * v0;
                    s1 += v1; q1 += v1 * v1;
                }
            }
            if (STATS) {
#pragma unroll
                for (int d = 4; d < 32; d <<= 1) {
                    s0 += __shfl_xor_sync(0xFFFFFFFFu, s0, d);
                    s1 += __shfl_xor_sync(0xFFFFFFFFu, s1, d);
                    q0 += __shfl_xor_sync(0xFFFFFFFFu, q0, d);
                    q1 += __shfl_xor_sync(0xFFFFFFFFu, q1, d);
                }
                if (lid < 4) {
                    atomicAdd(&smst[colloc], s0);
                    atomicAdd(&smst[colloc + 1], s1);
                    atomicAdd(&smst[160 + colloc], q0);
                    atomicAdd(&smst[160 + colloc + 1], q1);
                }
            }
        }
    }
    if (STATS) {
        __syncthreads();
        for (int i = tid; i < 160; i += 256) {
            atomicAdd(&st[ntile * 160 + i], smst[i]);
            atomicAdd(&st[4000 + ntile * 160 + i], smst[160 + i]);
        }
    }
}

// ---------------------------------------------------------------------------
// conversions
// ---------------------------------------------------------------------------
__global__ void conv_all_k(const float* __restrict__ h, const float* __restrict__ h2,
                           const float* __restrict__ e, const float* __restrict__ e2,
                           __half* __restrict__ th, __half* __restrict__ th2,
                           __half* __restrict__ te, __half* __restrict__ te2)
{
    int z = blockIdx.y;
    const float* A = (z == 0) ? h : (z == 1) ? h2 : (z == 2) ? e : e2;
    __half* T = (z == 0) ? th : (z == 1) ? th2 : (z == 2) ? te : te2;
    int n = (z < 2) ? NA_ * DD : NB_ * DD;
    int i4 = (blockIdx.x * blockDim.x + threadIdx.x) * 4;
    if (i4 >= n) return;
    float4 v = *(const float4*)(A + i4);
    __half2 a = __floats2half2_rn(v.x, v.y);
    __half2 b = __floats2half2_rn(v.z, v.w);
    *(uint2*)((unsigned short*)T + i4) = make_uint2(*(uint32_t*)&a, *(uint32_t*)&b);
}
__global__ void zero_k(float* p, int n) {
    int i = blockIdx.x * blockDim.x + threadIdx.x;
    if (i < n) p[i] = 0.f;
}
// y=0..3 counts, y=4 u conversion (AFTER zero_k — no race on cnts)
__global__ void setup_k(const int* __restrict__ ag1, const int* __restrict__ bg1,
                        const int* __restrict__ ag2, const int* __restrict__ bg2,
                        float* __restrict__ cnts,
                        const float* __restrict__ u, __half* __restrict__ tup)
{
    int y = blockIdx.y;
    int i = blockIdx.x * blockDim.x + threadIdx.x;
    if (y < 4) {
        const int* s = (y == 0) ? ag1 : (y == 1) ? bg1 : (y == 2) ? ag2 : bg2;
        int n = (y & 1) ? NB_ : NA_;
        if (i < n) atomicAdd(&cnts[y * 256 + s[i]], 1.0f);
    } else {
        int i4 = i * 4;
        if (i4 >= NG_ * DD) return;
        float4 v = *(const float4*)(u + i4);
        __half2 a = __floats2half2_rn(v.x, v.y);
        __half2 b = __floats2half2_rn(v.z, v.w);
        *(uint2*)((unsigned short*)tup + i4) = make_uint2(*(uint32_t*)&a, *(uint32_t*)&b);
    }
}

// weight transpose -> fp16 plane, packed groups
__global__ void conv_w_k(const float* __restrict__ Ws, __half* __restrict__ TW)
{
    static const int BASE[10]   = {0, 1920000, 2560000, 0, 0, 2560000, 4480000, 5120000, 2560000, 5760000};
    static const int ROWOFF[10] = {0, 0, 0, 800, 1600, 800, 0, 0, 1600, 0};
    __shared__ float t[32][33];
    int wi = blockIdx.z;
    const float* W = Ws + (size_t)wi * (DD * DD);
    __half* hi = TW + BASE[wi] + (size_t)ROWOFF[wi] * DD;
    int tx = threadIdx.x, ty = threadIdx.y;
    int kb = blockIdx.y * 32, nb = blockIdx.x * 32;
#pragma unroll
    for (int r = 0; r < 4; r++)
        t[ty + r * 8][tx] = W[(size_t)(kb + ty + r * 8) * DD + nb + tx];
    __syncthreads();
#pragma unroll
    for (int r = 0; r < 4; r++) {
        int nrow = nb + ty + r * 8;
        int kcol = kb + tx;
        hi[(size_t)nrow * DD + kcol] = __float2half_rn(t[tx][ty + r * 8]);
    }
}

// fused cross-gate + cast from fp16 P planes
__global__ void crossconv_k(const __half* __restrict__ P1, const __half* __restrict__ P2,
                            __half* __restrict__ T1, __half* __restrict__ T2)
{
    int i4 = (blockIdx.x * blockDim.x + threadIdx.x) * 4;
    if (i4 >= NA_ * DD) return;
    int r = i4 / DD, c = i4 % DD;
    size_t po = (size_t)r * 2400 + 800 + c;
    float2 d1a = __half22float2(*(const __half2*)(P1 + po));
    float2 d1b = __half22float2(*(const __half2*)(P1 + po + 2));
    float2 d2a = __half22float2(*(const __half2*)(P2 + po));
    float2 d2b = __half22float2(*(const __half2*)(P2 + po + 2));
    float4 t1v, t2v;
    float f;
    f = 1.f / (fabsf(d1a.x - d2a.x) + 1.f); t1v.x = f * d1a.x; t2v.x = f * d2a.x;
    f = 1.f / (fabsf(d1a.y - d2a.y) + 1.f); t1v.y = f * d1a.y; t2v.y = f * d2a.y;
    f = 1.f / (fabsf(d1b.x - d2b.x) + 1.f); t1v.z = f * d1b.x; t2v.z = f * d2b.x;
    f = 1.f / (fabsf(d1b.y - d2b.y) + 1.f); t1v.w = f * d1b.y; t2v.w = f * d2b.y;
    __half2 a = __floats2half2_rn(t1v.x, t1v.y);
    __half2 b = __floats2half2_rn(t1v.z, t1v.w);
    *(uint2*)((unsigned short*)T1 + i4) = make_uint2(*(uint32_t*)&a, *(uint32_t*)&b);
    a = __floats2half2_rn(t2v.x, t2v.y);
    b = __floats2half2_rn(t2v.z, t2v.w);
    *(uint2*)((unsigned short*)T2 + i4) = make_uint2(*(uint32_t*)&a, *(uint32_t*)&b);
}

// ---------------------------------------------------------------------------
// final u: BN prep computed inline + relu
__global__ void bnrelu_k(float* __restrict__ X, int n,
                         const float* __restrict__ sum, const float* __restrict__ sumsq,
                         const float* __restrict__ gamma, const float* __restrict__ beta,
                         float Rf)
{
    int i = blockIdx.x * blockDim.x + threadIdx.x;
    if (i >= n) return;
    int col = i % DD;
    float m = sum[col] / Rf;
    float v = sumsq[col] / Rf - m * m;
    float sc = gamma[col] * rsqrtf(v + 1e-5f);
    float sh = beta[col] - m * sc;
    X[i] = fmaxf(fmaf(X[i], sc, sh), 0.f);
}
// fused BN(prep+apply) + relu + segment-sum (+ optional fp16 sigmoid emit), z-pair
__global__ void bnseg2_k(float* __restrict__ X0, float* __restrict__ X1, int M,
                         const int* __restrict__ seg0, const int* __restrict__ seg1,
                         const float* __restrict__ sum, const float* __restrict__ sumsq,
                         const float* __restrict__ gamma, const float* __restrict__ beta,
                         float Rf,
                         float* __restrict__ ssum0, float* __restrict__ ssum1,
                         __half* __restrict__ sg0, __half* __restrict__ sg1)
{
    extern __shared__ float sm[];
    int zz = blockIdx.z;
    float* X = zz ? X1 : X0;
    const int* seg = zz ? seg1 : seg0;
    float* ssum = zz ? ssum1 : ssum0;
    __half* sigout = zz ? sg1 : sg0;
    int c0 = blockIdx.x * 64;
    int cl = threadIdx.x & 63;
    int col = c0 + cl;
    int rg = threadIdx.x >> 6;
    for (int i = threadIdx.x; i < 16384; i += 256) sm[i] = 0.f;
    __syncthreads();
    bool ok = col < DD;
    float sc = 0.f, sh = 0.f;
    if (ok) {
        float m = sum[zz * 800 + col] / Rf;
        float v = sumsq[zz * 800 + col] / Rf - m * m;
        sc = gamma[col] * rsqrtf(v + 1e-5f);
        sh = beta[col] - m * sc;
    }
    int chunk = (M + gridDim.y - 1) / gridDim.y;
    int r0 = blockIdx.y * chunk;
    int r1 = min(r0 + chunk, M);
    for (int r = r0 + rg; r < r1; r += 4) {
        int g = seg[r];
        if (ok) {
            float y = fmaxf(fmaf(X[(size_t)r * DD + col], sc, sh), 0.f);
            X[(size_t)r * DD + col] = y;
            if (sigout) {
                float s = __fdividef(1.f, 1.f + __expf(-y));
                sigout[(size_t)r * DD + col] = __float2half_rn(s);
            }
            atomicAdd(&sm[g * 64 + cl], y);
        }
    }
    __syncthreads();
    for (int i = threadIdx.x; i < 16384; i += 256) {
        int g = i >> 6;
        int c = c0 + (i & 63);
        float v = sm[i];
        if (c < DD && v != 0.f) atomicAdd(&ssum[g * DD + c], v);
    }
}
__global__ void meanprep_k(const float* __restrict__ ssum, const float* __restrict__ cnts,
                           __half* __restrict__ mH, __half* __restrict__ mE)
{
    int i4 = (blockIdx.x * blockDim.x + threadIdx.x) * 4;
    if (i4 >= NG_ * DD) return;
    int g = i4 / DD;
    float cA1 = fmaxf(cnts[g], 1.f),       cA2 = fmaxf(cnts[512 + g], 1.f);
    float cB1 = fmaxf(cnts[256 + g], 1.f), cB2 = fmaxf(cnts[768 + g], 1.f);
    const float* sh1 = ssum + i4;
    const float* se1 = ssum + 204800 + i4;
    const float* sh2 = ssum + 409600 + i4;
    const float* se2 = ssum + 614400 + i4;
    float4 vh, ve;
    vh.x = sh1[0] / cA1 + sh2[0] / cA2;  ve.x = se1[0] / cB1 + se2[0] / cB2;
    vh.y = sh1[1] / cA1 + sh2[1] / cA2;  ve.y = se1[1] / cB1 + se2[1] / cB2;
    vh.z = sh1[2] / cA1 + sh2[2] / cA2;  ve.z = se1[2] / cB1 + se2[2] / cB2;
    vh.w = sh1[3] / cA1 + sh2[3] / cA2;  ve.w = se1[3] / cB1 + se2[3] / cB2;
    __half2 a = __floats2half2_rn(vh.x, vh.y);
    __half2 b = __floats2half2_rn(vh.z, vh.w);
    *(uint2*)((unsigned short*)mH + i4) = make_uint2(*(uint32_t*)&a, *(uint32_t*)&b);
    a = __floats2half2_rn(ve.x, ve.y);
    b = __floats2half2_rn(ve.z, ve.w);
    *(uint2*)((unsigned short*)mE + i4) = make_uint2(*(uint32_t*)&a, *(uint32_t*)&b);
}
// fused: un = P6+P7+Iu+ind-bias, plus direct column stats
__global__ void ucombstats_k(float* __restrict__ un, const float* __restrict__ P6,
                             const float* __restrict__ P7, const __half* __restrict__ UFIh,
                             const float* __restrict__ cnts, const float* __restrict__ bs,
                             float* __restrict__ sum, float* __restrict__ sumsq)
{
    __shared__ float ssm[8][32], sqm[8][32];
    int cl = threadIdx.x & 31, rg = threadIdx.x >> 5;
    int col = blockIdx.x * 32 + cl;
    bool ok = col < DD;
    float s = 0.f, q = 0.f;
    if (ok) {
        float b6 = bs[6 * 800 + col], b7 = bs[7 * 800 + col];
        for (int g = rg; g < NG_; g += 8) {
            float indA = (cnts[g] > 0.f ? 1.f : 0.f) + (cnts[512 + g] > 0.f ? 1.f : 0.f);
            float indB = (cnts[256 + g] > 0.f ? 1.f : 0.f) + (cnts[768 + g] > 0.f ? 1.f : 0.f);
            float v = P6[(size_t)g * DD + col] + P7[(size_t)g * DD + col]
                    + __half2float(UFIh[(size_t)g * 2400 + 1600 + col])
                    + b6 * indA + b7 * indB;
            un[(size_t)g * DD + col] = v;
            s += v; q += v * v;
        }
    }
    ssm[rg][cl] = s; sqm[rg][cl] = q;
    __syncthreads();
    if (rg == 0 && ok) {
        float S = 0.f, Q = 0.f;
#pragma unroll
        for (int r = 0; r < 8; r++) { S += ssm[r][cl]; Q += sqm[r][cl]; }
        sum[col] = S; sumsq[col] = Q;
    }
}

// ---------------------------------------------------------------------------
extern "C" void kernel_launch(void* const* d_in, const int* in_sizes, int n_in,
                              void* d_out, int out_size)
{
    const float* h   = (const float*)d_in[0];
    const float* e   = (const float*)d_in[1];
    const float* h2  = (const float*)d_in[2];
    const float* e2  = (const float*)d_in[3];
    const float* u   = (const float*)d_in[4];
    const float* Ws  = (const float*)d_in[5];
    const float* bs  = (const float*)d_in[6];
    const float* gam = (const float*)d_in[7];
    const float* bet = (const float*)d_in[8];
    const int* ba1 = (const int*)d_in[9];
    const int* ab1 = (const int*)d_in[10];
    const int* ag1 = (const int*)d_in[11];
    const int* bg1 = (const int*)d_in[12];
    const int* ba2 = (const int*)d_in[13];
    const int* ab2 = (const int*)d_in[14];
    const int* ag2 = (const int*)d_in[15];
    const int* bg2 = (const int*)d_in[16];

    float* out = (float*)d_out;
    float* h1n = out;
    float* e1n = out + 16000000;
    float* h2n = out + 35200000;
    float* e2n = out + 51200000;
    float* un  = out + 70400000;

    float* sp = nullptr;
    cudaGetSymbolAddress((void**)&sp, g_scratch);

    __half* P1 = (__half*)(sp + O_P1);
    __half* P2 = (__half*)(sp + O_P2);
    float* SM  = sp + O_SMALL;
    __half* UFIh = (__half*)SM;               // [256][2400] fp16
    float* ssum  = SM + 614400;
    float* cnts  = SM + 1433600;
    float* bnsum = SM + 1434624;
    float* bnsq  = SM + 1438624;
    float* zbias = SM + 1442624;
    __half* mH = (__half*)(SM + 1456224);
    __half* mE = (__half*)(SM + 1661024);
    float* P6 = SM + 1865824;
    float* P7 = SM + 2070624;

    __half* tw   = (__half*)(sp + O_TW);
    __half* thp  = (__half*)(sp + O_THp);
    __half* th2p = (__half*)(sp + O_TH2p);
    __half* tep  = (__half*)(sp + O_TEp);
    __half* te2p = (__half*)(sp + O_TE2p);
    __half* tup  = (__half*)(sp + O_TUp);
    __half* sig1 = tep;
    __half* sig2 = te2p;

    __half* TADE = tw + 0;
    __half* TB1  = tw + 1920000;
    __half* TUFI = tw + 2560000;
    __half* TG   = tw + 4480000;
    __half* TH7  = tw + 5120000;
    __half* TW9  = tw + 5760000;

    const int NH = NA_ * DD, NU = NG_ * DD;

    cudaFuncSetAttribute(hgemm_k<0>, cudaFuncAttributeMaxDynamicSharedMemorySize, SMEM_TOT);
    cudaFuncSetAttribute(hgemm_k<3>, cudaFuncAttributeMaxDynamicSharedMemorySize, SMEM_TOT);
    cudaFuncSetAttribute(hgemm_k<4>, cudaFuncAttributeMaxDynamicSharedMemorySize, SMEM_TOT);
    cudaFuncSetAttribute(hgemm_k<5>, cudaFuncAttributeMaxDynamicSharedMemorySize, SMEM_TOT);
    cudaFuncSetAttribute(bnseg2_k, cudaFuncAttributeMaxDynamicSharedMemorySize, 65536);

    #define NIL6 nullptr, nullptr, nullptr, nullptr, nullptr, nullptr
    #define NILU nullptr, nullptr, nullptr, 0, 0, 0

    // setup + conversions (zero BEFORE counts — no race)
    zero_k<<<(829024 + 255) / 256, 256>>>(ssum, 829024);
    conv_all_k<<<dim3(18750, 4), 256>>>(h, h2, e, e2, thp, th2p, tep, te2p);
    setup_k<<<dim3(200, 5), 256>>>(ag1, bg1, ag2, bg2, cnts, u, tup);
    conv_w_k<<<dim3(25, 25, 10), dim3(32, 8)>>>(Ws, tw);

    // ADE projections -> fp16 P, with UFI fold (mtiles 157,158)
    hgemm_k<4><<<dim3(15, 159, 2), 256, SMEM_TOT>>>(
        thp, th2p, TADE, TADE, bs, bs, 0, 3, 4,
        P1, P2, NA_, 2400,
        nullptr, nullptr, nullptr, nullptr, nullptr, nullptr, nullptr, nullptr, nullptr, NIL6,
        tup, TUFI, UFIh, 2, 5, 8);

    // cross-gate -> thp/th2p reused as t1/t2
    crossconv_k<<<NH / 1024, 256>>>(P1, P2, thp, th2p);

    // e-projection + fused bond update + BN stats
    hgemm_k<3><<<dim3(5, 188, 2), 256, SMEM_TOT>>>(
        tep, te2p, TB1, TB1, bs, bs, 1, 1, 1,
        e1n, e2n, NB_, 800,
        ba1, ba2, bg1, bg2, P1, P2, UFIh,
        bnsum + 0, bnsum + 800, NIL6, NILU);

    // BN(e) apply (prep inline) + segsum + sigmoid emit
    bnseg2_k<<<dim3(13, 12, 2), 256, 65536>>>(e1n, e2n, NB_, bg1, bg2,
                                              bnsum + 0, bnsq + 0, gam, bet, (float)NB_,
                                              ssum + 204800, ssum + 614400, sig1, sig2);

    // fused atom update + cross mix + BN stats (MODE 5)
    hgemm_k<5><<<dim3(5, 157, 2), 256, SMEM_TOT>>>(
        th2p, thp, TW9, TW9, bs, bs, 9, 9, 9,
        h1n, h2n, NA_, 800,
        ba1, ba2, nullptr, nullptr, P1, P2, UFIh,
        bnsum + 1600, bnsum + 2400,
        ab1, ab2, ag1, ag2, sig1, sig2, NILU);

    // BN(h) apply (prep inline) + segsum
    bnseg2_k<<<dim3(13, 12, 2), 256, 65536>>>(h1n, h2n, NA_, ag1, ag2,
                                              bnsum + 1600, bnsq + 1600, gam + 800, bet + 800,
                                              (float)NA_,
                                              ssum + 0, ssum + 409600, nullptr, nullptr);

    // global readout on means
    meanprep_k<<<NU / 1024, 256>>>(ssum, cnts, mH, mE);
    hgemm_k<0><<<dim3(5, 2, 2), 256, SMEM_TOT>>>(
        mH, mE, TG, TH7, zbias, zbias, 0, 0, 0,
        P6, P7, NG_, 800,
        nullptr, nullptr, nullptr, nullptr, nullptr, nullptr, nullptr, nullptr, nullptr, NIL6, NILU);

    // fused combine + stats, then BN(u) prep-inline + relu
    ucombstats_k<<<25, 256>>>(un, P6, P7, UFIh, cnts, bs, bnsum + 3200, bnsq + 3200);
    bnrelu_k<<<(NU + 255) / 256, 256>>>(un, NU, bnsum + 3200, bnsq + 3200,
                                        gam + 1600, bet + 1600, (float)NG_);
    #undef NIL6
    #undef NILU
}